// round 2
// baseline (speedup 1.0000x reference)
#include <cuda_runtime.h>
#include <cstddef>

#define NBATCH 4
#define KNB 64

// ---------------- scratch layout (floats) ----------------
#define OFF_FEAT0 0ull
#define OFF_FEAT1 2097152ull
#define OFF_FEAT2 3145728ull
#define OFF_FEAT3 3670016ull
#define OFF_POS1  3932160ull
#define OFF_POS2  3956736ull
#define OFF_POS3  3969024ull
#define OFF_NBR   3975168ull
#define OFF_FIN   4499456ull
#define OFF_F1    8693760ull
#define OFF_XF    12888064ull
#define OFF_HIN   14985216ull
#define OFF_H1    84191232ull
#define OFF_H2    153397248ull
#define TOTAL_FLOATS 220506112ull

__device__ float g_buf[TOTAL_FLOATS];

// ---------------- generic GEMM: C = bn(relu(A@W + bias)) ----------------
// A [M,K] lda, W [K,N] row-major (ldw = N), C [M,N] ldc.
// If gam == nullptr: relu only.
__global__ __launch_bounds__(256)
void gemm_bra(const float* __restrict__ A, const float* __restrict__ W,
              const float* __restrict__ bias, const float* __restrict__ gam,
              const float* __restrict__ bet, float* __restrict__ C,
              int M, int N, int K, int lda, int ldc)
{
    __shared__ float As[16][68];   // [BK][BM+4] padded
    __shared__ float Ws[16][64];   // [BK][BN]
    const int bm = blockIdx.y * 64;
    const int bn = blockIdx.x * 64;
    const int tid = threadIdx.x;
    const int tx = tid & 15;
    const int ty = tid >> 4;
    float acc[4][4];
#pragma unroll
    for (int i = 0; i < 4; i++)
#pragma unroll
        for (int j = 0; j < 4; j++) acc[i][j] = 0.f;

    for (int k0 = 0; k0 < K; k0 += 16) {
        {   // load A tile (64 x 16)
            int m  = tid >> 2;
            int kq = (tid & 3) * 4;
            int gm = bm + m;
#pragma unroll
            for (int j = 0; j < 4; j++) {
                int gk = k0 + kq + j;
                As[kq + j][m] = (gm < M && gk < K) ? A[(size_t)gm * lda + gk] : 0.f;
            }
        }
        {   // load W tile (16 x 64)
            int kr = tid >> 4;
            int nq = (tid & 15) * 4;
            int gk = k0 + kr;
#pragma unroll
            for (int j = 0; j < 4; j++) {
                int gn = bn + nq + j;
                Ws[kr][nq + j] = (gk < K && gn < N) ? W[(size_t)gk * N + gn] : 0.f;
            }
        }
        __syncthreads();
#pragma unroll
        for (int kk = 0; kk < 16; kk++) {
            float a[4], w[4];
#pragma unroll
            for (int i = 0; i < 4; i++) a[i] = As[kk][ty * 4 + i];
#pragma unroll
            for (int j = 0; j < 4; j++) w[j] = Ws[kk][tx * 4 + j];
#pragma unroll
            for (int i = 0; i < 4; i++)
#pragma unroll
                for (int j = 0; j < 4; j++) acc[i][j] += a[i] * w[j];
        }
        __syncthreads();
    }

    const float inv = rsqrtf(1.f + 1e-5f);
#pragma unroll
    for (int i = 0; i < 4; i++) {
        int gm = bm + ty * 4 + i;
        if (gm >= M) continue;
#pragma unroll
        for (int j = 0; j < 4; j++) {
            int gn = bn + tx * 4 + j;
            if (gn >= N) continue;
            float v = acc[i][j] + bias[gn];
            v = fmaxf(v, 0.f);
            if (gam) v = gam[gn] * v * inv + bet[gn];
            C[(size_t)gm * ldc + gn] = v;
        }
    }
}

// ---------------- farthest point sampling ----------------
// One block per batch, 256 threads, PER points per thread (n = 256*PER).
// Writes the m sampled positions (q) directly.
template<int PER>
__global__ __launch_bounds__(256)
void fps_kernel(const float* __restrict__ pos, int n, int m, float* __restrict__ qout)
{
    const int b = blockIdx.x, tid = threadIdx.x;
    const float* P = pos + (size_t)b * n * 3;
    float* Q = qout + (size_t)b * m * 3;
    float px[PER], py[PER], pz[PER], dmin[PER];
#pragma unroll
    for (int u = 0; u < PER; u++) {
        int i = tid + 256 * u;
        px[u] = P[i * 3]; py[u] = P[i * 3 + 1]; pz[u] = P[i * 3 + 2];
        dmin[u] = 1e30f;
    }
    __shared__ float s_v[8];
    __shared__ int   s_i[8];
    __shared__ float s_q[3];
    if (tid == 0) {
        Q[0] = P[0]; Q[1] = P[1]; Q[2] = P[2];
        s_q[0] = P[0]; s_q[1] = P[1]; s_q[2] = P[2];
    }
    __syncthreads();
    float qx = s_q[0], qy = s_q[1], qz = s_q[2];

    for (int s = 1; s < m; s++) {
        float bv = -1e31f; int bi = 0;
#pragma unroll
        for (int u = 0; u < PER; u++) {
            float dx = px[u] - qx, dy = py[u] - qy, dz = pz[u] - qz;
            float d = dx * dx + dy * dy + dz * dz;
            d = fminf(dmin[u], d);
            dmin[u] = d;
            if (d > bv) { bv = d; bi = tid + 256 * u; }   // ascending i: strict > keeps lowest idx on ties
        }
#pragma unroll
        for (int off = 16; off; off >>= 1) {
            float ov = __shfl_down_sync(0xffffffffu, bv, off);
            int   oi = __shfl_down_sync(0xffffffffu, bi, off);
            if (ov > bv || (ov == bv && oi < bi)) { bv = ov; bi = oi; }
        }
        if ((tid & 31) == 0) { s_v[tid >> 5] = bv; s_i[tid >> 5] = bi; }
        __syncthreads();
        if (tid == 0) {
            float fv = s_v[0]; int fi = s_i[0];
#pragma unroll
            for (int w = 1; w < 8; w++)
                if (s_v[w] > fv || (s_v[w] == fv && s_i[w] < fi)) { fv = s_v[w]; fi = s_i[w]; }
            float xx = P[fi * 3], yy = P[fi * 3 + 1], zz = P[fi * 3 + 2];
            s_q[0] = xx; s_q[1] = yy; s_q[2] = zz;
            Q[s * 3] = xx; Q[s * 3 + 1] = yy; Q[s * 3 + 2] = zz;
        }
        __syncthreads();
        qx = s_q[0]; qy = s_q[1]; qz = s_q[2];
    }
}

// ---------------- ball-query top-K (K nearest within radius) ----------------
// one block per (batch,center); nbr[j] = point index or -1 (invalid tail)
__global__ __launch_bounds__(128)
void knn_ball(const float* __restrict__ pos, const float* __restrict__ q,
              int n, int m, int* __restrict__ nbr)
{
    __shared__ float sd[4096];
    __shared__ float s_pv[4];
    __shared__ int   s_pi[4];
    __shared__ int   s_sel;
    const int bc = blockIdx.x;            // b*m + c
    const int tid = threadIdx.x;
    const float* P = pos + (size_t)(bc / m) * n * 3;
    const float qx = q[(size_t)bc * 3], qy = q[(size_t)bc * 3 + 1], qz = q[(size_t)bc * 3 + 2];
    for (int i = tid; i < n; i += 128) {
        float dx = P[i * 3] - qx, dy = P[i * 3 + 1] - qy, dz = P[i * 3 + 2] - qz;
        sd[i] = dx * dx + dy * dy + dz * dz;
    }
    __syncthreads();
    int* out = nbr + (size_t)bc * KNB;
    for (int r = 0; r < KNB; r++) {
        float bv = 1e38f; int bi = 0x7fffffff;
        for (int i = tid; i < n; i += 128) {
            float v = sd[i];
            if (v < bv) { bv = v; bi = i; }
        }
#pragma unroll
        for (int off = 16; off; off >>= 1) {
            float ov = __shfl_down_sync(0xffffffffu, bv, off);
            int   oi = __shfl_down_sync(0xffffffffu, bi, off);
            if (ov < bv || (ov == bv && oi < bi)) { bv = ov; bi = oi; }
        }
        if ((tid & 31) == 0) { s_pv[tid >> 5] = bv; s_pi[tid >> 5] = bi; }
        __syncthreads();
        if (tid == 0) {
            float fv = s_pv[0]; int fi = s_pi[0];
#pragma unroll
            for (int w = 1; w < 4; w++)
                if (s_pv[w] < fv || (s_pv[w] == fv && s_pi[w] < fi)) { fv = s_pv[w]; fi = s_pi[w]; }
            if (fv <= 4.0f) { out[r] = fi; sd[fi] = 1e38f; s_sel = 1; }
            else s_sel = 0;
        }
        __syncthreads();
        if (!s_sel) {
            for (int rr = r + tid; rr < KNB; rr += 128) out[rr] = -1;
            break;
        }
    }
}

// ---------------- SA input gather: [row,132] = [x[nbr] | pos[nbr]-q] ----------------
__global__ __launch_bounds__(128)
void sa_gather(const float* __restrict__ feat, const float* __restrict__ posL,
               const float* __restrict__ q, const int* __restrict__ nbr,
               int m, int n, float* __restrict__ hin)
{
    const int row = blockIdx.x;
    const int tid = threadIdx.x;
    const int b = row / (m * KNB);
    const int rem = row - b * m * KNB;
    const int c = rem / KNB;
    const int bc = b * m + c;
    const int j = nbr[row];
    float* o = hin + (size_t)row * 132;
    if (j < 0) {
        o[tid] = 0.f;
        if (tid < 3) o[128 + tid] = 0.f;
    } else {
        o[tid] = feat[((size_t)b * n + j) * 128 + tid];
        if (tid < 3) o[128 + tid] = posL[((size_t)b * n + j) * 3 + tid] - q[(size_t)bc * 3 + tid];
    }
}

// ---------------- max aggregation over valid neighbors ----------------
__global__ __launch_bounds__(128)
void sa_max(const float* __restrict__ h2, const int* __restrict__ nbr,
            float* __restrict__ outf)
{
    const int bc = blockIdx.x;
    const int f = threadIdx.x;
    const float* hrow = h2 + (size_t)bc * KNB * 128;
    const int* nb = nbr + (size_t)bc * KNB;
    float mx = -1e30f;
    for (int k = 0; k < KNB; k++) {
        if (nb[k] < 0) break;          // invalid slots only at tail
        mx = fmaxf(mx, hrow[k * 128 + f]);
    }
    outf[(size_t)bc * 128 + f] = mx;
}

// ---------------- FP 3-NN interpolation + skip concat ----------------
// fin[row,256] = [interp(coarse feats) | skip feats]
__global__ __launch_bounds__(256)
void fp_interp(const float* __restrict__ cf, const float* __restrict__ cp,
               const float* __restrict__ fpos, const float* __restrict__ sf,
               int nc, int nf, float* __restrict__ fin)
{
    __shared__ float sp[2048 * 3];
    const int bpb = nf >> 8;
    const int b = blockIdx.x / bpb;
    const int i = (blockIdx.x % bpb) * 256 + threadIdx.x;
    for (int t = threadIdx.x; t < nc * 3; t += 256) sp[t] = cp[(size_t)b * nc * 3 + t];
    __syncthreads();
    const float px = fpos[((size_t)b * nf + i) * 3];
    const float py = fpos[((size_t)b * nf + i) * 3 + 1];
    const float pz = fpos[((size_t)b * nf + i) * 3 + 2];
    float bd0 = 1e38f, bd1 = 1e38f, bd2 = 1e38f;
    int bi0 = 0, bi1 = 0, bi2 = 0;
    for (int j = 0; j < nc; j++) {
        float dx = px - sp[j * 3], dy = py - sp[j * 3 + 1], dz = pz - sp[j * 3 + 2];
        float d = dx * dx + dy * dy + dz * dz;
        if (d < bd0)      { bd2 = bd1; bi2 = bi1; bd1 = bd0; bi1 = bi0; bd0 = d; bi0 = j; }
        else if (d < bd1) { bd2 = bd1; bi2 = bi1; bd1 = d; bi1 = j; }
        else if (d < bd2) { bd2 = d; bi2 = j; }
    }
    const float w0 = 1.f / fmaxf(bd0, 1e-16f);
    const float w1 = 1.f / fmaxf(bd1, 1e-16f);
    const float w2 = 1.f / fmaxf(bd2, 1e-16f);
    const float rws = 1.f / (w0 + w1 + w2);
    const float4* f0 = (const float4*)(cf + ((size_t)b * nc + bi0) * 128);
    const float4* f1 = (const float4*)(cf + ((size_t)b * nc + bi1) * 128);
    const float4* f2 = (const float4*)(cf + ((size_t)b * nc + bi2) * 128);
    const float4* s4 = (const float4*)(sf + ((size_t)b * nf + i) * 128);
    float4* o4 = (float4*)(fin + ((size_t)b * nf + i) * 256);
#pragma unroll 8
    for (int f = 0; f < 32; f++) {
        float4 a = f0[f], bb = f1[f], cc = f2[f];
        float4 r;
        r.x = (w0 * a.x + w1 * bb.x + w2 * cc.x) * rws;
        r.y = (w0 * a.y + w1 * bb.y + w2 * cc.y) * rws;
        r.z = (w0 * a.z + w1 * bb.z + w2 * cc.z) * rws;
        r.w = (w0 * a.w + w1 * bb.w + w2 * cc.w) * rws;
        o4[f] = r;
        o4[32 + f] = s4[f];
    }
}

// ---------------- host ----------------
static inline void launch_gemm(const float* A, const float* W, const float* bias,
                               const float* g, const float* be, float* C,
                               int M, int N, int K, int lda, int ldc)
{
    dim3 grid((N + 63) / 64, (M + 63) / 64);
    gemm_bra<<<grid, 256>>>(A, W, bias, g, be, C, M, N, K, lda, ldc);
}

extern "C" void kernel_launch(void* const* d_in, const int* in_sizes, int n_in,
                              void* d_out, int out_size)
{
    const float* x      = (const float*)d_in[0];
    const float* pos0   = (const float*)d_in[1];
    const float* lin_w  = (const float*)d_in[3];
    const float* lin_b  = (const float*)d_in[4];
    const float* sa_w1  = (const float*)d_in[5];
    const float* sa_b1  = (const float*)d_in[6];
    const float* sa_g1  = (const float*)d_in[7];
    const float* sa_be1 = (const float*)d_in[8];
    const float* sa_w2  = (const float*)d_in[9];
    const float* sa_b2  = (const float*)d_in[10];
    const float* sa_g2  = (const float*)d_in[11];
    const float* sa_be2 = (const float*)d_in[12];
    const float* fp_w1  = (const float*)d_in[13];
    const float* fp_b1  = (const float*)d_in[14];
    const float* fp_g1  = (const float*)d_in[15];
    const float* fp_be1 = (const float*)d_in[16];
    const float* fp_w2  = (const float*)d_in[17];
    const float* fp_b2  = (const float*)d_in[18];
    const float* fp_g2  = (const float*)d_in[19];
    const float* fp_be2 = (const float*)d_in[20];
    const float* lo_w1  = (const float*)d_in[21];
    const float* lo_b1  = (const float*)d_in[22];
    const float* lo_g1  = (const float*)d_in[23];
    const float* lo_be1 = (const float*)d_in[24];
    const float* lo_w2  = (const float*)d_in[25];
    const float* lo_b2  = (const float*)d_in[26];
    const float* lo_g2  = (const float*)d_in[27];
    const float* lo_be2 = (const float*)d_in[28];
    float* out = (float*)d_out;

    float* buf = nullptr;
    cudaGetSymbolAddress((void**)&buf, g_buf);

    float* feat[4] = { buf + OFF_FEAT0, buf + OFF_FEAT1, buf + OFF_FEAT2, buf + OFF_FEAT3 };
    const float* posl[4] = { pos0, buf + OFF_POS1, buf + OFF_POS2, buf + OFF_POS3 };
    int*   nbr = (int*)(buf + OFF_NBR);
    float* hin = buf + OFF_HIN;
    float* h1  = buf + OFF_H1;
    float* h2  = buf + OFF_H2;
    float* fin = buf + OFF_FIN;
    float* f1  = buf + OFF_F1;
    float* xf  = buf + OFF_XF;

    const int nlev[4] = {4096, 2048, 1024, 512};

    // lin_in + ReLU
    launch_gemm(x, lin_w, lin_b, nullptr, nullptr, feat[0], NBATCH * 4096, 128, 16, 16, 128);

    // ---- SA levels ----
    for (int l = 0; l < 3; l++) {
        int n = nlev[l], m = nlev[l + 1];
        if (l == 0)      fps_kernel<16><<<NBATCH, 256>>>(posl[0], n, m, (float*)posl[1]);
        else if (l == 1) fps_kernel<8><<<NBATCH, 256>>>(posl[1], n, m, (float*)posl[2]);
        else             fps_kernel<4><<<NBATCH, 256>>>(posl[2], n, m, (float*)posl[3]);

        knn_ball<<<NBATCH * m, 128>>>(posl[l], posl[l + 1], n, m, nbr);

        int rows = NBATCH * m * KNB;
        sa_gather<<<rows, 128>>>(feat[l], posl[l], posl[l + 1], nbr, m, n, hin);
        launch_gemm(hin, sa_w1 + (size_t)l * 131 * 131, sa_b1 + l * 131,
                    sa_g1 + l * 131, sa_be1 + l * 131, h1, rows, 131, 131, 132, 132);
        launch_gemm(h1, sa_w2 + (size_t)l * 131 * 128, sa_b2 + l * 128,
                    sa_g2 + l * 128, sa_be2 + l * 128, h2, rows, 128, 131, 132, 128);
        sa_max<<<NBATCH * m, 128>>>(h2, nbr, feat[l + 1]);
    }

    // ---- FP levels ----
    const float* cfeat = feat[3];
    for (int step = 0; step < 3; step++) {
        int mi = 2 - step;
        int nc = nlev[mi + 1], nf = nlev[mi];
        fp_interp<<<NBATCH * (nf / 256), 256>>>(cfeat, posl[mi + 1], posl[mi], feat[mi], nc, nf, fin);
        int rows = NBATCH * nf;
        launch_gemm(fin, fp_w1 + (size_t)mi * 256 * 256, fp_b1 + mi * 256,
                    fp_g1 + mi * 256, fp_be1 + mi * 256, f1, rows, 256, 256, 256, 256);
        launch_gemm(f1, fp_w2 + (size_t)mi * 256 * 128, fp_b2 + mi * 128,
                    fp_g2 + mi * 128, fp_be2 + mi * 128, xf, rows, 128, 256, 256, 128);
        cfeat = xf;
    }

    // ---- final MLP ----
    launch_gemm(xf, lo_w1, lo_b1, lo_g1, lo_be1, f1, NBATCH * 4096, 128, 128, 128, 128);
    launch_gemm(f1, lo_w2, lo_b2, lo_g2, lo_be2, out, NBATCH * 4096, 2, 128, 128, 2);
}

// round 5
// speedup vs baseline: 1.3240x; 1.3240x over previous
#include <cuda_runtime.h>
#include <cstddef>

#define NBATCH 4
#define KNB 64

// ---------------- scratch layout (floats) ----------------
#define OFF_FEAT0 0ull
#define OFF_FEAT1 2097152ull
#define OFF_FEAT2 3145728ull
#define OFF_FEAT3 3670016ull
#define OFF_POS1  3932160ull
#define OFF_POS2  3956736ull
#define OFF_POS3  3969024ull
#define OFF_NBR   3975168ull
#define OFF_FIN   4499456ull
#define OFF_F1    8693760ull
#define OFF_XF    12888064ull
#define OFF_H1    14985216ull
#define TOTAL_FLOATS 84191232ull

__device__ float g_buf[TOTAL_FLOATS];

// ---------------- tf32 helpers ----------------
__device__ __forceinline__ unsigned f2tf(float f) {
    unsigned u;
    asm("cvt.rna.tf32.f32 %0, %1;" : "=r"(u) : "f"(f));
    return u;
}

__device__ __forceinline__ void mma8(float* c, const unsigned* a, unsigned b0, unsigned b1) {
    asm volatile(
        "mma.sync.aligned.m16n8k8.row.col.f32.tf32.tf32.f32 "
        "{%0,%1,%2,%3}, {%4,%5,%6,%7}, {%8,%9}, {%0,%1,%2,%3};"
        : "+f"(c[0]), "+f"(c[1]), "+f"(c[2]), "+f"(c[3])
        : "r"(a[0]), "r"(a[1]), "r"(a[2]), "r"(a[3]), "r"(b0), "r"(b1));
}

// ---------------- tensor-core GEMM (3xTF32, fp32-accurate) ----------------
// C = epi(A@W + bias). Tile: BM=128, BN=64, BK=16. 256 threads = 8 warps (4M x 2N).
// EPI: 0 = relu, 1 = relu+bn, 2 = relu+bn + masked max over 64-row neighbor groups
//      (C is [M/64][N], masked by nbr[row] < 0).
// GATHER: A rows are built on the fly: [feat[nbr] | pos[nbr]-q | 0].
template<int EPI, int GATHER>
__global__ __launch_bounds__(256)
void gemm_tc(const float* __restrict__ A, int lda,
             const float* __restrict__ W, const float* __restrict__ bias,
             const float* __restrict__ gam, const float* __restrict__ bet,
             float* __restrict__ C, int ldc, int M, int N, int K,
             const float* __restrict__ feat, const float* __restrict__ posL,
             const float* __restrict__ q, const int* __restrict__ nbr,
             int nPts, int mCen)
{
    __shared__ unsigned As_hi[16][136];
    __shared__ unsigned As_lo[16][136];
    __shared__ unsigned Ws_hi[16][72];
    __shared__ unsigned Ws_lo[16][72];
    __shared__ float sred[2][2][64];

    const int tid  = threadIdx.x;
    const int lane = tid & 31;
    const int warp = tid >> 5;
    const int mwarp = warp >> 1;     // 0..3
    const int nwarp = warp & 1;      // 0..1
    const int gid = lane >> 2;       // 0..7
    const int tig = lane & 3;        // 0..3
    const int bm = blockIdx.y * 128;
    const int bn = blockIdx.x * 64;

    float acc[2][4][4];
#pragma unroll
    for (int mt = 0; mt < 2; mt++)
#pragma unroll
        for (int nt = 0; nt < 4; nt++)
#pragma unroll
            for (int e = 0; e < 4; e++) acc[mt][nt][e] = 0.f;

    const int arow = tid >> 1;
    const int ac0  = (tid & 1) * 8;
    const int wr   = tid >> 4;
    const int wc0  = (tid & 15) * 4;
    const int gm_ld = bm + arow;

    // gather-mode row metadata (constant across k-chunks)
    int gj = -1, gb = 0, gbc = 0;
    if (GATHER) {
        gj  = (gm_ld < M) ? nbr[gm_ld] : -1;
        gb  = gm_ld / (mCen * 64);
        gbc = gm_ld >> 6;
    }

    for (int k0 = 0; k0 < K; k0 += 16) {
        // ---- load A tile: rows of 128, this thread covers cols [ac0, ac0+8) ----
        float av[8];
        if (GATHER) {
            const int gk0 = k0 + ac0;
            if (gj < 0) {
#pragma unroll
                for (int j = 0; j < 8; j++) av[j] = 0.f;
            } else if (gk0 + 7 < 128) {
                const float4* fp = (const float4*)(feat + ((size_t)gb * nPts + gj) * 128 + gk0);
                float4 v0 = fp[0], v1 = fp[1];
                av[0]=v0.x; av[1]=v0.y; av[2]=v0.z; av[3]=v0.w;
                av[4]=v1.x; av[5]=v1.y; av[6]=v1.z; av[7]=v1.w;
            } else {
#pragma unroll
                for (int j = 0; j < 8; j++) {
                    int gk = gk0 + j;
                    float v = 0.f;
                    if (gk < 128) v = feat[((size_t)gb * nPts + gj) * 128 + gk];
                    else if (gk < 131) v = posL[((size_t)gb * nPts + gj) * 3 + (gk - 128)]
                                         - q[(size_t)gbc * 3 + (gk - 128)];
                    av[j] = v;
                }
            }
        } else {
            const int gk0 = k0 + ac0;
            if (gm_ld < M && gk0 + 7 < K) {
                const float4* fp = (const float4*)(A + (size_t)gm_ld * lda + gk0);
                float4 v0 = fp[0], v1 = fp[1];
                av[0]=v0.x; av[1]=v0.y; av[2]=v0.z; av[3]=v0.w;
                av[4]=v1.x; av[5]=v1.y; av[6]=v1.z; av[7]=v1.w;
            } else {
#pragma unroll
                for (int j = 0; j < 8; j++) {
                    int gk = gk0 + j;
                    av[j] = (gm_ld < M && gk < K) ? A[(size_t)gm_ld * lda + gk] : 0.f;
                }
            }
        }
#pragma unroll
        for (int j = 0; j < 8; j++) {
            unsigned h = f2tf(av[j]);
            As_hi[ac0 + j][arow] = h;
            As_lo[ac0 + j][arow] = f2tf(av[j] - __uint_as_float(h));
        }

        // ---- load W tile: 16 x 64 ----
        {
            const int gk = k0 + wr;
#pragma unroll
            for (int j = 0; j < 4; j++) {
                int gn = bn + wc0 + j;
                float v = (gk < K && gn < N) ? W[(size_t)gk * N + gn] : 0.f;
                unsigned h = f2tf(v);
                Ws_hi[wr][wc0 + j] = h;
                Ws_lo[wr][wc0 + j] = f2tf(v - __uint_as_float(h));
            }
        }
        __syncthreads();

        // ---- mma over two k-substeps ----
#pragma unroll
        for (int ks = 0; ks < 16; ks += 8) {
            unsigned ah[2][4], al[2][4];
#pragma unroll
            for (int mt = 0; mt < 2; mt++) {
                int mr = mwarp * 32 + mt * 16 + gid;
                ah[mt][0] = As_hi[ks + tig][mr];
                ah[mt][1] = As_hi[ks + tig][mr + 8];
                ah[mt][2] = As_hi[ks + tig + 4][mr];
                ah[mt][3] = As_hi[ks + tig + 4][mr + 8];
                al[mt][0] = As_lo[ks + tig][mr];
                al[mt][1] = As_lo[ks + tig][mr + 8];
                al[mt][2] = As_lo[ks + tig + 4][mr];
                al[mt][3] = As_lo[ks + tig + 4][mr + 8];
            }
#pragma unroll
            for (int nt = 0; nt < 4; nt++) {
                int nc = nwarp * 32 + nt * 8 + gid;
                unsigned bh0 = Ws_hi[ks + tig][nc];
                unsigned bh1 = Ws_hi[ks + tig + 4][nc];
                unsigned bl0 = Ws_lo[ks + tig][nc];
                unsigned bl1 = Ws_lo[ks + tig + 4][nc];
#pragma unroll
                for (int mt = 0; mt < 2; mt++) {
                    mma8(acc[mt][nt], ah[mt], bh0, bh1);
                    mma8(acc[mt][nt], ah[mt], bl0, bl1);
                    mma8(acc[mt][nt], al[mt], bh0, bh1);
                }
            }
        }
        __syncthreads();
    }

    const float inv = rsqrtf(1.f + 1e-5f);

    if (EPI < 2) {
#pragma unroll
        for (int mt = 0; mt < 2; mt++) {
#pragma unroll
            for (int nt = 0; nt < 4; nt++) {
#pragma unroll
                for (int e = 0; e < 4; e++) {
                    int gm = bm + mwarp * 32 + mt * 16 + gid + ((e >> 1) ? 8 : 0);
                    int gn = bn + nwarp * 32 + nt * 8 + 2 * tig + (e & 1);
                    if (gm >= M || gn >= N) continue;
                    float v = acc[mt][nt][e] + bias[gn];
                    v = fmaxf(v, 0.f);
                    if (EPI == 1) v = gam[gn] * v * inv + bet[gn];
                    C[(size_t)gm * ldc + gn] = v;
                }
            }
        }
    } else {
        // masked max over 64-row neighbor groups (2 centers per block)
        bool val[2][2];
#pragma unroll
        for (int mt = 0; mt < 2; mt++) {
            int r = bm + mwarp * 32 + mt * 16 + gid;
            val[mt][0] = nbr[r] >= 0;
            val[mt][1] = nbr[r + 8] >= 0;
        }
        float cmax[4][2];
#pragma unroll
        for (int nt = 0; nt < 4; nt++) { cmax[nt][0] = -1e30f; cmax[nt][1] = -1e30f; }
#pragma unroll
        for (int mt = 0; mt < 2; mt++) {
#pragma unroll
            for (int nt = 0; nt < 4; nt++) {
                int gn0 = bn + nwarp * 32 + nt * 8 + 2 * tig;
#pragma unroll
                for (int e = 0; e < 4; e++) {
                    int gn = gn0 + (e & 1);
                    if (gn >= N) continue;
                    float v = acc[mt][nt][e] + bias[gn];
                    v = fmaxf(v, 0.f);
                    v = gam[gn] * v * inv + bet[gn];
                    if (val[mt][e >> 1]) {
                        float& m = cmax[nt][e & 1];
                        m = fmaxf(m, v);
                    }
                }
            }
        }
#pragma unroll
        for (int off = 4; off <= 16; off <<= 1) {
#pragma unroll
            for (int nt = 0; nt < 4; nt++) {
                cmax[nt][0] = fmaxf(cmax[nt][0], __shfl_xor_sync(0xffffffffu, cmax[nt][0], off));
                cmax[nt][1] = fmaxf(cmax[nt][1], __shfl_xor_sync(0xffffffffu, cmax[nt][1], off));
            }
        }
        if (gid == 0) {
#pragma unroll
            for (int nt = 0; nt < 4; nt++) {
                sred[mwarp >> 1][mwarp & 1][nwarp * 32 + nt * 8 + 2 * tig]     = cmax[nt][0];
                sred[mwarp >> 1][mwarp & 1][nwarp * 32 + nt * 8 + 2 * tig + 1] = cmax[nt][1];
            }
        }
        __syncthreads();
        if (tid < 128) {
            int c = tid >> 6, col = tid & 63;
            int gn = bn + col;
            if (gn < N) {
                float v = fmaxf(sred[c][0][col], sred[c][1][col]);
                int cen = blockIdx.y * 2 + c;
                C[(size_t)cen * ldc + gn] = v;
            }
        }
    }
}

// ---------------- SIMT GEMM kept for the tiny N=2 final layer ----------------
__global__ __launch_bounds__(256)
void gemm_bra(const float* __restrict__ A, const float* __restrict__ W,
              const float* __restrict__ bias, const float* __restrict__ gam,
              const float* __restrict__ bet, float* __restrict__ C,
              int M, int N, int K, int lda, int ldc)
{
    __shared__ float As[16][68];
    __shared__ float Ws[16][64];
    const int bm = blockIdx.y * 64;
    const int bn = blockIdx.x * 64;
    const int tid = threadIdx.x;
    const int tx = tid & 15;
    const int ty = tid >> 4;
    float acc[4][4];
#pragma unroll
    for (int i = 0; i < 4; i++)
#pragma unroll
        for (int j = 0; j < 4; j++) acc[i][j] = 0.f;

    for (int k0 = 0; k0 < K; k0 += 16) {
        {
            int m  = tid >> 2;
            int kq = (tid & 3) * 4;
            int gm = bm + m;
#pragma unroll
            for (int j = 0; j < 4; j++) {
                int gk = k0 + kq + j;
                As[kq + j][m] = (gm < M && gk < K) ? A[(size_t)gm * lda + gk] : 0.f;
            }
        }
        {
            int kr = tid >> 4;
            int nq = (tid & 15) * 4;
            int gk = k0 + kr;
#pragma unroll
            for (int j = 0; j < 4; j++) {
                int gn = bn + nq + j;
                Ws[kr][nq + j] = (gk < K && gn < N) ? W[(size_t)gk * N + gn] : 0.f;
            }
        }
        __syncthreads();
#pragma unroll
        for (int kk = 0; kk < 16; kk++) {
            float a[4], w[4];
#pragma unroll
            for (int i = 0; i < 4; i++) a[i] = As[kk][ty * 4 + i];
#pragma unroll
            for (int j = 0; j < 4; j++) w[j] = Ws[kk][tx * 4 + j];
#pragma unroll
            for (int i = 0; i < 4; i++)
#pragma unroll
                for (int j = 0; j < 4; j++) acc[i][j] += a[i] * w[j];
        }
        __syncthreads();
    }

    const float inv = rsqrtf(1.f + 1e-5f);
#pragma unroll
    for (int i = 0; i < 4; i++) {
        int gm = bm + ty * 4 + i;
        if (gm >= M) continue;
#pragma unroll
        for (int j = 0; j < 4; j++) {
            int gn = bn + tx * 4 + j;
            if (gn >= N) continue;
            float v = acc[i][j] + bias[gn];
            v = fmaxf(v, 0.f);
            if (gam) v = gam[gn] * v * inv + bet[gn];
            C[(size_t)gm * ldc + gn] = v;
        }
    }
}

// ---------------- farthest point sampling ----------------
template<int PER>
__global__ __launch_bounds__(256)
void fps_kernel(const float* __restrict__ pos, int n, int m, float* __restrict__ qout)
{
    const int b = blockIdx.x, tid = threadIdx.x;
    const float* P = pos + (size_t)b * n * 3;
    float* Q = qout + (size_t)b * m * 3;
    float px[PER], py[PER], pz[PER], dmin[PER];
#pragma unroll
    for (int u = 0; u < PER; u++) {
        int i = tid + 256 * u;
        px[u] = P[i * 3]; py[u] = P[i * 3 + 1]; pz[u] = P[i * 3 + 2];
        dmin[u] = 1e30f;
    }
    __shared__ float s_v[8];
    __shared__ int   s_i[8];
    __shared__ float s_q[3];
    if (tid == 0) {
        Q[0] = P[0]; Q[1] = P[1]; Q[2] = P[2];
        s_q[0] = P[0]; s_q[1] = P[1]; s_q[2] = P[2];
    }
    __syncthreads();
    float qx = s_q[0], qy = s_q[1], qz = s_q[2];

    for (int s = 1; s < m; s++) {
        float bv = -1e31f; int bi = 0;
#pragma unroll
        for (int u = 0; u < PER; u++) {
            float dx = px[u] - qx, dy = py[u] - qy, dz = pz[u] - qz;
            float d = dx * dx + dy * dy + dz * dz;
            d = fminf(dmin[u], d);
            dmin[u] = d;
            if (d > bv) { bv = d; bi = tid + 256 * u; }
        }
#pragma unroll
        for (int off = 16; off; off >>= 1) {
            float ov = __shfl_down_sync(0xffffffffu, bv, off);
            int   oi = __shfl_down_sync(0xffffffffu, bi, off);
            if (ov > bv || (ov == bv && oi < bi)) { bv = ov; bi = oi; }
        }
        if ((tid & 31) == 0) { s_v[tid >> 5] = bv; s_i[tid >> 5] = bi; }
        __syncthreads();
        if (tid == 0) {
            float fv = s_v[0]; int fi = s_i[0];
#pragma unroll
            for (int w = 1; w < 8; w++)
                if (s_v[w] > fv || (s_v[w] == fv && s_i[w] < fi)) { fv = s_v[w]; fi = s_i[w]; }
            float xx = P[fi * 3], yy = P[fi * 3 + 1], zz = P[fi * 3 + 2];
            s_q[0] = xx; s_q[1] = yy; s_q[2] = zz;
            Q[s * 3] = xx; Q[s * 3 + 1] = yy; Q[s * 3 + 2] = zz;
        }
        __syncthreads();
        qx = s_q[0]; qy = s_q[1]; qz = s_q[2];
    }
}

// ---------------- ball-query top-K ----------------
__global__ __launch_bounds__(128)
void knn_ball(const float* __restrict__ pos, const float* __restrict__ q,
              int n, int m, int* __restrict__ nbr)
{
    __shared__ float sd[4096];
    __shared__ float s_pv[4];
    __shared__ int   s_pi[4];
    __shared__ int   s_sel;
    const int bc = blockIdx.x;
    const int tid = threadIdx.x;
    const float* P = pos + (size_t)(bc / m) * n * 3;
    const float qx = q[(size_t)bc * 3], qy = q[(size_t)bc * 3 + 1], qz = q[(size_t)bc * 3 + 2];
    for (int i = tid; i < n; i += 128) {
        float dx = P[i * 3] - qx, dy = P[i * 3 + 1] - qy, dz = P[i * 3 + 2] - qz;
        sd[i] = dx * dx + dy * dy + dz * dz;
    }
    __syncthreads();
    int* out = nbr + (size_t)bc * KNB;
    for (int r = 0; r < KNB; r++) {
        float bv = 1e38f; int bi = 0x7fffffff;
        for (int i = tid; i < n; i += 128) {
            float v = sd[i];
            if (v < bv) { bv = v; bi = i; }
        }
#pragma unroll
        for (int off = 16; off; off >>= 1) {
            float ov = __shfl_down_sync(0xffffffffu, bv, off);
            int   oi = __shfl_down_sync(0xffffffffu, bi, off);
            if (ov < bv || (ov == bv && oi < bi)) { bv = ov; bi = oi; }
        }
        if ((tid & 31) == 0) { s_pv[tid >> 5] = bv; s_pi[tid >> 5] = bi; }
        __syncthreads();
        if (tid == 0) {
            float fv = s_pv[0]; int fi = s_pi[0];
#pragma unroll
            for (int w = 1; w < 4; w++)
                if (s_pv[w] < fv || (s_pv[w] == fv && s_pi[w] < fi)) { fv = s_pv[w]; fi = s_pi[w]; }
            if (fv <= 4.0f) { out[r] = fi; sd[fi] = 1e38f; s_sel = 1; }
            else s_sel = 0;
        }
        __syncthreads();
        if (!s_sel) {
            for (int rr = r + tid; rr < KNB; rr += 128) out[rr] = -1;
            break;
        }
    }
}

// ---------------- FP 3-NN interpolation + skip concat ----------------
__global__ __launch_bounds__(256)
void fp_interp(const float* __restrict__ cf, const float* __restrict__ cp,
               const float* __restrict__ fpos, const float* __restrict__ sf,
               int nc, int nf, float* __restrict__ fin)
{
    __shared__ float sp[2048 * 3];
    const int bpb = nf >> 8;
    const int b = blockIdx.x / bpb;
    const int i = (blockIdx.x % bpb) * 256 + threadIdx.x;
    for (int t = threadIdx.x; t < nc * 3; t += 256) sp[t] = cp[(size_t)b * nc * 3 + t];
    __syncthreads();
    const float px = fpos[((size_t)b * nf + i) * 3];
    const float py = fpos[((size_t)b * nf + i) * 3 + 1];
    const float pz = fpos[((size_t)b * nf + i) * 3 + 2];
    float bd0 = 1e38f, bd1 = 1e38f, bd2 = 1e38f;
    int bi0 = 0, bi1 = 0, bi2 = 0;
    for (int j = 0; j < nc; j++) {
        float dx = px - sp[j * 3], dy = py - sp[j * 3 + 1], dz = pz - sp[j * 3 + 2];
        float d = dx * dx + dy * dy + dz * dz;
        if (d < bd0)      { bd2 = bd1; bi2 = bi1; bd1 = bd0; bi1 = bi0; bd0 = d; bi0 = j; }
        else if (d < bd1) { bd2 = bd1; bi2 = bi1; bd1 = d; bi1 = j; }
        else if (d < bd2) { bd2 = d; bi2 = j; }
    }
    const float w0 = 1.f / fmaxf(bd0, 1e-16f);
    const float w1 = 1.f / fmaxf(bd1, 1e-16f);
    const float w2 = 1.f / fmaxf(bd2, 1e-16f);
    const float rws = 1.f / (w0 + w1 + w2);
    const float4* f0 = (const float4*)(cf + ((size_t)b * nc + bi0) * 128);
    const float4* f1 = (const float4*)(cf + ((size_t)b * nc + bi1) * 128);
    const float4* f2 = (const float4*)(cf + ((size_t)b * nc + bi2) * 128);
    const float4* s4 = (const float4*)(sf + ((size_t)b * nf + i) * 128);
    float4* o4 = (float4*)(fin + ((size_t)b * nf + i) * 256);
#pragma unroll 8
    for (int f = 0; f < 32; f++) {
        float4 a = f0[f], bb = f1[f], cc = f2[f];
        float4 r;
        r.x = (w0 * a.x + w1 * bb.x + w2 * cc.x) * rws;
        r.y = (w0 * a.y + w1 * bb.y + w2 * cc.y) * rws;
        r.z = (w0 * a.z + w1 * bb.z + w2 * cc.z) * rws;
        r.w = (w0 * a.w + w1 * bb.w + w2 * cc.w) * rws;
        o4[f] = r;
        o4[32 + f] = s4[f];
    }
}

// ---------------- host ----------------
extern "C" void kernel_launch(void* const* d_in, const int* in_sizes, int n_in,
                              void* d_out, int out_size)
{
    const float* x      = (const float*)d_in[0];
    const float* pos0   = (const float*)d_in[1];
    const float* lin_w  = (const float*)d_in[3];
    const float* lin_b  = (const float*)d_in[4];
    const float* sa_w1  = (const float*)d_in[5];
    const float* sa_b1  = (const float*)d_in[6];
    const float* sa_g1  = (const float*)d_in[7];
    const float* sa_be1 = (const float*)d_in[8];
    const float* sa_w2  = (const float*)d_in[9];
    const float* sa_b2  = (const float*)d_in[10];
    const float* sa_g2  = (const float*)d_in[11];
    const float* sa_be2 = (const float*)d_in[12];
    const float* fp_w1  = (const float*)d_in[13];
    const float* fp_b1  = (const float*)d_in[14];
    const float* fp_g1  = (const float*)d_in[15];
    const float* fp_be1 = (const float*)d_in[16];
    const float* fp_w2  = (const float*)d_in[17];
    const float* fp_b2  = (const float*)d_in[18];
    const float* fp_g2  = (const float*)d_in[19];
    const float* fp_be2 = (const float*)d_in[20];
    const float* lo_w1  = (const float*)d_in[21];
    const float* lo_b1  = (const float*)d_in[22];
    const float* lo_g1  = (const float*)d_in[23];
    const float* lo_be1 = (const float*)d_in[24];
    const float* lo_w2  = (const float*)d_in[25];
    const float* lo_b2  = (const float*)d_in[26];
    const float* lo_g2  = (const float*)d_in[27];
    const float* lo_be2 = (const float*)d_in[28];
    float* out = (float*)d_out;

    float* buf = nullptr;
    cudaGetSymbolAddress((void**)&buf, g_buf);

    float* feat[4] = { buf + OFF_FEAT0, buf + OFF_FEAT1, buf + OFF_FEAT2, buf + OFF_FEAT3 };
    const float* posl[4] = { pos0, buf + OFF_POS1, buf + OFF_POS2, buf + OFF_POS3 };
    int*   nbr = (int*)(buf + OFF_NBR);
    float* h1  = buf + OFF_H1;
    float* fin = buf + OFF_FIN;
    float* f1  = buf + OFF_F1;
    float* xf  = buf + OFF_XF;

    const int nlev[4] = {4096, 2048, 1024, 512};

    // lin_in + ReLU (tensor core)
    {
        dim3 grid((128 + 63) / 64, (NBATCH * 4096) / 128);
        gemm_tc<0, 0><<<grid, 256>>>(x, 16, lin_w, lin_b, nullptr, nullptr,
                                     feat[0], 128, NBATCH * 4096, 128, 16,
                                     nullptr, nullptr, nullptr, nullptr, 0, 0);
    }

    // ---- SA levels ----
    for (int l = 0; l < 3; l++) {
        int n = nlev[l], m = nlev[l + 1];
        if (l == 0)      fps_kernel<16><<<NBATCH, 256>>>(posl[0], n, m, (float*)posl[1]);
        else if (l == 1) fps_kernel<8><<<NBATCH, 256>>>(posl[1], n, m, (float*)posl[2]);
        else             fps_kernel<4><<<NBATCH, 256>>>(posl[2], n, m, (float*)posl[3]);

        knn_ball<<<NBATCH * m, 128>>>(posl[l], posl[l + 1], n, m, nbr);

        int rows = NBATCH * m * KNB;
        // GEMM1: gather fused into A load
        {
            dim3 grid((131 + 63) / 64, rows / 128);
            gemm_tc<1, 1><<<grid, 256>>>(nullptr, 0,
                                         sa_w1 + (size_t)l * 131 * 131, sa_b1 + l * 131,
                                         sa_g1 + l * 131, sa_be1 + l * 131,
                                         h1, 132, rows, 131, 131,
                                         feat[l], posl[l], posl[l + 1], nbr, n, m);
        }
        // GEMM2: masked row-group max fused into epilogue
        {
            dim3 grid((128 + 63) / 64, rows / 128);
            gemm_tc<2, 0><<<grid, 256>>>(h1, 132,
                                         sa_w2 + (size_t)l * 131 * 128, sa_b2 + l * 128,
                                         sa_g2 + l * 128, sa_be2 + l * 128,
                                         feat[l + 1], 128, rows, 128, 131,
                                         nullptr, nullptr, nullptr, nbr, n, m);
        }
    }

    // ---- FP levels ----
    const float* cfeat = feat[3];
    for (int step = 0; step < 3; step++) {
        int mi = 2 - step;
        int nc = nlev[mi + 1], nf = nlev[mi];
        fp_interp<<<NBATCH * (nf / 256), 256>>>(cfeat, posl[mi + 1], posl[mi], feat[mi], nc, nf, fin);
        int rows = NBATCH * nf;
        {
            dim3 grid((256 + 63) / 64, rows / 128);
            gemm_tc<1, 0><<<grid, 256>>>(fin, 256,
                                         fp_w1 + (size_t)mi * 256 * 256, fp_b1 + mi * 256,
                                         fp_g1 + mi * 256, fp_be1 + mi * 256,
                                         f1, 256, rows, 256, 256,
                                         nullptr, nullptr, nullptr, nullptr, 0, 0);
        }
        {
            dim3 grid((128 + 63) / 64, rows / 128);
            gemm_tc<1, 0><<<grid, 256>>>(f1, 256,
                                         fp_w2 + (size_t)mi * 256 * 128, fp_b2 + mi * 128,
                                         fp_g2 + mi * 128, fp_be2 + mi * 128,
                                         xf, 128, rows, 128, 256,
                                         nullptr, nullptr, nullptr, nullptr, 0, 0);
        }
        cfeat = xf;
    }

    // ---- final MLP ----
    {
        dim3 grid((128 + 63) / 64, (NBATCH * 4096) / 128);
        gemm_tc<1, 0><<<grid, 256>>>(xf, 128, lo_w1, lo_b1, lo_g1, lo_be1,
                                     f1, 128, NBATCH * 4096, 128, 128,
                                     nullptr, nullptr, nullptr, nullptr, 0, 0);
    }
    {
        dim3 grid(1, (NBATCH * 4096 + 63) / 64);
        gemm_bra<<<grid, 256>>>(f1, lo_w2, lo_b2, lo_g2, lo_be2, out,
                                NBATCH * 4096, 2, 128, 128, 2);
    }
}

// round 6
// speedup vs baseline: 1.5456x; 1.1674x over previous
#include <cuda_runtime.h>
#include <cuda_bf16.h>
#include <cstddef>

#define NBATCH 4
#define KNB 64

// ---------------- scratch layout (floats) ----------------
#define OFF_FEAT0 0ull
#define OFF_FEAT1 2097152ull
#define OFF_FEAT2 3145728ull
#define OFF_FEAT3 3670016ull
#define OFF_POS1  3932160ull
#define OFF_POS2  3956736ull
#define OFF_POS3  3969024ull
#define OFF_NBR   3975168ull
#define OFF_FIN   4499456ull
#define OFF_F1    8693760ull
#define OFF_XF    12888064ull
#define OFF_H1    14985216ull
#define TOTAL_FLOATS 84191232ull

__device__ float g_buf[TOTAL_FLOATS];

// ---------------- bf16 split helpers ----------------
__device__ __forceinline__ void splitf(float v, unsigned short& h, unsigned short& l) {
    __nv_bfloat16 hb = __float2bfloat16(v);
    float r = v - __bfloat162float(hb);
    __nv_bfloat16 lb = __float2bfloat16(r);
    h = __bfloat16_as_ushort(hb);
    l = __bfloat16_as_ushort(lb);
}

__device__ __forceinline__ void mma16(float* c, const unsigned* a, unsigned b0, unsigned b1) {
    asm volatile(
        "mma.sync.aligned.m16n8k16.row.col.f32.bf16.bf16.f32 "
        "{%0,%1,%2,%3}, {%4,%5,%6,%7}, {%8,%9}, {%0,%1,%2,%3};"
        : "+f"(c[0]), "+f"(c[1]), "+f"(c[2]), "+f"(c[3])
        : "r"(a[0]), "r"(a[1]), "r"(a[2]), "r"(a[3]), "r"(b0), "r"(b1));
}

// xor swizzle: conflict-free LDS.128 / STS.128 for both row-consecutive writers
// and gid-strided fragment readers (verified per 8-lane phase)
__device__ __forceinline__ int swz(int row, int t) {
    return t ^ ((row ^ (row >> 2)) & 3);
}

// ---------------- tensor-core GEMM (3xBF16, ~1e-5 accurate) ----------------
// C = epi(A@W + bias). Tile: BM=128, BN=64, BK=16. 256 threads = 8 warps (4M x 2N).
// EPI: 0 = relu, 1 = relu+bn, 2 = relu+bn + masked max over 64-row neighbor groups.
// GATHER: A rows built on the fly: [feat[nbr] | pos[nbr]-q | 0].
template<int EPI, int GATHER>
__global__ __launch_bounds__(256)
void gemm_tc(const float* __restrict__ A, int lda,
             const float* __restrict__ W, const float* __restrict__ bias,
             const float* __restrict__ gam, const float* __restrict__ bet,
             float* __restrict__ C, int ldc, int M, int N, int K,
             const float* __restrict__ feat, const float* __restrict__ posL,
             const float* __restrict__ q, const int* __restrict__ nbr,
             int nPts, int mCen)
{
    __shared__ uint4 As4[512];   // 128 rows x 4 uint4 (hi2t,hi2t+8,lo2t,lo2t+8) swizzled
    __shared__ uint4 Ws4[256];   // 64 cols x 4 uint4
    __shared__ float sred[2][2][64];

    const int tid  = threadIdx.x;
    const int lane = tid & 31;
    const int warp = tid >> 5;
    const int mwarp = warp >> 1;     // 0..3
    const int nwarp = warp & 1;      // 0..1
    const int gid = lane >> 2;       // 0..7
    const int tig = lane & 3;        // 0..3
    const int bm = blockIdx.y * 128;
    const int bn = blockIdx.x * 64;

    float acc[2][4][4];
#pragma unroll
    for (int mt = 0; mt < 2; mt++)
#pragma unroll
        for (int nt = 0; nt < 4; nt++)
#pragma unroll
            for (int e = 0; e < 4; e++) acc[mt][nt][e] = 0.f;

    // loader roles: tid<128 -> A row tid; 128<=tid<192 -> W col tid-128
    const int gm_ld = bm + tid;       // valid when tid < 128
    int gj = -1, gb = 0, gbc = 0;
    if (GATHER && tid < 128) {
        gj  = nbr[gm_ld];
        gb  = gm_ld / (mCen * 64);
        gbc = gm_ld >> 6;
    }

    for (int k0 = 0; k0 < K; k0 += 16) {
        if (tid < 128) {
            float av[16];
            if (GATHER) {
                if (gj < 0) {
#pragma unroll
                    for (int j = 0; j < 16; j++) av[j] = 0.f;
                } else if (k0 + 16 <= 128) {
                    const float4* fp = (const float4*)(feat + ((size_t)gb * nPts + gj) * 128 + k0);
#pragma unroll
                    for (int i = 0; i < 4; i++) {
                        float4 v = fp[i];
                        av[i * 4]     = v.x; av[i * 4 + 1] = v.y;
                        av[i * 4 + 2] = v.z; av[i * 4 + 3] = v.w;
                    }
                } else {
#pragma unroll
                    for (int j = 0; j < 16; j++) {
                        int gk = k0 + j;
                        float v = 0.f;
                        if (gk < 128) v = feat[((size_t)gb * nPts + gj) * 128 + gk];
                        else if (gk < 131) v = posL[((size_t)gb * nPts + gj) * 3 + (gk - 128)]
                                             - q[(size_t)gbc * 3 + (gk - 128)];
                        av[j] = v;
                    }
                }
            } else {
                if (gm_ld < M && k0 + 16 <= K) {
                    const float4* fp = (const float4*)(A + (size_t)gm_ld * lda + k0);
#pragma unroll
                    for (int i = 0; i < 4; i++) {
                        float4 v = fp[i];
                        av[i * 4]     = v.x; av[i * 4 + 1] = v.y;
                        av[i * 4 + 2] = v.z; av[i * 4 + 3] = v.w;
                    }
                } else {
#pragma unroll
                    for (int j = 0; j < 16; j++) {
                        int gk = k0 + j;
                        av[j] = (gm_ld < M && gk < K) ? A[(size_t)gm_ld * lda + gk] : 0.f;
                    }
                }
            }
            unsigned short hs[16], ls[16];
#pragma unroll
            for (int j = 0; j < 16; j++) splitf(av[j], hs[j], ls[j]);
            const int r = tid;
#pragma unroll
            for (int t = 0; t < 4; t++) {
                uint4 u;
                u.x = (unsigned)hs[2 * t]     | ((unsigned)hs[2 * t + 1] << 16);
                u.y = (unsigned)hs[2 * t + 8] | ((unsigned)hs[2 * t + 9] << 16);
                u.z = (unsigned)ls[2 * t]     | ((unsigned)ls[2 * t + 1] << 16);
                u.w = (unsigned)ls[2 * t + 8] | ((unsigned)ls[2 * t + 9] << 16);
                As4[r * 4 + swz(r, t)] = u;
            }
        } else if (tid < 192) {
            const int n = tid - 128;
            const int gn = bn + n;
            float wv[16];
#pragma unroll
            for (int kk = 0; kk < 16; kk++) {
                int gk = k0 + kk;
                wv[kk] = (gk < K && gn < N) ? W[(size_t)gk * N + gn] : 0.f;
            }
            unsigned short hs[16], ls[16];
#pragma unroll
            for (int j = 0; j < 16; j++) splitf(wv[j], hs[j], ls[j]);
#pragma unroll
            for (int t = 0; t < 4; t++) {
                uint4 u;
                u.x = (unsigned)hs[2 * t]     | ((unsigned)hs[2 * t + 1] << 16);
                u.y = (unsigned)hs[2 * t + 8] | ((unsigned)hs[2 * t + 9] << 16);
                u.z = (unsigned)ls[2 * t]     | ((unsigned)ls[2 * t + 1] << 16);
                u.w = (unsigned)ls[2 * t + 8] | ((unsigned)ls[2 * t + 9] << 16);
                Ws4[n * 4 + swz(n, t)] = u;
            }
        }
        __syncthreads();

        unsigned ah[2][4], al[2][4];
#pragma unroll
        for (int mt = 0; mt < 2; mt++) {
            int mr  = mwarp * 32 + mt * 16 + gid;
            int mr8 = mr + 8;
            uint4 ua = As4[mr * 4 + swz(mr, tig)];
            uint4 ub = As4[mr8 * 4 + swz(mr8, tig)];
            ah[mt][0] = ua.x; ah[mt][1] = ub.x; ah[mt][2] = ua.y; ah[mt][3] = ub.y;
            al[mt][0] = ua.z; al[mt][1] = ub.z; al[mt][2] = ua.w; al[mt][3] = ub.w;
        }
#pragma unroll
        for (int nt = 0; nt < 4; nt++) {
            int nc = nwarp * 32 + nt * 8 + gid;
            uint4 uw = Ws4[nc * 4 + swz(nc, tig)];
#pragma unroll
            for (int mt = 0; mt < 2; mt++) {
                mma16(acc[mt][nt], ah[mt], uw.x, uw.y);
                mma16(acc[mt][nt], ah[mt], uw.z, uw.w);
                mma16(acc[mt][nt], al[mt], uw.x, uw.y);
            }
        }
        __syncthreads();
    }

    const float inv = rsqrtf(1.f + 1e-5f);

    if (EPI < 2) {
#pragma unroll
        for (int mt = 0; mt < 2; mt++) {
#pragma unroll
            for (int nt = 0; nt < 4; nt++) {
#pragma unroll
                for (int e = 0; e < 4; e++) {
                    int gm = bm + mwarp * 32 + mt * 16 + gid + ((e >> 1) ? 8 : 0);
                    int gn = bn + nwarp * 32 + nt * 8 + 2 * tig + (e & 1);
                    if (gm >= M || gn >= N) continue;
                    float v = acc[mt][nt][e] + bias[gn];
                    v = fmaxf(v, 0.f);
                    if (EPI == 1) v = gam[gn] * v * inv + bet[gn];
                    C[(size_t)gm * ldc + gn] = v;
                }
            }
        }
    } else {
        bool val[2][2];
#pragma unroll
        for (int mt = 0; mt < 2; mt++) {
            int r = bm + mwarp * 32 + mt * 16 + gid;
            val[mt][0] = nbr[r] >= 0;
            val[mt][1] = nbr[r + 8] >= 0;
        }
        float cmax[4][2];
#pragma unroll
        for (int nt = 0; nt < 4; nt++) { cmax[nt][0] = -1e30f; cmax[nt][1] = -1e30f; }
#pragma unroll
        for (int mt = 0; mt < 2; mt++) {
#pragma unroll
            for (int nt = 0; nt < 4; nt++) {
                int gn0 = bn + nwarp * 32 + nt * 8 + 2 * tig;
#pragma unroll
                for (int e = 0; e < 4; e++) {
                    int gn = gn0 + (e & 1);
                    if (gn >= N) continue;
                    float v = acc[mt][nt][e] + bias[gn];
                    v = fmaxf(v, 0.f);
                    v = gam[gn] * v * inv + bet[gn];
                    if (val[mt][e >> 1]) {
                        float& m = cmax[nt][e & 1];
                        m = fmaxf(m, v);
                    }
                }
            }
        }
#pragma unroll
        for (int off = 4; off <= 16; off <<= 1) {
#pragma unroll
            for (int nt = 0; nt < 4; nt++) {
                cmax[nt][0] = fmaxf(cmax[nt][0], __shfl_xor_sync(0xffffffffu, cmax[nt][0], off));
                cmax[nt][1] = fmaxf(cmax[nt][1], __shfl_xor_sync(0xffffffffu, cmax[nt][1], off));
            }
        }
        if (gid == 0) {
#pragma unroll
            for (int nt = 0; nt < 4; nt++) {
                sred[mwarp >> 1][mwarp & 1][nwarp * 32 + nt * 8 + 2 * tig]     = cmax[nt][0];
                sred[mwarp >> 1][mwarp & 1][nwarp * 32 + nt * 8 + 2 * tig + 1] = cmax[nt][1];
            }
        }
        __syncthreads();
        if (tid < 128) {
            int c = tid >> 6, col = tid & 63;
            int gn = bn + col;
            if (gn < N) {
                float v = fmaxf(sred[c][0][col], sred[c][1][col]);
                int cen = blockIdx.y * 2 + c;
                C[(size_t)cen * ldc + gn] = v;
            }
        }
    }
}

// ---------------- final tiny layer: out[M,2] = bn(relu(A[M,128] @ W[128,2] + b)) ----------------
__global__ __launch_bounds__(256)
void final_out(const float* __restrict__ A, const float* __restrict__ W,
               const float* __restrict__ bias, const float* __restrict__ gam,
               const float* __restrict__ bet, float* __restrict__ out, int M)
{
    __shared__ float sw[256];
    const int tid = threadIdx.x;
    sw[tid] = W[tid];
    __syncthreads();
    const int row = blockIdx.x * 32 + (tid >> 3);
    const int sub = tid & 7;
    if (row >= M) return;
    const float4* a4 = (const float4*)(A + (size_t)row * 128 + sub * 16);
    float acc0 = 0.f, acc1 = 0.f;
#pragma unroll
    for (int i = 0; i < 4; i++) {
        float4 v = a4[i];
        int k = sub * 16 + i * 4;
        acc0 += v.x * sw[(k + 0) * 2] + v.y * sw[(k + 1) * 2]
              + v.z * sw[(k + 2) * 2] + v.w * sw[(k + 3) * 2];
        acc1 += v.x * sw[(k + 0) * 2 + 1] + v.y * sw[(k + 1) * 2 + 1]
              + v.z * sw[(k + 2) * 2 + 1] + v.w * sw[(k + 3) * 2 + 1];
    }
#pragma unroll
    for (int off = 4; off; off >>= 1) {
        acc0 += __shfl_down_sync(0xffffffffu, acc0, off);
        acc1 += __shfl_down_sync(0xffffffffu, acc1, off);
    }
    if (sub == 0) {
        const float inv = rsqrtf(1.f + 1e-5f);
        float v0 = fmaxf(acc0 + bias[0], 0.f);
        float v1 = fmaxf(acc1 + bias[1], 0.f);
        v0 = gam[0] * v0 * inv + bet[0];
        v1 = gam[1] * v1 * inv + bet[1];
        out[(size_t)row * 2]     = v0;
        out[(size_t)row * 2 + 1] = v1;
    }
}

// ---------------- farthest point sampling ----------------
template<int PER>
__global__ __launch_bounds__(256)
void fps_kernel(const float* __restrict__ pos, int n, int m, float* __restrict__ qout)
{
    const int b = blockIdx.x, tid = threadIdx.x;
    const float* P = pos + (size_t)b * n * 3;
    float* Q = qout + (size_t)b * m * 3;
    float px[PER], py[PER], pz[PER], dmin[PER];
#pragma unroll
    for (int u = 0; u < PER; u++) {
        int i = tid + 256 * u;
        px[u] = P[i * 3]; py[u] = P[i * 3 + 1]; pz[u] = P[i * 3 + 2];
        dmin[u] = 1e30f;
    }
    __shared__ float s_v[8];
    __shared__ int   s_i[8];
    __shared__ float s_q[3];
    if (tid == 0) {
        Q[0] = P[0]; Q[1] = P[1]; Q[2] = P[2];
        s_q[0] = P[0]; s_q[1] = P[1]; s_q[2] = P[2];
    }
    __syncthreads();
    float qx = s_q[0], qy = s_q[1], qz = s_q[2];

    for (int s = 1; s < m; s++) {
        float bv = -1e31f; int bi = 0;
#pragma unroll
        for (int u = 0; u < PER; u++) {
            float dx = px[u] - qx, dy = py[u] - qy, dz = pz[u] - qz;
            float d = dx * dx + dy * dy + dz * dz;
            d = fminf(dmin[u], d);
            dmin[u] = d;
            if (d > bv) { bv = d; bi = tid + 256 * u; }
        }
#pragma unroll
        for (int off = 16; off; off >>= 1) {
            float ov = __shfl_down_sync(0xffffffffu, bv, off);
            int   oi = __shfl_down_sync(0xffffffffu, bi, off);
            if (ov > bv || (ov == bv && oi < bi)) { bv = ov; bi = oi; }
        }
        if ((tid & 31) == 0) { s_v[tid >> 5] = bv; s_i[tid >> 5] = bi; }
        __syncthreads();
        if (tid == 0) {
            float fv = s_v[0]; int fi = s_i[0];
#pragma unroll
            for (int w = 1; w < 8; w++)
                if (s_v[w] > fv || (s_v[w] == fv && s_i[w] < fi)) { fv = s_v[w]; fi = s_i[w]; }
            float xx = P[fi * 3], yy = P[fi * 3 + 1], zz = P[fi * 3 + 2];
            s_q[0] = xx; s_q[1] = yy; s_q[2] = zz;
            Q[s * 3] = xx; Q[s * 3 + 1] = yy; Q[s * 3 + 2] = zz;
        }
        __syncthreads();
        qx = s_q[0]; qy = s_q[1]; qz = s_q[2];
    }
}

// ---------------- ball-query top-K ----------------
__global__ __launch_bounds__(128)
void knn_ball(const float* __restrict__ pos, const float* __restrict__ q,
              int n, int m, int* __restrict__ nbr)
{
    __shared__ float sd[4096];
    __shared__ float s_pv[4];
    __shared__ int   s_pi[4];
    __shared__ int   s_sel;
    const int bc = blockIdx.x;
    const int tid = threadIdx.x;
    const float* P = pos + (size_t)(bc / m) * n * 3;
    const float qx = q[(size_t)bc * 3], qy = q[(size_t)bc * 3 + 1], qz = q[(size_t)bc * 3 + 2];
    for (int i = tid; i < n; i += 128) {
        float dx = P[i * 3] - qx, dy = P[i * 3 + 1] - qy, dz = P[i * 3 + 2] - qz;
        sd[i] = dx * dx + dy * dy + dz * dz;
    }
    __syncthreads();
    int* out = nbr + (size_t)bc * KNB;
    for (int r = 0; r < KNB; r++) {
        float bv = 1e38f; int bi = 0x7fffffff;
        for (int i = tid; i < n; i += 128) {
            float v = sd[i];
            if (v < bv) { bv = v; bi = i; }
        }
#pragma unroll
        for (int off = 16; off; off >>= 1) {
            float ov = __shfl_down_sync(0xffffffffu, bv, off);
            int   oi = __shfl_down_sync(0xffffffffu, bi, off);
            if (ov < bv || (ov == bv && oi < bi)) { bv = ov; bi = oi; }
        }
        if ((tid & 31) == 0) { s_pv[tid >> 5] = bv; s_pi[tid >> 5] = bi; }
        __syncthreads();
        if (tid == 0) {
            float fv = s_pv[0]; int fi = s_pi[0];
#pragma unroll
            for (int w = 1; w < 4; w++)
                if (s_pv[w] < fv || (s_pv[w] == fv && s_pi[w] < fi)) { fv = s_pv[w]; fi = s_pi[w]; }
            if (fv <= 4.0f) { out[r] = fi; sd[fi] = 1e38f; s_sel = 1; }
            else s_sel = 0;
        }
        __syncthreads();
        if (!s_sel) {
            for (int rr = r + tid; rr < KNB; rr += 128) out[rr] = -1;
            break;
        }
    }
}

// ---------------- FP 3-NN interpolation + skip concat ----------------
__global__ __launch_bounds__(256)
void fp_interp(const float* __restrict__ cf, const float* __restrict__ cp,
               const float* __restrict__ fpos, const float* __restrict__ sf,
               int nc, int nf, float* __restrict__ fin)
{
    __shared__ float sp[2048 * 3];
    const int bpb = nf >> 8;
    const int b = blockIdx.x / bpb;
    const int i = (blockIdx.x % bpb) * 256 + threadIdx.x;
    for (int t = threadIdx.x; t < nc * 3; t += 256) sp[t] = cp[(size_t)b * nc * 3 + t];
    __syncthreads();
    const float px = fpos[((size_t)b * nf + i) * 3];
    const float py = fpos[((size_t)b * nf + i) * 3 + 1];
    const float pz = fpos[((size_t)b * nf + i) * 3 + 2];
    float bd0 = 1e38f, bd1 = 1e38f, bd2 = 1e38f;
    int bi0 = 0, bi1 = 0, bi2 = 0;
    for (int j = 0; j < nc; j++) {
        float dx = px - sp[j * 3], dy = py - sp[j * 3 + 1], dz = pz - sp[j * 3 + 2];
        float d = dx * dx + dy * dy + dz * dz;
        if (d < bd0)      { bd2 = bd1; bi2 = bi1; bd1 = bd0; bi1 = bi0; bd0 = d; bi0 = j; }
        else if (d < bd1) { bd2 = bd1; bi2 = bi1; bd1 = d; bi1 = j; }
        else if (d < bd2) { bd2 = d; bi2 = j; }
    }
    const float w0 = 1.f / fmaxf(bd0, 1e-16f);
    const float w1 = 1.f / fmaxf(bd1, 1e-16f);
    const float w2 = 1.f / fmaxf(bd2, 1e-16f);
    const float rws = 1.f / (w0 + w1 + w2);
    const float4* f0 = (const float4*)(cf + ((size_t)b * nc + bi0) * 128);
    const float4* f1 = (const float4*)(cf + ((size_t)b * nc + bi1) * 128);
    const float4* f2 = (const float4*)(cf + ((size_t)b * nc + bi2) * 128);
    const float4* s4 = (const float4*)(sf + ((size_t)b * nf + i) * 128);
    float4* o4 = (float4*)(fin + ((size_t)b * nf + i) * 256);
#pragma unroll 8
    for (int f = 0; f < 32; f++) {
        float4 a = f0[f], bb = f1[f], cc = f2[f];
        float4 r;
        r.x = (w0 * a.x + w1 * bb.x + w2 * cc.x) * rws;
        r.y = (w0 * a.y + w1 * bb.y + w2 * cc.y) * rws;
        r.z = (w0 * a.z + w1 * bb.z + w2 * cc.z) * rws;
        r.w = (w0 * a.w + w1 * bb.w + w2 * cc.w) * rws;
        o4[f] = r;
        o4[32 + f] = s4[f];
    }
}

// ---------------- host ----------------
extern "C" void kernel_launch(void* const* d_in, const int* in_sizes, int n_in,
                              void* d_out, int out_size)
{
    const float* x      = (const float*)d_in[0];
    const float* pos0   = (const float*)d_in[1];
    const float* lin_w  = (const float*)d_in[3];
    const float* lin_b  = (const float*)d_in[4];
    const float* sa_w1  = (const float*)d_in[5];
    const float* sa_b1  = (const float*)d_in[6];
    const float* sa_g1  = (const float*)d_in[7];
    const float* sa_be1 = (const float*)d_in[8];
    const float* sa_w2  = (const float*)d_in[9];
    const float* sa_b2  = (const float*)d_in[10];
    const float* sa_g2  = (const float*)d_in[11];
    const float* sa_be2 = (const float*)d_in[12];
    const float* fp_w1  = (const float*)d_in[13];
    const float* fp_b1  = (const float*)d_in[14];
    const float* fp_g1  = (const float*)d_in[15];
    const float* fp_be1 = (const float*)d_in[16];
    const float* fp_w2  = (const float*)d_in[17];
    const float* fp_b2  = (const float*)d_in[18];
    const float* fp_g2  = (const float*)d_in[19];
    const float* fp_be2 = (const float*)d_in[20];
    const float* lo_w1  = (const float*)d_in[21];
    const float* lo_b1  = (const float*)d_in[22];
    const float* lo_g1  = (const float*)d_in[23];
    const float* lo_be1 = (const float*)d_in[24];
    const float* lo_w2  = (const float*)d_in[25];
    const float* lo_b2  = (const float*)d_in[26];
    const float* lo_g2  = (const float*)d_in[27];
    const float* lo_be2 = (const float*)d_in[28];
    float* out = (float*)d_out;

    float* buf = nullptr;
    cudaGetSymbolAddress((void**)&buf, g_buf);

    float* feat[4] = { buf + OFF_FEAT0, buf + OFF_FEAT1, buf + OFF_FEAT2, buf + OFF_FEAT3 };
    const float* posl[4] = { pos0, buf + OFF_POS1, buf + OFF_POS2, buf + OFF_POS3 };
    int*   nbr = (int*)(buf + OFF_NBR);
    float* h1  = buf + OFF_H1;
    float* fin = buf + OFF_FIN;
    float* f1  = buf + OFF_F1;
    float* xf  = buf + OFF_XF;

    const int nlev[4] = {4096, 2048, 1024, 512};

    // lin_in + ReLU
    {
        dim3 grid((128 + 63) / 64, (NBATCH * 4096) / 128);
        gemm_tc<0, 0><<<grid, 256>>>(x, 16, lin_w, lin_b, nullptr, nullptr,
                                     feat[0], 128, NBATCH * 4096, 128, 16,
                                     nullptr, nullptr, nullptr, nullptr, 0, 0);
    }

    // ---- SA levels ----
    for (int l = 0; l < 3; l++) {
        int n = nlev[l], m = nlev[l + 1];
        if (l == 0)      fps_kernel<16><<<NBATCH, 256>>>(posl[0], n, m, (float*)posl[1]);
        else if (l == 1) fps_kernel<8><<<NBATCH, 256>>>(posl[1], n, m, (float*)posl[2]);
        else             fps_kernel<4><<<NBATCH, 256>>>(posl[2], n, m, (float*)posl[3]);

        knn_ball<<<NBATCH * m, 128>>>(posl[l], posl[l + 1], n, m, nbr);

        int rows = NBATCH * m * KNB;
        {
            dim3 grid((131 + 63) / 64, rows / 128);
            gemm_tc<1, 1><<<grid, 256>>>(nullptr, 0,
                                         sa_w1 + (size_t)l * 131 * 131, sa_b1 + l * 131,
                                         sa_g1 + l * 131, sa_be1 + l * 131,
                                         h1, 132, rows, 131, 131,
                                         feat[l], posl[l], posl[l + 1], nbr, n, m);
        }
        {
            dim3 grid((128 + 63) / 64, rows / 128);
            gemm_tc<2, 0><<<grid, 256>>>(h1, 132,
                                         sa_w2 + (size_t)l * 131 * 128, sa_b2 + l * 128,
                                         sa_g2 + l * 128, sa_be2 + l * 128,
                                         feat[l + 1], 128, rows, 128, 131,
                                         nullptr, nullptr, nullptr, nbr, n, m);
        }
    }

    // ---- FP levels ----
    const float* cfeat = feat[3];
    for (int step = 0; step < 3; step++) {
        int mi = 2 - step;
        int nc = nlev[mi + 1], nf = nlev[mi];
        fp_interp<<<NBATCH * (nf / 256), 256>>>(cfeat, posl[mi + 1], posl[mi], feat[mi], nc, nf, fin);
        int rows = NBATCH * nf;
        {
            dim3 grid((256 + 63) / 64, rows / 128);
            gemm_tc<1, 0><<<grid, 256>>>(fin, 256,
                                         fp_w1 + (size_t)mi * 256 * 256, fp_b1 + mi * 256,
                                         fp_g1 + mi * 256, fp_be1 + mi * 256,
                                         f1, 256, rows, 256, 256,
                                         nullptr, nullptr, nullptr, nullptr, 0, 0);
        }
        {
            dim3 grid((128 + 63) / 64, rows / 128);
            gemm_tc<1, 0><<<grid, 256>>>(f1, 256,
                                         fp_w2 + (size_t)mi * 256 * 128, fp_b2 + mi * 128,
                                         fp_g2 + mi * 128, fp_be2 + mi * 128,
                                         xf, 128, rows, 128, 256,
                                         nullptr, nullptr, nullptr, nullptr, 0, 0);
        }
        cfeat = xf;
    }

    // ---- final MLP ----
    {
        dim3 grid((128 + 63) / 64, (NBATCH * 4096) / 128);
        gemm_tc<1, 0><<<grid, 256>>>(xf, 128, lo_w1, lo_b1, lo_g1, lo_be1,
                                     f1, 128, NBATCH * 4096, 128, 128,
                                     nullptr, nullptr, nullptr, nullptr, 0, 0);
    }
    final_out<<<(NBATCH * 4096) / 32, 256>>>(f1, lo_w2, lo_b2, lo_g2, lo_be2,
                                             out, NBATCH * 4096);
}

// round 7
// speedup vs baseline: 1.6430x; 1.0630x over previous
#include <cuda_runtime.h>
#include <cuda_bf16.h>
#include <cstddef>

#define NBATCH 4
#define KNB 64

// ---------------- scratch layout (floats) ----------------
#define OFF_FEAT0 0ull
#define OFF_FEAT1 2097152ull
#define OFF_FEAT2 3145728ull
#define OFF_FEAT3 3670016ull
#define OFF_POS1  3932160ull
#define OFF_POS2  3956736ull
#define OFF_POS3  3969024ull
#define OFF_NBR   3975168ull
#define OFF_FIN   4499456ull
#define OFF_F1    8693760ull
#define OFF_XF    12888064ull
#define OFF_WT    14985216ull
#define OFF_H1    15509504ull
#define TOTAL_FLOATS 91006976ull

__device__ __align__(256) float g_buf[TOTAL_FLOATS];

// ---- WT sub-offsets (uint32 elements inside WT region) ----
#define WTO_LIN   0
#define WTO_SAW1  2048      // + l*18864   (Kp=144, N=131)
#define WTO_SAW2  58640     // + l*18432   (Kp=144, N=128)
#define WTO_FPW1  113936    // + l*65536   (Kp=256, N=256)
#define WTO_FPW2  310544    // + l*32768   (Kp=256, N=128)
#define WTO_LOW1  408848    //             (Kp=128, N=128)

// ---------------- bf16 helpers ----------------
__device__ __forceinline__ float bf2f(unsigned s16) {       // s16 in low 16 bits
    return __uint_as_float(s16 << 16);
}
__device__ __forceinline__ void split2(float a, float b, unsigned& hw, unsigned& lw) {
    __nv_bfloat16 ah = __float2bfloat16(a), bh = __float2bfloat16(b);
    float ar = a - __bfloat162float(ah);
    float br = b - __bfloat162float(bh);
    hw = (unsigned)__bfloat16_as_ushort(ah) | ((unsigned)__bfloat16_as_ushort(bh) << 16);
    lw = (unsigned)__bfloat16_as_ushort(__float2bfloat16(ar))
       | ((unsigned)__bfloat16_as_ushort(__float2bfloat16(br)) << 16);
}
// packed store of a (col g0, col g0+1) fp32 pair into hi/lo packed layout
__device__ __forceinline__ void store_pair(unsigned* C, int KpOut, int row, int g0,
                                           float v0, float v1) {
    unsigned hw, lw;
    split2(v0, v1, hw, lw);
    size_t off = ((size_t)row * (KpOut >> 2) + ((g0 >> 4) << 2) + ((g0 & 7) >> 1)) * 4
               + ((g0 >> 3) & 1);
    C[off]     = hw;
    C[off + 2] = lw;
}

__device__ __forceinline__ void mma16(float* c, const unsigned* a, unsigned b0, unsigned b1) {
    asm volatile(
        "mma.sync.aligned.m16n8k16.row.col.f32.bf16.bf16.f32 "
        "{%0,%1,%2,%3}, {%4,%5,%6,%7}, {%8,%9}, {%0,%1,%2,%3};"
        : "+f"(c[0]), "+f"(c[1]), "+f"(c[2]), "+f"(c[3])
        : "r"(a[0]), "r"(a[1]), "r"(a[2]), "r"(a[3]), "r"(b0), "r"(b1));
}

__device__ __forceinline__ int swz(int row, int t) {
    return t ^ ((row ^ (row >> 2)) & 3);
}

// ---------------- weight preprocess: W[K,N] fp32 -> packed [N][Kp] hi/lo uint4 stream ----------------
__global__ void wconv(const float* __restrict__ W, int K, int N, int Kp,
                      uint4* __restrict__ out)
{
    int idx = blockIdx.x * blockDim.x + threadIdx.x;
    int total = N * (Kp >> 4) * 4;
    if (idx >= total) return;
    int t = idx & 3;
    int c = (idx >> 2) % (Kp >> 4);
    int n = idx / ((Kp >> 4) * 4);
    int k0 = 16 * c + 2 * t;
    float v0 = (k0     < K) ? W[(size_t)(k0    ) * N + n] : 0.f;
    float v1 = (k0 + 1 < K) ? W[(size_t)(k0 + 1) * N + n] : 0.f;
    float v2 = (k0 + 8 < K) ? W[(size_t)(k0 + 8) * N + n] : 0.f;
    float v3 = (k0 + 9 < K) ? W[(size_t)(k0 + 9) * N + n] : 0.f;
    uint4 u;
    split2(v0, v1, u.x, u.z);
    split2(v2, v3, u.y, u.w);
    out[idx] = u;
}

// ---------------- tensor-core GEMM (3xBF16), packed hi/lo I/O ----------------
// EPI: 0 = relu, 1 = relu+bn, 2 = relu+bn + masked max over 64-row groups.
// ASRC: 0 = fp32 A (lda), 1 = packed A, 2 = gather from packed feat + pos delta.
template<int EPI, int ASRC>
__global__ __launch_bounds__(256)
void gemm_tc(const float* __restrict__ Afp, int lda,
             const uint4* __restrict__ Apk,
             const uint4* __restrict__ Wt,
             const float* __restrict__ bias, const float* __restrict__ gam,
             const float* __restrict__ bet,
             unsigned* __restrict__ Cpk, int KpOut, int M, int N, int Kp,
             const uint4* __restrict__ featPk, const float* __restrict__ posL,
             const float* __restrict__ q, const int* __restrict__ nbr,
             int nPts, int mCen)
{
    __shared__ uint4 As4[512];
    __shared__ uint4 Ws4[256];
    __shared__ float sred[2][2][64];

    const int tid  = threadIdx.x;
    const int lane = tid & 31;
    const int warp = tid >> 5;
    const int mwarp = warp >> 1;
    const int nwarp = warp & 1;
    const int gid = lane >> 2;
    const int tig = lane & 3;
    const int bm = blockIdx.y * 128;
    const int bn = blockIdx.x * 64;

    float acc[2][4][4];
#pragma unroll
    for (int mt = 0; mt < 2; mt++)
#pragma unroll
        for (int nt = 0; nt < 4; nt++)
#pragma unroll
            for (int e = 0; e < 4; e++) acc[mt][nt][e] = 0.f;

    // gather row metadata
    int gj = -1, gb = 0, gbc = 0;
    if (ASRC == 2 && tid < 128) {
        int gm = bm + tid;
        gj  = nbr[gm];
        gb  = gm / (mCen * 64);
        gbc = gm >> 6;
    }

    const int rowU4 = Kp >> 2;   // uint4 per packed A row

    for (int k0 = 0; k0 < Kp; k0 += 16) {
        if (tid < 128) {
            const int r = tid;
            uint4 u[4];
            if (ASRC == 1) {
                const uint4* p = Apk + (size_t)(bm + r) * rowU4 + (k0 >> 4) * 4;
                u[0] = p[0]; u[1] = p[1]; u[2] = p[2]; u[3] = p[3];
            } else if (ASRC == 2) {
                if (gj < 0) {
                    u[0] = u[1] = u[2] = u[3] = make_uint4(0, 0, 0, 0);
                } else if (k0 < 128) {
                    const uint4* p = featPk + ((size_t)gb * nPts + gj) * 32 + (k0 >> 4) * 4;
                    u[0] = p[0]; u[1] = p[1]; u[2] = p[2]; u[3] = p[3];
                } else {
                    // cols 128..130 = pos[nbr] - q, rest zero
                    const float* pp = posL + ((size_t)gb * nPts + gj) * 3;
                    const float* qq = q + (size_t)gbc * 3;
                    float d0 = pp[0] - qq[0], d1 = pp[1] - qq[1], d2 = pp[2] - qq[2];
                    unsigned h01, l01, h2z, l2z;
                    split2(d0, d1, h01, l01);
                    split2(d2, 0.f, h2z, l2z);
                    u[0] = make_uint4(h01, 0, l01, 0);
                    u[1] = make_uint4(h2z, 0, l2z, 0);
                    u[2] = make_uint4(0, 0, 0, 0);
                    u[3] = make_uint4(0, 0, 0, 0);
                }
            } else { // fp32 A (lin_in, Kp==16 single chunk)
                float av[16];
                const float4* fp = (const float4*)(Afp + (size_t)(bm + r) * lda + k0);
#pragma unroll
                for (int i = 0; i < 4; i++) {
                    float4 v = fp[i];
                    av[i * 4]     = v.x; av[i * 4 + 1] = v.y;
                    av[i * 4 + 2] = v.z; av[i * 4 + 3] = v.w;
                }
#pragma unroll
                for (int t = 0; t < 4; t++) {
                    split2(av[2 * t],     av[2 * t + 1], u[t].x, u[t].z);
                    split2(av[2 * t + 8], av[2 * t + 9], u[t].y, u[t].w);
                }
            }
#pragma unroll
            for (int t = 0; t < 4; t++) As4[r * 4 + swz(r, t)] = u[t];
        } else if (tid < 192) {
            const int n = tid - 128;
            const int gn = bn + n;
            uint4 u[4];
            if (gn < N) {
                const uint4* p = Wt + (size_t)gn * rowU4 + (k0 >> 4) * 4;
                u[0] = p[0]; u[1] = p[1]; u[2] = p[2]; u[3] = p[3];
            } else {
                u[0] = u[1] = u[2] = u[3] = make_uint4(0, 0, 0, 0);
            }
#pragma unroll
            for (int t = 0; t < 4; t++) Ws4[n * 4 + swz(n, t)] = u[t];
        }
        __syncthreads();

        unsigned ah[2][4], al[2][4];
#pragma unroll
        for (int mt = 0; mt < 2; mt++) {
            int mr  = mwarp * 32 + mt * 16 + gid;
            int mr8 = mr + 8;
            uint4 ua = As4[mr * 4 + swz(mr, tig)];
            uint4 ub = As4[mr8 * 4 + swz(mr8, tig)];
            ah[mt][0] = ua.x; ah[mt][1] = ub.x; ah[mt][2] = ua.y; ah[mt][3] = ub.y;
            al[mt][0] = ua.z; al[mt][1] = ub.z; al[mt][2] = ua.w; al[mt][3] = ub.w;
        }
#pragma unroll
        for (int nt = 0; nt < 4; nt++) {
            int nc = nwarp * 32 + nt * 8 + gid;
            uint4 uw = Ws4[nc * 4 + swz(nc, tig)];
#pragma unroll
            for (int mt = 0; mt < 2; mt++) {
                mma16(acc[mt][nt], ah[mt], uw.x, uw.y);
                mma16(acc[mt][nt], ah[mt], uw.z, uw.w);
                mma16(acc[mt][nt], al[mt], uw.x, uw.y);
            }
        }
        __syncthreads();
    }

    const float inv = rsqrtf(1.f + 1e-5f);

    if (EPI < 2) {
#pragma unroll
        for (int mt = 0; mt < 2; mt++) {
#pragma unroll
            for (int nt = 0; nt < 4; nt++) {
                int g0 = bn + nwarp * 32 + nt * 8 + 2 * tig;
                if (g0 + 1 >= KpOut && g0 >= N) continue;
#pragma unroll
                for (int rr = 0; rr < 2; rr++) {
                    int row = bm + mwarp * 32 + mt * 16 + gid + rr * 8;
                    float v0 = acc[mt][nt][rr * 2];
                    float v1 = acc[mt][nt][rr * 2 + 1];
                    if (g0 < N) {
                        v0 = fmaxf(v0 + bias[g0], 0.f);
                        if (EPI == 1) v0 = gam[g0] * v0 * inv + bet[g0];
                    } else v0 = 0.f;
                    if (g0 + 1 < N) {
                        v1 = fmaxf(v1 + bias[g0 + 1], 0.f);
                        if (EPI == 1) v1 = gam[g0 + 1] * v1 * inv + bet[g0 + 1];
                    } else v1 = 0.f;
                    if (g0 + 1 < KpOut + 1 && g0 < KpOut)
                        store_pair(Cpk, KpOut, row, g0, v0, v1);
                }
            }
        }
    } else {
        bool val[2][2];
#pragma unroll
        for (int mt = 0; mt < 2; mt++) {
            int r = bm + mwarp * 32 + mt * 16 + gid;
            val[mt][0] = nbr[r] >= 0;
            val[mt][1] = nbr[r + 8] >= 0;
        }
        float cmax[4][2];
#pragma unroll
        for (int nt = 0; nt < 4; nt++) { cmax[nt][0] = -1e30f; cmax[nt][1] = -1e30f; }
#pragma unroll
        for (int mt = 0; mt < 2; mt++) {
#pragma unroll
            for (int nt = 0; nt < 4; nt++) {
                int gn0 = bn + nwarp * 32 + nt * 8 + 2 * tig;
#pragma unroll
                for (int e = 0; e < 4; e++) {
                    int gn = gn0 + (e & 1);
                    float v = acc[mt][nt][e] + bias[gn];
                    v = fmaxf(v, 0.f);
                    v = gam[gn] * v * inv + bet[gn];
                    if (val[mt][e >> 1]) {
                        float& m = cmax[nt][e & 1];
                        m = fmaxf(m, v);
                    }
                }
            }
        }
#pragma unroll
        for (int off = 4; off <= 16; off <<= 1) {
#pragma unroll
            for (int nt = 0; nt < 4; nt++) {
                cmax[nt][0] = fmaxf(cmax[nt][0], __shfl_xor_sync(0xffffffffu, cmax[nt][0], off));
                cmax[nt][1] = fmaxf(cmax[nt][1], __shfl_xor_sync(0xffffffffu, cmax[nt][1], off));
            }
        }
        if (gid == 0) {
#pragma unroll
            for (int nt = 0; nt < 4; nt++) {
                sred[mwarp >> 1][mwarp & 1][nwarp * 32 + nt * 8 + 2 * tig]     = cmax[nt][0];
                sred[mwarp >> 1][mwarp & 1][nwarp * 32 + nt * 8 + 2 * tig + 1] = cmax[nt][1];
            }
        }
        __syncthreads();
        if (tid < 64) {
            int center = tid >> 5;
            int pr = tid & 31;
            int g0 = bn + pr * 2;
            float v0 = fmaxf(sred[center][0][pr * 2],     sred[center][1][pr * 2]);
            float v1 = fmaxf(sred[center][0][pr * 2 + 1], sred[center][1][pr * 2 + 1]);
            int row = blockIdx.y * 2 + center;
            store_pair(Cpk, KpOut, row, g0, v0, v1);
        }
    }
}

// ---------------- final tiny layer: packed A[M,128] -> out[M,2] fp32 ----------------
__global__ __launch_bounds__(256)
void final_out(const uint4* __restrict__ Apk, const float* __restrict__ W,
               const float* __restrict__ bias, const float* __restrict__ gam,
               const float* __restrict__ bet, float* __restrict__ out, int M)
{
    __shared__ float sw[256];
    const int tid = threadIdx.x;
    sw[tid] = W[tid];
    __syncthreads();
    const int row = blockIdx.x * 32 + (tid >> 3);
    const int sub = tid & 7;
    if (row >= M) return;
    const uint4* a4 = Apk + (size_t)row * 32 + sub * 4;
    float acc0 = 0.f, acc1 = 0.f;
#pragma unroll
    for (int i = 0; i < 4; i++) {
        uint4 u = a4[i];
        int g = sub * 4 + i;
        int e0 = 16 * (g >> 2) + 2 * (g & 3);
        float va = bf2f(u.x & 0xffff) + bf2f(u.z & 0xffff);
        float vb = bf2f(u.x >> 16)    + bf2f(u.z >> 16);
        float vc = bf2f(u.y & 0xffff) + bf2f(u.w & 0xffff);
        float vd = bf2f(u.y >> 16)    + bf2f(u.w >> 16);
        acc0 += va * sw[e0 * 2]        + vb * sw[(e0 + 1) * 2]
              + vc * sw[(e0 + 8) * 2]  + vd * sw[(e0 + 9) * 2];
        acc1 += va * sw[e0 * 2 + 1]       + vb * sw[(e0 + 1) * 2 + 1]
              + vc * sw[(e0 + 8) * 2 + 1] + vd * sw[(e0 + 9) * 2 + 1];
    }
#pragma unroll
    for (int off = 4; off; off >>= 1) {
        acc0 += __shfl_down_sync(0xffffffffu, acc0, off);
        acc1 += __shfl_down_sync(0xffffffffu, acc1, off);
    }
    if (sub == 0) {
        const float inv = rsqrtf(1.f + 1e-5f);
        float v0 = fmaxf(acc0 + bias[0], 0.f);
        float v1 = fmaxf(acc1 + bias[1], 0.f);
        v0 = gam[0] * v0 * inv + bet[0];
        v1 = gam[1] * v1 * inv + bet[1];
        out[(size_t)row * 2]     = v0;
        out[(size_t)row * 2 + 1] = v1;
    }
}

// ---------------- farthest point sampling ----------------
template<int PER>
__global__ __launch_bounds__(256)
void fps_kernel(const float* __restrict__ pos, int n, int m, float* __restrict__ qout)
{
    const int b = blockIdx.x, tid = threadIdx.x;
    const float* P = pos + (size_t)b * n * 3;
    float* Q = qout + (size_t)b * m * 3;
    float px[PER], py[PER], pz[PER], dmin[PER];
#pragma unroll
    for (int u = 0; u < PER; u++) {
        int i = tid + 256 * u;
        px[u] = P[i * 3]; py[u] = P[i * 3 + 1]; pz[u] = P[i * 3 + 2];
        dmin[u] = 1e30f;
    }
    __shared__ float s_v[8];
    __shared__ int   s_i[8];
    __shared__ float s_q[3];
    if (tid == 0) {
        Q[0] = P[0]; Q[1] = P[1]; Q[2] = P[2];
        s_q[0] = P[0]; s_q[1] = P[1]; s_q[2] = P[2];
    }
    __syncthreads();
    float qx = s_q[0], qy = s_q[1], qz = s_q[2];

    for (int s = 1; s < m; s++) {
        float bv = -1e31f; int bi = 0;
#pragma unroll
        for (int u = 0; u < PER; u++) {
            float dx = px[u] - qx, dy = py[u] - qy, dz = pz[u] - qz;
            float d = dx * dx + dy * dy + dz * dz;
            d = fminf(dmin[u], d);
            dmin[u] = d;
            if (d > bv) { bv = d; bi = tid + 256 * u; }
        }
#pragma unroll
        for (int off = 16; off; off >>= 1) {
            float ov = __shfl_down_sync(0xffffffffu, bv, off);
            int   oi = __shfl_down_sync(0xffffffffu, bi, off);
            if (ov > bv || (ov == bv && oi < bi)) { bv = ov; bi = oi; }
        }
        if ((tid & 31) == 0) { s_v[tid >> 5] = bv; s_i[tid >> 5] = bi; }
        __syncthreads();
        if (tid == 0) {
            float fv = s_v[0]; int fi = s_i[0];
#pragma unroll
            for (int w = 1; w < 8; w++)
                if (s_v[w] > fv || (s_v[w] == fv && s_i[w] < fi)) { fv = s_v[w]; fi = s_i[w]; }
            float xx = P[fi * 3], yy = P[fi * 3 + 1], zz = P[fi * 3 + 2];
            s_q[0] = xx; s_q[1] = yy; s_q[2] = zz;
            Q[s * 3] = xx; Q[s * 3 + 1] = yy; Q[s * 3 + 2] = zz;
        }
        __syncthreads();
        qx = s_q[0]; qy = s_q[1]; qz = s_q[2];
    }
}

// ---------------- ball-query top-K ----------------
__global__ __launch_bounds__(128)
void knn_ball(const float* __restrict__ pos, const float* __restrict__ q,
              int n, int m, int* __restrict__ nbr)
{
    __shared__ float sd[4096];
    __shared__ float s_pv[4];
    __shared__ int   s_pi[4];
    __shared__ int   s_sel;
    const int bc = blockIdx.x;
    const int tid = threadIdx.x;
    const float* P = pos + (size_t)(bc / m) * n * 3;
    const float qx = q[(size_t)bc * 3], qy = q[(size_t)bc * 3 + 1], qz = q[(size_t)bc * 3 + 2];
    for (int i = tid; i < n; i += 128) {
        float dx = P[i * 3] - qx, dy = P[i * 3 + 1] - qy, dz = P[i * 3 + 2] - qz;
        sd[i] = dx * dx + dy * dy + dz * dz;
    }
    __syncthreads();
    int* out = nbr + (size_t)bc * KNB;
    for (int r = 0; r < KNB; r++) {
        float bv = 1e38f; int bi = 0x7fffffff;
        for (int i = tid; i < n; i += 128) {
            float v = sd[i];
            if (v < bv) { bv = v; bi = i; }
        }
#pragma unroll
        for (int off = 16; off; off >>= 1) {
            float ov = __shfl_down_sync(0xffffffffu, bv, off);
            int   oi = __shfl_down_sync(0xffffffffu, bi, off);
            if (ov < bv || (ov == bv && oi < bi)) { bv = ov; bi = oi; }
        }
        if ((tid & 31) == 0) { s_pv[tid >> 5] = bv; s_pi[tid >> 5] = bi; }
        __syncthreads();
        if (tid == 0) {
            float fv = s_pv[0]; int fi = s_pi[0];
#pragma unroll
            for (int w = 1; w < 4; w++)
                if (s_pv[w] < fv || (s_pv[w] == fv && s_pi[w] < fi)) { fv = s_pv[w]; fi = s_pi[w]; }
            if (fv <= 4.0f) { out[r] = fi; sd[fi] = 1e38f; s_sel = 1; }
            else s_sel = 0;
        }
        __syncthreads();
        if (!s_sel) {
            for (int rr = r + tid; rr < KNB; rr += 128) out[rr] = -1;
            break;
        }
    }
}

// ---------------- FP 3-NN interpolation + skip concat (packed IO) ----------------
__global__ __launch_bounds__(256)
void fp_interp(const uint4* __restrict__ cf, const float* __restrict__ cp,
               const float* __restrict__ fpos, const uint4* __restrict__ sf,
               int nc, int nf, uint4* __restrict__ fin)
{
    __shared__ float sp[2048 * 3];
    const int bpb = nf >> 8;
    const int b = blockIdx.x / bpb;
    const int i = (blockIdx.x % bpb) * 256 + threadIdx.x;
    for (int t = threadIdx.x; t < nc * 3; t += 256) sp[t] = cp[(size_t)b * nc * 3 + t];
    __syncthreads();
    const float px = fpos[((size_t)b * nf + i) * 3];
    const float py = fpos[((size_t)b * nf + i) * 3 + 1];
    const float pz = fpos[((size_t)b * nf + i) * 3 + 2];
    float bd0 = 1e38f, bd1 = 1e38f, bd2 = 1e38f;
    int bi0 = 0, bi1 = 0, bi2 = 0;
    for (int j = 0; j < nc; j++) {
        float dx = px - sp[j * 3], dy = py - sp[j * 3 + 1], dz = pz - sp[j * 3 + 2];
        float d = dx * dx + dy * dy + dz * dz;
        if (d < bd0)      { bd2 = bd1; bi2 = bi1; bd1 = bd0; bi1 = bi0; bd0 = d; bi0 = j; }
        else if (d < bd1) { bd2 = bd1; bi2 = bi1; bd1 = d; bi1 = j; }
        else if (d < bd2) { bd2 = d; bi2 = j; }
    }
    const float w0 = 1.f / fmaxf(bd0, 1e-16f);
    const float w1 = 1.f / fmaxf(bd1, 1e-16f);
    const float w2 = 1.f / fmaxf(bd2, 1e-16f);
    const float rws = 1.f / (w0 + w1 + w2);
    const uint4* f0 = cf + ((size_t)b * nc + bi0) * 32;
    const uint4* f1 = cf + ((size_t)b * nc + bi1) * 32;
    const uint4* f2 = cf + ((size_t)b * nc + bi2) * 32;
    const uint4* s4 = sf + ((size_t)b * nf + i) * 32;
    uint4* o4 = fin + ((size_t)b * nf + i) * 64;
#pragma unroll 8
    for (int u = 0; u < 32; u++) {
        uint4 a = f0[u], bb = f1[u], cc = f2[u];
        float ra = (w0 * (bf2f(a.x & 0xffff) + bf2f(a.z & 0xffff))
                  + w1 * (bf2f(bb.x & 0xffff) + bf2f(bb.z & 0xffff))
                  + w2 * (bf2f(cc.x & 0xffff) + bf2f(cc.z & 0xffff))) * rws;
        float rb = (w0 * (bf2f(a.x >> 16) + bf2f(a.z >> 16))
                  + w1 * (bf2f(bb.x >> 16) + bf2f(bb.z >> 16))
                  + w2 * (bf2f(cc.x >> 16) + bf2f(cc.z >> 16))) * rws;
        float rc = (w0 * (bf2f(a.y & 0xffff) + bf2f(a.w & 0xffff))
                  + w1 * (bf2f(bb.y & 0xffff) + bf2f(bb.w & 0xffff))
                  + w2 * (bf2f(cc.y & 0xffff) + bf2f(cc.w & 0xffff))) * rws;
        float rd = (w0 * (bf2f(a.y >> 16) + bf2f(a.w >> 16))
                  + w1 * (bf2f(bb.y >> 16) + bf2f(bb.w >> 16))
                  + w2 * (bf2f(cc.y >> 16) + bf2f(cc.w >> 16))) * rws;
        uint4 r;
        split2(ra, rb, r.x, r.z);
        split2(rc, rd, r.y, r.w);
        o4[u] = r;
        o4[32 + u] = s4[u];
    }
}

// ---------------- host ----------------
extern "C" void kernel_launch(void* const* d_in, const int* in_sizes, int n_in,
                              void* d_out, int out_size)
{
    const float* x      = (const float*)d_in[0];
    const float* pos0   = (const float*)d_in[1];
    const float* lin_w  = (const float*)d_in[3];
    const float* lin_b  = (const float*)d_in[4];
    const float* sa_w1  = (const float*)d_in[5];
    const float* sa_b1  = (const float*)d_in[6];
    const float* sa_g1  = (const float*)d_in[7];
    const float* sa_be1 = (const float*)d_in[8];
    const float* sa_w2  = (const float*)d_in[9];
    const float* sa_b2  = (const float*)d_in[10];
    const float* sa_g2  = (const float*)d_in[11];
    const float* sa_be2 = (const float*)d_in[12];
    const float* fp_w1  = (const float*)d_in[13];
    const float* fp_b1  = (const float*)d_in[14];
    const float* fp_g1  = (const float*)d_in[15];
    const float* fp_be1 = (const float*)d_in[16];
    const float* fp_w2  = (const float*)d_in[17];
    const float* fp_b2  = (const float*)d_in[18];
    const float* fp_g2  = (const float*)d_in[19];
    const float* fp_be2 = (const float*)d_in[20];
    const float* lo_w1  = (const float*)d_in[21];
    const float* lo_b1  = (const float*)d_in[22];
    const float* lo_g1  = (const float*)d_in[23];
    const float* lo_be1 = (const float*)d_in[24];
    const float* lo_w2  = (const float*)d_in[25];
    const float* lo_b2  = (const float*)d_in[26];
    const float* lo_g2  = (const float*)d_in[27];
    const float* lo_be2 = (const float*)d_in[28];
    float* out = (float*)d_out;

    float* buf = nullptr;
    cudaGetSymbolAddress((void**)&buf, g_buf);

    uint4* featPk[4] = { (uint4*)(buf + OFF_FEAT0), (uint4*)(buf + OFF_FEAT1),
                         (uint4*)(buf + OFF_FEAT2), (uint4*)(buf + OFF_FEAT3) };
    const float* posl[4] = { pos0, buf + OFF_POS1, buf + OFF_POS2, buf + OFF_POS3 };
    int*   nbr = (int*)(buf + OFF_NBR);
    uint4* h1Pk  = (uint4*)(buf + OFF_H1);
    uint4* finPk = (uint4*)(buf + OFF_FIN);
    uint4* f1Pk  = (uint4*)(buf + OFF_F1);
    uint4* xfPk  = (uint4*)(buf + OFF_XF);
    unsigned* wtBase = (unsigned*)(buf + OFF_WT);

    uint4* wtLin  = (uint4*)(wtBase + WTO_LIN);
    uint4* wtLo1  = (uint4*)(wtBase + WTO_LOW1);

    const int nlev[4] = {4096, 2048, 1024, 512};

    // ---- weight preprocessing ----
    wconv<<<(128 * 1 * 4 + 255) / 256, 256>>>(lin_w, 16, 128, 16, wtLin);
    for (int l = 0; l < 3; l++) {
        wconv<<<(131 * 9 * 4 + 255) / 256, 256>>>(sa_w1 + (size_t)l * 131 * 131, 131, 131, 144,
                                                  (uint4*)(wtBase + WTO_SAW1 + l * 18864));
        wconv<<<(128 * 9 * 4 + 255) / 256, 256>>>(sa_w2 + (size_t)l * 131 * 128, 131, 128, 144,
                                                  (uint4*)(wtBase + WTO_SAW2 + l * 18432));
        wconv<<<(256 * 16 * 4 + 255) / 256, 256>>>(fp_w1 + (size_t)l * 256 * 256, 256, 256, 256,
                                                   (uint4*)(wtBase + WTO_FPW1 + l * 65536));
        wconv<<<(128 * 16 * 4 + 255) / 256, 256>>>(fp_w2 + (size_t)l * 256 * 128, 256, 128, 256,
                                                   (uint4*)(wtBase + WTO_FPW2 + l * 32768));
    }
    wconv<<<(128 * 8 * 4 + 255) / 256, 256>>>(lo_w1, 128, 128, 128, wtLo1);

    // ---- lin_in + ReLU ----
    {
        dim3 grid(2, (NBATCH * 4096) / 128);
        gemm_tc<0, 0><<<grid, 256>>>(x, 16, nullptr, wtLin, lin_b, nullptr, nullptr,
                                     (unsigned*)featPk[0], 128, NBATCH * 4096, 128, 16,
                                     nullptr, nullptr, nullptr, nullptr, 0, 0);
    }

    // ---- SA levels ----
    for (int l = 0; l < 3; l++) {
        int n = nlev[l], m = nlev[l + 1];
        if (l == 0)      fps_kernel<16><<<NBATCH, 256>>>(posl[0], n, m, (float*)posl[1]);
        else if (l == 1) fps_kernel<8><<<NBATCH, 256>>>(posl[1], n, m, (float*)posl[2]);
        else             fps_kernel<4><<<NBATCH, 256>>>(posl[2], n, m, (float*)posl[3]);

        knn_ball<<<NBATCH * m, 128>>>(posl[l], posl[l + 1], n, m, nbr);

        int rows = NBATCH * m * KNB;
        {
            dim3 grid(3, rows / 128);
            gemm_tc<1, 2><<<grid, 256>>>(nullptr, 0, nullptr,
                                         (uint4*)(wtBase + WTO_SAW1 + l * 18864),
                                         sa_b1 + l * 131, sa_g1 + l * 131, sa_be1 + l * 131,
                                         (unsigned*)h1Pk, 144, rows, 131, 144,
                                         featPk[l], posl[l], posl[l + 1], nbr, n, m);
        }
        {
            dim3 grid(2, rows / 128);
            gemm_tc<2, 1><<<grid, 256>>>(nullptr, 0, h1Pk,
                                         (uint4*)(wtBase + WTO_SAW2 + l * 18432),
                                         sa_b2 + l * 128, sa_g2 + l * 128, sa_be2 + l * 128,
                                         (unsigned*)featPk[l + 1], 128, rows, 128, 144,
                                         nullptr, nullptr, nullptr, nbr, n, m);
        }
    }

    // ---- FP levels ----
    const uint4* cfeat = featPk[3];
    for (int step = 0; step < 3; step++) {
        int mi = 2 - step;
        int nc = nlev[mi + 1], nf = nlev[mi];
        fp_interp<<<NBATCH * (nf / 256), 256>>>(cfeat, posl[mi + 1], posl[mi],
                                                featPk[mi], nc, nf, finPk);
        int rows = NBATCH * nf;
        {
            dim3 grid(4, rows / 128);
            gemm_tc<1, 1><<<grid, 256>>>(nullptr, 0, finPk,
                                         (uint4*)(wtBase + WTO_FPW1 + mi * 65536),
                                         fp_b1 + mi * 256, fp_g1 + mi * 256, fp_be1 + mi * 256,
                                         (unsigned*)f1Pk, 256, rows, 256, 256,
                                         nullptr, nullptr, nullptr, nullptr, 0, 0);
        }
        {
            dim3 grid(2, rows / 128);
            gemm_tc<1, 1><<<grid, 256>>>(nullptr, 0, f1Pk,
                                         (uint4*)(wtBase + WTO_FPW2 + mi * 32768),
                                         fp_b2 + mi * 128, fp_g2 + mi * 128, fp_be2 + mi * 128,
                                         (unsigned*)xfPk, 128, rows, 128, 256,
                                         nullptr, nullptr, nullptr, nullptr, 0, 0);
        }
        cfeat = xfPk;
    }

    // ---- final MLP ----
    {
        dim3 grid(2, (NBATCH * 4096) / 128);
        gemm_tc<1, 1><<<grid, 256>>>(nullptr, 0, xfPk, wtLo1,
                                     lo_b1, lo_g1, lo_be1,
                                     (unsigned*)f1Pk, 128, NBATCH * 4096, 128, 128,
                                     nullptr, nullptr, nullptr, nullptr, 0, 0);
    }
    final_out<<<(NBATCH * 4096) / 32, 256>>>(f1Pk, lo_w2, lo_b2, lo_g2, lo_be2,
                                             out, NBATCH * 4096);
}

// round 9
// speedup vs baseline: 1.8890x; 1.1497x over previous
#include <cuda_runtime.h>
#include <cuda_bf16.h>
#include <cstddef>

#define NBATCH 4
#define KNB 64
#define FULLM 0xffffffffu

// ---------------- scratch layout (floats) ----------------
#define OFF_FEAT0 0ull
#define OFF_FEAT1 2097152ull
#define OFF_FEAT2 3145728ull
#define OFF_FEAT3 3670016ull
#define OFF_POS1  3932160ull
#define OFF_POS2  3956736ull
#define OFF_POS3  3969024ull
#define OFF_NBR   3975168ull
#define OFF_FIN   4499456ull
#define OFF_F1    8693760ull
#define OFF_XF    12888064ull
#define OFF_WT    14985216ull
#define OFF_H1    15509504ull
#define TOTAL_FLOATS 91006976ull

__device__ __align__(256) float g_buf[TOTAL_FLOATS];

// ---- WT sub-offsets (uint32 elements inside WT region) ----
#define WTO_LIN   0
#define WTO_SAW1  2048
#define WTO_SAW2  58640
#define WTO_FPW1  113936
#define WTO_FPW2  310544
#define WTO_LOW1  408848

// ---------------- bf16 helpers ----------------
__device__ __forceinline__ float bf2f(unsigned s16) {
    return __uint_as_float(s16 << 16);
}
__device__ __forceinline__ void split2(float a, float b, unsigned& hw, unsigned& lw) {
    __nv_bfloat16 ah = __float2bfloat16(a), bh = __float2bfloat16(b);
    float ar = a - __bfloat162float(ah);
    float br = b - __bfloat162float(bh);
    hw = (unsigned)__bfloat16_as_ushort(ah) | ((unsigned)__bfloat16_as_ushort(bh) << 16);
    lw = (unsigned)__bfloat16_as_ushort(__float2bfloat16(ar))
       | ((unsigned)__bfloat16_as_ushort(__float2bfloat16(br)) << 16);
}
__device__ __forceinline__ void store_pair(unsigned* C, int KpOut, int row, int g0,
                                           float v0, float v1) {
    unsigned hw, lw;
    split2(v0, v1, hw, lw);
    size_t off = ((size_t)row * (KpOut >> 2) + ((g0 >> 4) << 2) + ((g0 & 7) >> 1)) * 4
               + ((g0 >> 3) & 1);
    C[off]     = hw;
    C[off + 2] = lw;
}

__device__ __forceinline__ void mma16(float* c, const unsigned* a, unsigned b0, unsigned b1) {
    asm volatile(
        "mma.sync.aligned.m16n8k16.row.col.f32.bf16.bf16.f32 "
        "{%0,%1,%2,%3}, {%4,%5,%6,%7}, {%8,%9}, {%0,%1,%2,%3};"
        : "+f"(c[0]), "+f"(c[1]), "+f"(c[2]), "+f"(c[3])
        : "r"(a[0]), "r"(a[1]), "r"(a[2]), "r"(a[3]), "r"(b0), "r"(b1));
}

__device__ __forceinline__ int swz(int row, int t) {
    return t ^ ((row ^ (row >> 2)) & 3);
}

// ---------------- fused weight preprocess (ALL matrices, one launch) ----------------
struct WDesc { const float* src; unsigned dstOff; int K; int N; int Kp; int start; };
struct WTable { WDesc d[14]; int total; };

__global__ void wconv_all(WTable tb, unsigned* __restrict__ wtBase)
{
    int idx = blockIdx.x * blockDim.x + threadIdx.x;
    if (idx >= tb.total) return;
    int di = 0;
#pragma unroll
    for (int i = 1; i < 14; i++) if (idx >= tb.d[i].start) di = i;
    const WDesc D = tb.d[di];
    int e = idx - D.start;
    int t = e & 3;
    int c = (e >> 2) % (D.Kp >> 4);
    int n = e / ((D.Kp >> 4) * 4);
    int k0 = 16 * c + 2 * t;
    const float* W = D.src;
    float v0 = (k0     < D.K) ? W[(size_t)(k0    ) * D.N + n] : 0.f;
    float v1 = (k0 + 1 < D.K) ? W[(size_t)(k0 + 1) * D.N + n] : 0.f;
    float v2 = (k0 + 8 < D.K) ? W[(size_t)(k0 + 8) * D.N + n] : 0.f;
    float v3 = (k0 + 9 < D.K) ? W[(size_t)(k0 + 9) * D.N + n] : 0.f;
    uint4 u;
    split2(v0, v1, u.x, u.z);
    split2(v2, v3, u.y, u.w);
    ((uint4*)(wtBase + D.dstOff))[e] = u;
}

// ---------------- tensor-core GEMM (3xBF16), packed hi/lo I/O, double-buffered ----------------
// EPI: 0 = relu, 1 = relu+bn, 2 = relu+bn + masked max over 64-row groups.
// ASRC: 0 = fp32 A (lda), 1 = packed A, 2 = gather from packed feat + pos delta.
template<int EPI, int ASRC>
__global__ __launch_bounds__(256)
void gemm_tc(const float* __restrict__ Afp, int lda,
             const uint4* __restrict__ Apk,
             const uint4* __restrict__ Wt,
             const float* __restrict__ bias, const float* __restrict__ gam,
             const float* __restrict__ bet,
             unsigned* __restrict__ Cpk, int KpOut, int M, int N, int Kp,
             const uint4* __restrict__ featPk, const float* __restrict__ posL,
             const float* __restrict__ q, const int* __restrict__ nbr,
             int nPts, int mCen)
{
    __shared__ uint4 As4[2][512];
    __shared__ uint4 Ws4[2][256];
    __shared__ float sred[2][2][64];

    const int tid  = threadIdx.x;
    const int lane = tid & 31;
    const int warp = tid >> 5;
    const int mwarp = warp >> 1;
    const int nwarp = warp & 1;
    const int gid = lane >> 2;
    const int tig = lane & 3;
    const int bm = blockIdx.y * 128;
    const int bn = blockIdx.x * 64;

    float acc[2][4][4];
#pragma unroll
    for (int mt = 0; mt < 2; mt++)
#pragma unroll
        for (int nt = 0; nt < 4; nt++)
#pragma unroll
            for (int e = 0; e < 4; e++) acc[mt][nt][e] = 0.f;

    int gj = -1, gb = 0, gbc = 0;
    if (ASRC == 2 && tid < 128) {
        int gm = bm + tid;
        gj  = nbr[gm];
        gb  = gm / (mCen * 64);
        gbc = gm >> 6;
    }

    const int rowU4 = Kp >> 2;
    const int C = Kp >> 4;
    uint4 st[4];

    auto loadStage = [&](int c) {
        const int k0 = c << 4;
        if (tid < 128) {
            const int r = tid;
            if (ASRC == 1) {
                const uint4* p = Apk + (size_t)(bm + r) * rowU4 + c * 4;
                st[0] = p[0]; st[1] = p[1]; st[2] = p[2]; st[3] = p[3];
            } else if (ASRC == 2) {
                if (gj < 0) {
                    st[0] = st[1] = st[2] = st[3] = make_uint4(0, 0, 0, 0);
                } else if (k0 < 128) {
                    const uint4* p = featPk + ((size_t)gb * nPts + gj) * 32 + c * 4;
                    st[0] = p[0]; st[1] = p[1]; st[2] = p[2]; st[3] = p[3];
                } else {
                    const float* pp = posL + ((size_t)gb * nPts + gj) * 3;
                    const float* qq = q + (size_t)gbc * 3;
                    float d0 = pp[0] - qq[0], d1 = pp[1] - qq[1], d2 = pp[2] - qq[2];
                    unsigned h01, l01, h2z, l2z;
                    split2(d0, d1, h01, l01);
                    split2(d2, 0.f, h2z, l2z);
                    st[0] = make_uint4(h01, 0, l01, 0);
                    st[1] = make_uint4(h2z, 0, l2z, 0);
                    st[2] = make_uint4(0, 0, 0, 0);
                    st[3] = make_uint4(0, 0, 0, 0);
                }
            } else {
                float av[16];
                const float4* fp = (const float4*)(Afp + (size_t)(bm + r) * lda + k0);
#pragma unroll
                for (int i = 0; i < 4; i++) {
                    float4 v = fp[i];
                    av[i * 4]     = v.x; av[i * 4 + 1] = v.y;
                    av[i * 4 + 2] = v.z; av[i * 4 + 3] = v.w;
                }
#pragma unroll
                for (int t = 0; t < 4; t++) {
                    split2(av[2 * t],     av[2 * t + 1], st[t].x, st[t].z);
                    split2(av[2 * t + 8], av[2 * t + 9], st[t].y, st[t].w);
                }
            }
        } else if (tid < 192) {
            const int gn = bn + tid - 128;
            if (gn < N) {
                const uint4* p = Wt + (size_t)gn * rowU4 + c * 4;
                st[0] = p[0]; st[1] = p[1]; st[2] = p[2]; st[3] = p[3];
            } else {
                st[0] = st[1] = st[2] = st[3] = make_uint4(0, 0, 0, 0);
            }
        }
    };
    auto storeStage = [&](int b) {
        if (tid < 128) {
            const int r = tid;
#pragma unroll
            for (int t = 0; t < 4; t++) As4[b][r * 4 + swz(r, t)] = st[t];
        } else if (tid < 192) {
            const int n = tid - 128;
#pragma unroll
            for (int t = 0; t < 4; t++) Ws4[b][n * 4 + swz(n, t)] = st[t];
        }
    };

    loadStage(0);
    storeStage(0);
    __syncthreads();

    for (int c = 0; c < C; c++) {
        const int cb = c & 1;
        if (c + 1 < C) loadStage(c + 1);

        unsigned ah[2][4], al[2][4];
#pragma unroll
        for (int mt = 0; mt < 2; mt++) {
            int mr  = mwarp * 32 + mt * 16 + gid;
            int mr8 = mr + 8;
            uint4 ua = As4[cb][mr * 4 + swz(mr, tig)];
            uint4 ub = As4[cb][mr8 * 4 + swz(mr8, tig)];
            ah[mt][0] = ua.x; ah[mt][1] = ub.x; ah[mt][2] = ua.y; ah[mt][3] = ub.y;
            al[mt][0] = ua.z; al[mt][1] = ub.z; al[mt][2] = ua.w; al[mt][3] = ub.w;
        }
#pragma unroll
        for (int nt = 0; nt < 4; nt++) {
            int nc = nwarp * 32 + nt * 8 + gid;
            uint4 uw = Ws4[cb][nc * 4 + swz(nc, tig)];
#pragma unroll
            for (int mt = 0; mt < 2; mt++) {
                mma16(acc[mt][nt], ah[mt], uw.x, uw.y);
                mma16(acc[mt][nt], ah[mt], uw.z, uw.w);
                mma16(acc[mt][nt], al[mt], uw.x, uw.y);
            }
        }

        if (c + 1 < C) storeStage(cb ^ 1);
        __syncthreads();
    }

    const float inv = rsqrtf(1.f + 1e-5f);

    if (EPI < 2) {
#pragma unroll
        for (int mt = 0; mt < 2; mt++) {
#pragma unroll
            for (int nt = 0; nt < 4; nt++) {
                int g0 = bn + nwarp * 32 + nt * 8 + 2 * tig;
                if (g0 + 1 >= KpOut && g0 >= N) continue;
#pragma unroll
                for (int rr = 0; rr < 2; rr++) {
                    int row = bm + mwarp * 32 + mt * 16 + gid + rr * 8;
                    float v0 = acc[mt][nt][rr * 2];
                    float v1 = acc[mt][nt][rr * 2 + 1];
                    if (g0 < N) {
                        v0 = fmaxf(v0 + bias[g0], 0.f);
                        if (EPI == 1) v0 = gam[g0] * v0 * inv + bet[g0];
                    } else v0 = 0.f;
                    if (g0 + 1 < N) {
                        v1 = fmaxf(v1 + bias[g0 + 1], 0.f);
                        if (EPI == 1) v1 = gam[g0 + 1] * v1 * inv + bet[g0 + 1];
                    } else v1 = 0.f;
                    if (g0 + 1 < KpOut + 1 && g0 < KpOut)
                        store_pair(Cpk, KpOut, row, g0, v0, v1);
                }
            }
        }
    } else {
        bool val[2][2];
#pragma unroll
        for (int mt = 0; mt < 2; mt++) {
            int r = bm + mwarp * 32 + mt * 16 + gid;
            val[mt][0] = nbr[r] >= 0;
            val[mt][1] = nbr[r + 8] >= 0;
        }
        float cmax[4][2];
#pragma unroll
        for (int nt = 0; nt < 4; nt++) { cmax[nt][0] = -1e30f; cmax[nt][1] = -1e30f; }
#pragma unroll
        for (int mt = 0; mt < 2; mt++) {
#pragma unroll
            for (int nt = 0; nt < 4; nt++) {
                int gn0 = bn + nwarp * 32 + nt * 8 + 2 * tig;
#pragma unroll
                for (int e = 0; e < 4; e++) {
                    int gn = gn0 + (e & 1);
                    float v = acc[mt][nt][e] + bias[gn];
                    v = fmaxf(v, 0.f);
                    v = gam[gn] * v * inv + bet[gn];
                    if (val[mt][e >> 1]) {
                        float& m = cmax[nt][e & 1];
                        m = fmaxf(m, v);
                    }
                }
            }
        }
#pragma unroll
        for (int off = 4; off <= 16; off <<= 1) {
#pragma unroll
            for (int nt = 0; nt < 4; nt++) {
                cmax[nt][0] = fmaxf(cmax[nt][0], __shfl_xor_sync(FULLM, cmax[nt][0], off));
                cmax[nt][1] = fmaxf(cmax[nt][1], __shfl_xor_sync(FULLM, cmax[nt][1], off));
            }
        }
        if (gid == 0) {
#pragma unroll
            for (int nt = 0; nt < 4; nt++) {
                sred[mwarp >> 1][mwarp & 1][nwarp * 32 + nt * 8 + 2 * tig]     = cmax[nt][0];
                sred[mwarp >> 1][mwarp & 1][nwarp * 32 + nt * 8 + 2 * tig + 1] = cmax[nt][1];
            }
        }
        __syncthreads();
        if (tid < 64) {
            int center = tid >> 5;
            int pr = tid & 31;
            int g0 = bn + pr * 2;
            float v0 = fmaxf(sred[center][0][pr * 2],     sred[center][1][pr * 2]);
            float v1 = fmaxf(sred[center][0][pr * 2 + 1], sred[center][1][pr * 2 + 1]);
            int row = blockIdx.y * 2 + center;
            store_pair(Cpk, KpOut, row, g0, v0, v1);
        }
    }
}

// ---------------- final tiny layer: packed A[M,128] -> out[M,2] fp32 ----------------
__global__ __launch_bounds__(256)
void final_out(const uint4* __restrict__ Apk, const float* __restrict__ W,
               const float* __restrict__ bias, const float* __restrict__ gam,
               const float* __restrict__ bet, float* __restrict__ out, int M)
{
    __shared__ float sw[256];
    const int tid = threadIdx.x;
    sw[tid] = W[tid];
    __syncthreads();
    const int row = blockIdx.x * 32 + (tid >> 3);
    const int sub = tid & 7;
    if (row >= M) return;
    const uint4* a4 = Apk + (size_t)row * 32 + sub * 4;
    float acc0 = 0.f, acc1 = 0.f;
#pragma unroll
    for (int i = 0; i < 4; i++) {
        uint4 u = a4[i];
        int g = sub * 4 + i;
        int e0 = 16 * (g >> 2) + 2 * (g & 3);
        float va = bf2f(u.x & 0xffff) + bf2f(u.z & 0xffff);
        float vb = bf2f(u.x >> 16)    + bf2f(u.z >> 16);
        float vc = bf2f(u.y & 0xffff) + bf2f(u.w & 0xffff);
        float vd = bf2f(u.y >> 16)    + bf2f(u.w >> 16);
        acc0 += va * sw[e0 * 2]        + vb * sw[(e0 + 1) * 2]
              + vc * sw[(e0 + 8) * 2]  + vd * sw[(e0 + 9) * 2];
        acc1 += va * sw[e0 * 2 + 1]       + vb * sw[(e0 + 1) * 2 + 1]
              + vc * sw[(e0 + 8) * 2 + 1] + vd * sw[(e0 + 9) * 2 + 1];
    }
#pragma unroll
    for (int off = 4; off; off >>= 1) {
        acc0 += __shfl_down_sync(FULLM, acc0, off);
        acc1 += __shfl_down_sync(FULLM, acc1, off);
    }
    if (sub == 0) {
        const float inv = rsqrtf(1.f + 1e-5f);
        float v0 = fmaxf(acc0 + bias[0], 0.f);
        float v1 = fmaxf(acc1 + bias[1], 0.f);
        v0 = gam[0] * v0 * inv + bet[0];
        v1 = gam[1] * v1 * inv + bet[1];
        out[(size_t)row * 2]     = v0;
        out[(size_t)row * 2 + 1] = v1;
    }
}

// ---------------- farthest point sampling (redux, 1 barrier/step) ----------------
template<int PER>
__global__ __launch_bounds__(256)
void fps_kernel(const float* __restrict__ pos, int n, int m, float* __restrict__ qout)
{
    const int b = blockIdx.x, tid = threadIdx.x;
    const int lane = tid & 31, warp = tid >> 5;
    const float* P = pos + (size_t)b * n * 3;
    float* Q = qout + (size_t)b * m * 3;
    float px[PER], py[PER], pz[PER], dmin[PER];
#pragma unroll
    for (int u = 0; u < PER; u++) {
        int i = tid + 256 * u;
        px[u] = P[i * 3]; py[u] = P[i * 3 + 1]; pz[u] = P[i * 3 + 2];
        dmin[u] = 1e30f;
    }
    __shared__ unsigned s_v[2][8];
    __shared__ int      s_i[2][8];

    float qx = P[0], qy = P[1], qz = P[2];
    if (tid == 0) { Q[0] = qx; Q[1] = qy; Q[2] = qz; }

    for (int s = 1; s < m; s++) {
        float bv = -1e31f; int bi = 0;
#pragma unroll
        for (int u = 0; u < PER; u++) {
            float dx = px[u] - qx, dy = py[u] - qy, dz = pz[u] - qz;
            float d = dx * dx + dy * dy + dz * dz;
            d = fminf(dmin[u], d);
            dmin[u] = d;
            if (d > bv) { bv = d; bi = tid + 256 * u; }   // ascending u: lowest idx on ties
        }
        // warp argmax via redux (d >= 0 so float bits are order-preserving)
        unsigned vb = __float_as_uint(bv);
        unsigned vmax = __reduce_max_sync(FULLM, vb);
        int cand = (vb == vmax) ? bi : 0x7fffffff;
        int imin = __reduce_min_sync(FULLM, cand);
        const int par = s & 1;
        if (lane == 0) { s_v[par][warp] = vmax; s_i[par][warp] = imin; }
        __syncthreads();
        // redundant final reduce in every warp (no second barrier; parity protects reuse)
        unsigned v8 = (lane < 8) ? s_v[par][lane] : 0u;
        unsigned vm8 = __reduce_max_sync(FULLM, v8);
        int c8 = (lane < 8 && v8 == vm8) ? s_i[par][lane] : 0x7fffffff;
        int fi = __reduce_min_sync(FULLM, c8);
        qx = P[fi * 3]; qy = P[fi * 3 + 1]; qz = P[fi * 3 + 2];
        if (tid == 0) { Q[s * 3] = qx; Q[s * 3 + 1] = qy; Q[s * 3 + 2] = qz; }
    }
}

// ---------------- ball-query top-K (redux, 1 barrier/round) ----------------
__global__ __launch_bounds__(128)
void knn_ball(const float* __restrict__ pos, const float* __restrict__ q,
              int n, int m, int* __restrict__ nbr)
{
    __shared__ float sd[4096];
    __shared__ unsigned s_v[2][4];
    __shared__ int      s_i[2][4];
    const int bc = blockIdx.x;
    const int tid = threadIdx.x;
    const int lane = tid & 31, warp = tid >> 5;
    const float* P = pos + (size_t)(bc / m) * n * 3;
    const float qx = q[(size_t)bc * 3], qy = q[(size_t)bc * 3 + 1], qz = q[(size_t)bc * 3 + 2];
    for (int i = tid; i < n; i += 128) {
        float dx = P[i * 3] - qx, dy = P[i * 3 + 1] - qy, dz = P[i * 3 + 2] - qz;
        sd[i] = dx * dx + dy * dy + dz * dz;
    }
    __syncthreads();
    int* out = nbr + (size_t)bc * KNB;
    int r = 0;
    for (; r < KNB; r++) {
        float bv = 1e38f; int bi = 0x7fffffff;
        for (int i = tid; i < n; i += 128) {
            float v = sd[i];
            if (v < bv) { bv = v; bi = i; }
        }
        unsigned vb = __float_as_uint(bv);
        unsigned vmin = __reduce_min_sync(FULLM, vb);
        int cand = (vb == vmin) ? bi : 0x7fffffff;
        int imin = __reduce_min_sync(FULLM, cand);
        const int par = r & 1;
        if (lane == 0) { s_v[par][warp] = vmin; s_i[par][warp] = imin; }
        __syncthreads();
        unsigned v4 = (lane < 4) ? s_v[par][lane] : 0xffffffffu;
        unsigned vm4 = __reduce_min_sync(FULLM, v4);
        int c4 = (lane < 4 && v4 == vm4) ? s_i[par][lane] : 0x7fffffff;
        int fi = __reduce_min_sync(FULLM, c4);
        if (__uint_as_float(vm4) > 4.0f) break;
        if (tid == 0) out[r] = fi;
        if ((fi & 127) == tid) sd[fi] = 1e38f;   // only owner ever reads sd[fi]
    }
    for (int rr = r + tid; rr < KNB; rr += 128) out[rr] = -1;
}

// ---------------- FP 3-NN interpolation + skip concat (packed IO) ----------------
__global__ __launch_bounds__(256)
void fp_interp(const uint4* __restrict__ cf, const float* __restrict__ cp,
               const float* __restrict__ fpos, const uint4* __restrict__ sf,
               int nc, int nf, uint4* __restrict__ fin)
{
    __shared__ float sp[2048 * 3];
    const int bpb = nf >> 8;
    const int b = blockIdx.x / bpb;
    const int i = (blockIdx.x % bpb) * 256 + threadIdx.x;
    for (int t = threadIdx.x; t < nc * 3; t += 256) sp[t] = cp[(size_t)b * nc * 3 + t];
    __syncthreads();
    const float px = fpos[((size_t)b * nf + i) * 3];
    const float py = fpos[((size_t)b * nf + i) * 3 + 1];
    const float pz = fpos[((size_t)b * nf + i) * 3 + 2];
    float bd0 = 1e38f, bd1 = 1e38f, bd2 = 1e38f;
    int bi0 = 0, bi1 = 0, bi2 = 0;
    for (int j = 0; j < nc; j++) {
        float dx = px - sp[j * 3], dy = py - sp[j * 3 + 1], dz = pz - sp[j * 3 + 2];
        float d = dx * dx + dy * dy + dz * dz;
        if (d < bd0)      { bd2 = bd1; bi2 = bi1; bd1 = bd0; bi1 = bi0; bd0 = d; bi0 = j; }
        else if (d < bd1) { bd2 = bd1; bi2 = bi1; bd1 = d; bi1 = j; }
        else if (d < bd2) { bd2 = d; bi2 = j; }
    }
    const float w0 = 1.f / fmaxf(bd0, 1e-16f);
    const float w1 = 1.f / fmaxf(bd1, 1e-16f);
    const float w2 = 1.f / fmaxf(bd2, 1e-16f);
    const float rws = 1.f / (w0 + w1 + w2);
    const uint4* f0 = cf + ((size_t)b * nc + bi0) * 32;
    const uint4* f1 = cf + ((size_t)b * nc + bi1) * 32;
    const uint4* f2 = cf + ((size_t)b * nc + bi2) * 32;
    const uint4* s4 = sf + ((size_t)b * nf + i) * 32;
    uint4* o4 = fin + ((size_t)b * nf + i) * 64;
#pragma unroll 8
    for (int u = 0; u < 32; u++) {
        uint4 a = f0[u], bb = f1[u], cc = f2[u];
        float ra = (w0 * (bf2f(a.x & 0xffff) + bf2f(a.z & 0xffff))
                  + w1 * (bf2f(bb.x & 0xffff) + bf2f(bb.z & 0xffff))
                  + w2 * (bf2f(cc.x & 0xffff) + bf2f(cc.z & 0xffff))) * rws;
        float rb = (w0 * (bf2f(a.x >> 16) + bf2f(a.z >> 16))
                  + w1 * (bf2f(bb.x >> 16) + bf2f(bb.z >> 16))
                  + w2 * (bf2f(cc.x >> 16) + bf2f(cc.z >> 16))) * rws;
        float rc = (w0 * (bf2f(a.y & 0xffff) + bf2f(a.w & 0xffff))
                  + w1 * (bf2f(bb.y & 0xffff) + bf2f(bb.w & 0xffff))
                  + w2 * (bf2f(cc.y & 0xffff) + bf2f(cc.w & 0xffff))) * rws;
        float rd = (w0 * (bf2f(a.y >> 16) + bf2f(a.w >> 16))
                  + w1 * (bf2f(bb.y >> 16) + bf2f(bb.w >> 16))
                  + w2 * (bf2f(cc.y >> 16) + bf2f(cc.w >> 16))) * rws;
        uint4 r;
        split2(ra, rb, r.x, r.z);
        split2(rc, rd, r.y, r.w);
        o4[u] = r;
        o4[32 + u] = s4[u];
    }
}

// ---------------- host ----------------
extern "C" void kernel_launch(void* const* d_in, const int* in_sizes, int n_in,
                              void* d_out, int out_size)
{
    const float* x      = (const float*)d_in[0];
    const float* pos0   = (const float*)d_in[1];
    const float* lin_w  = (const float*)d_in[3];
    const float* lin_b  = (const float*)d_in[4];
    const float* sa_w1  = (const float*)d_in[5];
    const float* sa_b1  = (const float*)d_in[6];
    const float* sa_g1  = (const float*)d_in[7];
    const float* sa_be1 = (const float*)d_in[8];
    const float* sa_w2  = (const float*)d_in[9];
    const float* sa_b2  = (const float*)d_in[10];
    const float* sa_g2  = (const float*)d_in[11];
    const float* sa_be2 = (const float*)d_in[12];
    const float* fp_w1  = (const float*)d_in[13];
    const float* fp_b1  = (const float*)d_in[14];
    const float* fp_g1  = (const float*)d_in[15];
    const float* fp_be1 = (const float*)d_in[16];
    const float* fp_w2  = (const float*)d_in[17];
    const float* fp_b2  = (const float*)d_in[18];
    const float* fp_g2  = (const float*)d_in[19];
    const float* fp_be2 = (const float*)d_in[20];
    const float* lo_w1  = (const float*)d_in[21];
    const float* lo_b1  = (const float*)d_in[22];
    const float* lo_g1  = (const float*)d_in[23];
    const float* lo_be1 = (const float*)d_in[24];
    const float* lo_w2  = (const float*)d_in[25];
    const float* lo_b2  = (const float*)d_in[26];
    const float* lo_g2  = (const float*)d_in[27];
    const float* lo_be2 = (const float*)d_in[28];
    float* out = (float*)d_out;

    float* buf = nullptr;
    cudaGetSymbolAddress((void**)&buf, g_buf);

    uint4* featPk[4] = { (uint4*)(buf + OFF_FEAT0), (uint4*)(buf + OFF_FEAT1),
                         (uint4*)(buf + OFF_FEAT2), (uint4*)(buf + OFF_FEAT3) };
    const float* posl[4] = { pos0, buf + OFF_POS1, buf + OFF_POS2, buf + OFF_POS3 };
    int*   nbr = (int*)(buf + OFF_NBR);
    uint4* h1Pk  = (uint4*)(buf + OFF_H1);
    uint4* finPk = (uint4*)(buf + OFF_FIN);
    uint4* f1Pk  = (uint4*)(buf + OFF_F1);
    uint4* xfPk  = (uint4*)(buf + OFF_XF);
    unsigned* wtBase = (unsigned*)(buf + OFF_WT);

    const int nlev[4] = {4096, 2048, 1024, 512};

    // ---- fused weight preprocessing (one launch) ----
    {
        WTable tb;
        int cur = 0, e = 0;
        auto add = [&](const float* src, unsigned off, int K, int N, int Kp) {
            tb.d[e].src = src; tb.d[e].dstOff = off;
            tb.d[e].K = K; tb.d[e].N = N; tb.d[e].Kp = Kp; tb.d[e].start = cur;
            cur += N * (Kp >> 4) * 4;
            e++;
        };
        add(lin_w, WTO_LIN, 16, 128, 16);
        for (int l = 0; l < 3; l++) {
            add(sa_w1 + (size_t)l * 131 * 131, WTO_SAW1 + l * 18864, 131, 131, 144);
            add(sa_w2 + (size_t)l * 131 * 128, WTO_SAW2 + l * 18432, 131, 128, 144);
            add(fp_w1 + (size_t)l * 256 * 256, WTO_FPW1 + l * 65536, 256, 256, 256);
            add(fp_w2 + (size_t)l * 256 * 128, WTO_FPW2 + l * 32768, 256, 128, 256);
        }
        add(lo_w1, WTO_LOW1, 128, 128, 128);
        tb.total = cur;
        wconv_all<<<(cur + 255) / 256, 256>>>(tb, wtBase);
    }

    // ---- lin_in + ReLU ----
    {
        dim3 grid(2, (NBATCH * 4096) / 128);
        gemm_tc<0, 0><<<grid, 256>>>(x, 16, nullptr, (uint4*)(wtBase + WTO_LIN),
                                     lin_b, nullptr, nullptr,
                                     (unsigned*)featPk[0], 128, NBATCH * 4096, 128, 16,
                                     nullptr, nullptr, nullptr, nullptr, 0, 0);
    }

    // ---- SA levels ----
    for (int l = 0; l < 3; l++) {
        int n = nlev[l], m = nlev[l + 1];
        if (l == 0)      fps_kernel<16><<<NBATCH, 256>>>(posl[0], n, m, (float*)posl[1]);
        else if (l == 1) fps_kernel<8><<<NBATCH, 256>>>(posl[1], n, m, (float*)posl[2]);
        else             fps_kernel<4><<<NBATCH, 256>>>(posl[2], n, m, (float*)posl[3]);

        knn_ball<<<NBATCH * m, 128>>>(posl[l], posl[l + 1], n, m, nbr);

        int rows = NBATCH * m * KNB;
        {
            dim3 grid(3, rows / 128);
            gemm_tc<1, 2><<<grid, 256>>>(nullptr, 0, nullptr,
                                         (uint4*)(wtBase + WTO_SAW1 + l * 18864),
                                         sa_b1 + l * 131, sa_g1 + l * 131, sa_be1 + l * 131,
                                         (unsigned*)h1Pk, 144, rows, 131, 144,
                                         featPk[l], posl[l], posl[l + 1], nbr, n, m);
        }
        {
            dim3 grid(2, rows / 128);
            gemm_tc<2, 1><<<grid, 256>>>(nullptr, 0, h1Pk,
                                         (uint4*)(wtBase + WTO_SAW2 + l * 18432),
                                         sa_b2 + l * 128, sa_g2 + l * 128, sa_be2 + l * 128,
                                         (unsigned*)featPk[l + 1], 128, rows, 128, 144,
                                         nullptr, nullptr, nullptr, nbr, n, m);
        }
    }

    // ---- FP levels ----
    const uint4* cfeat = featPk[3];
    for (int step = 0; step < 3; step++) {
        int mi = 2 - step;
        int nc = nlev[mi + 1], nf = nlev[mi];
        fp_interp<<<NBATCH * (nf / 256), 256>>>(cfeat, posl[mi + 1], posl[mi],
                                                featPk[mi], nc, nf, finPk);
        int rows = NBATCH * nf;
        {
            dim3 grid(4, rows / 128);
            gemm_tc<1, 1><<<grid, 256>>>(nullptr, 0, finPk,
                                         (uint4*)(wtBase + WTO_FPW1 + mi * 65536),
                                         fp_b1 + mi * 256, fp_g1 + mi * 256, fp_be1 + mi * 256,
                                         (unsigned*)f1Pk, 256, rows, 256, 256,
                                         nullptr, nullptr, nullptr, nullptr, 0, 0);
        }
        {
            dim3 grid(2, rows / 128);
            gemm_tc<1, 1><<<grid, 256>>>(nullptr, 0, f1Pk,
                                         (uint4*)(wtBase + WTO_FPW2 + mi * 32768),
                                         fp_b2 + mi * 128, fp_g2 + mi * 128, fp_be2 + mi * 128,
                                         (unsigned*)xfPk, 128, rows, 128, 256,
                                         nullptr, nullptr, nullptr, nullptr, 0, 0);
        }
        cfeat = xfPk;
    }

    // ---- final MLP ----
    {
        dim3 grid(2, (NBATCH * 4096) / 128);
        gemm_tc<1, 1><<<grid, 256>>>(nullptr, 0, xfPk, (uint4*)(wtBase + WTO_LOW1),
                                     lo_b1, lo_g1, lo_be1,
                                     (unsigned*)f1Pk, 128, NBATCH * 4096, 128, 128,
                                     nullptr, nullptr, nullptr, nullptr, 0, 0);
    }
    final_out<<<(NBATCH * 4096) / 32, 256>>>(f1Pk, lo_w2, lo_b2, lo_g2, lo_be2,
                                             out, NBATCH * 4096);
}

// round 11
// speedup vs baseline: 2.2332x; 1.1822x over previous
#include <cuda_runtime.h>
#include <cuda_bf16.h>
#include <cstddef>

#define NBATCH 4
#define KNB 64
#define KCAP 320
#define FULLM 0xffffffffu

// ---------------- scratch layout (floats) ----------------
#define OFF_FEAT0 0ull
#define OFF_FEAT1 2097152ull
#define OFF_FEAT2 3145728ull
#define OFF_FEAT3 3670016ull
#define OFF_POS1  3932160ull
#define OFF_POS2  3956736ull
#define OFF_POS3  3969024ull
#define OFF_NBR0  3975168ull
#define OFF_FIN   4499456ull
#define OFF_F1    8693760ull
#define OFF_XF    12888064ull
#define OFF_WT    14985216ull
#define OFF_H1    15509504ull
#define OFF_NBR1  91006976ull
#define OFF_NBR2  91269120ull
#define TOTAL_FLOATS 91400192ull

__device__ __align__(256) float g_buf[TOTAL_FLOATS];

// ---- WT sub-offsets (uint32 elements inside WT region) ----
#define WTO_LIN   0
#define WTO_SAW1  2048
#define WTO_SAW2  58640
#define WTO_FPW1  113936
#define WTO_FPW2  310544
#define WTO_LOW1  408848

// ---------------- bf16 helpers ----------------
__device__ __forceinline__ float bf2f(unsigned s16) {
    return __uint_as_float(s16 << 16);
}
__device__ __forceinline__ void split2(float a, float b, unsigned& hw, unsigned& lw) {
    __nv_bfloat16 ah = __float2bfloat16(a), bh = __float2bfloat16(b);
    float ar = a - __bfloat162float(ah);
    float br = b - __bfloat162float(bh);
    hw = (unsigned)__bfloat16_as_ushort(ah) | ((unsigned)__bfloat16_as_ushort(bh) << 16);
    lw = (unsigned)__bfloat16_as_ushort(__float2bfloat16(ar))
       | ((unsigned)__bfloat16_as_ushort(__float2bfloat16(br)) << 16);
}
__device__ __forceinline__ void store_pair(unsigned* C, int KpOut, int row, int g0,
                                           float v0, float v1) {
    unsigned hw, lw;
    split2(v0, v1, hw, lw);
    size_t off = ((size_t)row * (KpOut >> 2) + ((g0 >> 4) << 2) + ((g0 & 7) >> 1)) * 4
               + ((g0 >> 3) & 1);
    C[off]     = hw;
    C[off + 2] = lw;
}

__device__ __forceinline__ void mma16(float* c, const unsigned* a, unsigned b0, unsigned b1) {
    asm volatile(
        "mma.sync.aligned.m16n8k16.row.col.f32.bf16.bf16.f32 "
        "{%0,%1,%2,%3}, {%4,%5,%6,%7}, {%8,%9}, {%0,%1,%2,%3};"
        : "+f"(c[0]), "+f"(c[1]), "+f"(c[2]), "+f"(c[3])
        : "r"(a[0]), "r"(a[1]), "r"(a[2]), "r"(a[3]), "r"(b0), "r"(b1));
}

__device__ __forceinline__ int swz(int row, int t) {
    return t ^ ((row ^ (row >> 2)) & 3);
}

// ---------------- fused weight preprocess ----------------
struct WDesc { const float* src; unsigned dstOff; int K; int N; int Kp; int start; };
struct WTable { WDesc d[14]; int total; };

__global__ void wconv_all(WTable tb, unsigned* __restrict__ wtBase)
{
    int idx = blockIdx.x * blockDim.x + threadIdx.x;
    if (idx >= tb.total) return;
    int di = 0;
#pragma unroll
    for (int i = 1; i < 14; i++) if (idx >= tb.d[i].start) di = i;
    const WDesc D = tb.d[di];
    int e = idx - D.start;
    int t = e & 3;
    int c = (e >> 2) % (D.Kp >> 4);
    int n = e / ((D.Kp >> 4) * 4);
    int k0 = 16 * c + 2 * t;
    const float* W = D.src;
    float v0 = (k0     < D.K) ? W[(size_t)(k0    ) * D.N + n] : 0.f;
    float v1 = (k0 + 1 < D.K) ? W[(size_t)(k0 + 1) * D.N + n] : 0.f;
    float v2 = (k0 + 8 < D.K) ? W[(size_t)(k0 + 8) * D.N + n] : 0.f;
    float v3 = (k0 + 9 < D.K) ? W[(size_t)(k0 + 9) * D.N + n] : 0.f;
    uint4 u;
    split2(v0, v1, u.x, u.z);
    split2(v2, v3, u.y, u.w);
    ((uint4*)(wtBase + D.dstOff))[e] = u;
}

// ---------------- tensor-core GEMM (3xBF16), packed hi/lo I/O, double-buffered ----------------
template<int EPI, int ASRC>
__global__ __launch_bounds__(256)
void gemm_tc(const float* __restrict__ Afp, int lda,
             const uint4* __restrict__ Apk,
             const uint4* __restrict__ Wt,
             const float* __restrict__ bias, const float* __restrict__ gam,
             const float* __restrict__ bet,
             unsigned* __restrict__ Cpk, int KpOut, int M, int N, int Kp,
             const uint4* __restrict__ featPk, const float* __restrict__ posL,
             const float* __restrict__ q, const int* __restrict__ nbr,
             int nPts, int mCen)
{
    __shared__ uint4 As4[2][512];
    __shared__ uint4 Ws4[2][256];
    __shared__ float sred[2][2][64];

    const int tid  = threadIdx.x;
    const int lane = tid & 31;
    const int warp = tid >> 5;
    const int mwarp = warp >> 1;
    const int nwarp = warp & 1;
    const int gid = lane >> 2;
    const int tig = lane & 3;
    const int bm = blockIdx.y * 128;
    const int bn = blockIdx.x * 64;

    float acc[2][4][4];
#pragma unroll
    for (int mt = 0; mt < 2; mt++)
#pragma unroll
        for (int nt = 0; nt < 4; nt++)
#pragma unroll
            for (int e = 0; e < 4; e++) acc[mt][nt][e] = 0.f;

    int gj = -1, gb = 0, gbc = 0;
    if (ASRC == 2 && tid < 128) {
        int gm = bm + tid;
        gj  = nbr[gm];
        gb  = gm / (mCen * 64);
        gbc = gm >> 6;
    }

    const int rowU4 = Kp >> 2;
    const int C = Kp >> 4;
    uint4 st[4];

    auto loadStage = [&](int c) {
        const int k0 = c << 4;
        if (tid < 128) {
            const int r = tid;
            if (ASRC == 1) {
                const uint4* p = Apk + (size_t)(bm + r) * rowU4 + c * 4;
                st[0] = p[0]; st[1] = p[1]; st[2] = p[2]; st[3] = p[3];
            } else if (ASRC == 2) {
                if (gj < 0) {
                    st[0] = st[1] = st[2] = st[3] = make_uint4(0, 0, 0, 0);
                } else if (k0 < 128) {
                    const uint4* p = featPk + ((size_t)gb * nPts + gj) * 32 + c * 4;
                    st[0] = p[0]; st[1] = p[1]; st[2] = p[2]; st[3] = p[3];
                } else {
                    const float* pp = posL + ((size_t)gb * nPts + gj) * 3;
                    const float* qq = q + (size_t)gbc * 3;
                    float d0 = pp[0] - qq[0], d1 = pp[1] - qq[1], d2 = pp[2] - qq[2];
                    unsigned h01, l01, h2z, l2z;
                    split2(d0, d1, h01, l01);
                    split2(d2, 0.f, h2z, l2z);
                    st[0] = make_uint4(h01, 0, l01, 0);
                    st[1] = make_uint4(h2z, 0, l2z, 0);
                    st[2] = make_uint4(0, 0, 0, 0);
                    st[3] = make_uint4(0, 0, 0, 0);
                }
            } else {
                float av[16];
                const float4* fp = (const float4*)(Afp + (size_t)(bm + r) * lda + k0);
#pragma unroll
                for (int i = 0; i < 4; i++) {
                    float4 v = fp[i];
                    av[i * 4]     = v.x; av[i * 4 + 1] = v.y;
                    av[i * 4 + 2] = v.z; av[i * 4 + 3] = v.w;
                }
#pragma unroll
                for (int t = 0; t < 4; t++) {
                    split2(av[2 * t],     av[2 * t + 1], st[t].x, st[t].z);
                    split2(av[2 * t + 8], av[2 * t + 9], st[t].y, st[t].w);
                }
            }
        } else if (tid < 192) {
            const int gn = bn + tid - 128;
            if (gn < N) {
                const uint4* p = Wt + (size_t)gn * rowU4 + c * 4;
                st[0] = p[0]; st[1] = p[1]; st[2] = p[2]; st[3] = p[3];
            } else {
                st[0] = st[1] = st[2] = st[3] = make_uint4(0, 0, 0, 0);
            }
        }
    };
    auto storeStage = [&](int b) {
        if (tid < 128) {
            const int r = tid;
#pragma unroll
            for (int t = 0; t < 4; t++) As4[b][r * 4 + swz(r, t)] = st[t];
        } else if (tid < 192) {
            const int n = tid - 128;
#pragma unroll
            for (int t = 0; t < 4; t++) Ws4[b][n * 4 + swz(n, t)] = st[t];
        }
    };

    loadStage(0);
    storeStage(0);
    __syncthreads();

    for (int c = 0; c < C; c++) {
        const int cb = c & 1;
        if (c + 1 < C) loadStage(c + 1);

        unsigned ah[2][4], al[2][4];
#pragma unroll
        for (int mt = 0; mt < 2; mt++) {
            int mr  = mwarp * 32 + mt * 16 + gid;
            int mr8 = mr + 8;
            uint4 ua = As4[cb][mr * 4 + swz(mr, tig)];
            uint4 ub = As4[cb][mr8 * 4 + swz(mr8, tig)];
            ah[mt][0] = ua.x; ah[mt][1] = ub.x; ah[mt][2] = ua.y; ah[mt][3] = ub.y;
            al[mt][0] = ua.z; al[mt][1] = ub.z; al[mt][2] = ua.w; al[mt][3] = ub.w;
        }
#pragma unroll
        for (int nt = 0; nt < 4; nt++) {
            int nc = nwarp * 32 + nt * 8 + gid;
            uint4 uw = Ws4[cb][nc * 4 + swz(nc, tig)];
#pragma unroll
            for (int mt = 0; mt < 2; mt++) {
                mma16(acc[mt][nt], ah[mt], uw.x, uw.y);
                mma16(acc[mt][nt], ah[mt], uw.z, uw.w);
                mma16(acc[mt][nt], al[mt], uw.x, uw.y);
            }
        }

        if (c + 1 < C) storeStage(cb ^ 1);
        __syncthreads();
    }

    const float inv = rsqrtf(1.f + 1e-5f);

    if (EPI < 2) {
#pragma unroll
        for (int mt = 0; mt < 2; mt++) {
#pragma unroll
            for (int nt = 0; nt < 4; nt++) {
                int g0 = bn + nwarp * 32 + nt * 8 + 2 * tig;
                if (g0 + 1 >= KpOut && g0 >= N) continue;
#pragma unroll
                for (int rr = 0; rr < 2; rr++) {
                    int row = bm + mwarp * 32 + mt * 16 + gid + rr * 8;
                    float v0 = acc[mt][nt][rr * 2];
                    float v1 = acc[mt][nt][rr * 2 + 1];
                    if (g0 < N) {
                        v0 = fmaxf(v0 + bias[g0], 0.f);
                        if (EPI == 1) v0 = gam[g0] * v0 * inv + bet[g0];
                    } else v0 = 0.f;
                    if (g0 + 1 < N) {
                        v1 = fmaxf(v1 + bias[g0 + 1], 0.f);
                        if (EPI == 1) v1 = gam[g0 + 1] * v1 * inv + bet[g0 + 1];
                    } else v1 = 0.f;
                    if (g0 + 1 < KpOut + 1 && g0 < KpOut)
                        store_pair(Cpk, KpOut, row, g0, v0, v1);
                }
            }
        }
    } else {
        bool val[2][2];
#pragma unroll
        for (int mt = 0; mt < 2; mt++) {
            int r = bm + mwarp * 32 + mt * 16 + gid;
            val[mt][0] = nbr[r] >= 0;
            val[mt][1] = nbr[r + 8] >= 0;
        }
        float cmax[4][2];
#pragma unroll
        for (int nt = 0; nt < 4; nt++) { cmax[nt][0] = -1e30f; cmax[nt][1] = -1e30f; }
#pragma unroll
        for (int mt = 0; mt < 2; mt++) {
#pragma unroll
            for (int nt = 0; nt < 4; nt++) {
                int gn0 = bn + nwarp * 32 + nt * 8 + 2 * tig;
#pragma unroll
                for (int e = 0; e < 4; e++) {
                    int gn = gn0 + (e & 1);
                    float v = acc[mt][nt][e] + bias[gn];
                    v = fmaxf(v, 0.f);
                    v = gam[gn] * v * inv + bet[gn];
                    if (val[mt][e >> 1]) {
                        float& m = cmax[nt][e & 1];
                        m = fmaxf(m, v);
                    }
                }
            }
        }
#pragma unroll
        for (int off = 4; off <= 16; off <<= 1) {
#pragma unroll
            for (int nt = 0; nt < 4; nt++) {
                cmax[nt][0] = fmaxf(cmax[nt][0], __shfl_xor_sync(FULLM, cmax[nt][0], off));
                cmax[nt][1] = fmaxf(cmax[nt][1], __shfl_xor_sync(FULLM, cmax[nt][1], off));
            }
        }
        if (gid == 0) {
#pragma unroll
            for (int nt = 0; nt < 4; nt++) {
                sred[mwarp >> 1][mwarp & 1][nwarp * 32 + nt * 8 + 2 * tig]     = cmax[nt][0];
                sred[mwarp >> 1][mwarp & 1][nwarp * 32 + nt * 8 + 2 * tig + 1] = cmax[nt][1];
            }
        }
        __syncthreads();
        if (tid < 64) {
            int center = tid >> 5;
            int pr = tid & 31;
            int g0 = bn + pr * 2;
            float v0 = fmaxf(sred[center][0][pr * 2],     sred[center][1][pr * 2]);
            float v1 = fmaxf(sred[center][0][pr * 2 + 1], sred[center][1][pr * 2 + 1]);
            int row = blockIdx.y * 2 + center;
            store_pair(Cpk, KpOut, row, g0, v0, v1);
        }
    }
}

// ---------------- final tiny layer ----------------
__global__ __launch_bounds__(256)
void final_out(const uint4* __restrict__ Apk, const float* __restrict__ W,
               const float* __restrict__ bias, const float* __restrict__ gam,
               const float* __restrict__ bet, float* __restrict__ out, int M)
{
    __shared__ float sw[256];
    const int tid = threadIdx.x;
    sw[tid] = W[tid];
    __syncthreads();
    const int row = blockIdx.x * 32 + (tid >> 3);
    const int sub = tid & 7;
    if (row >= M) return;
    const uint4* a4 = Apk + (size_t)row * 32 + sub * 4;
    float acc0 = 0.f, acc1 = 0.f;
#pragma unroll
    for (int i = 0; i < 4; i++) {
        uint4 u = a4[i];
        int g = sub * 4 + i;
        int e0 = 16 * (g >> 2) + 2 * (g & 3);
        float va = bf2f(u.x & 0xffff) + bf2f(u.z & 0xffff);
        float vb = bf2f(u.x >> 16)    + bf2f(u.z >> 16);
        float vc = bf2f(u.y & 0xffff) + bf2f(u.w & 0xffff);
        float vd = bf2f(u.y >> 16)    + bf2f(u.w >> 16);
        acc0 += va * sw[e0 * 2]        + vb * sw[(e0 + 1) * 2]
              + vc * sw[(e0 + 8) * 2]  + vd * sw[(e0 + 9) * 2];
        acc1 += va * sw[e0 * 2 + 1]       + vb * sw[(e0 + 1) * 2 + 1]
              + vc * sw[(e0 + 8) * 2 + 1] + vd * sw[(e0 + 9) * 2 + 1];
    }
#pragma unroll
    for (int off = 4; off; off >>= 1) {
        acc0 += __shfl_down_sync(FULLM, acc0, off);
        acc1 += __shfl_down_sync(FULLM, acc1, off);
    }
    if (sub == 0) {
        const float inv = rsqrtf(1.f + 1e-5f);
        float v0 = fmaxf(acc0 + bias[0], 0.f);
        float v1 = fmaxf(acc1 + bias[1], 0.f);
        v0 = gam[0] * v0 * inv + bet[0];
        v1 = gam[1] * v1 * inv + bet[1];
        out[(size_t)row * 2]     = v0;
        out[(size_t)row * 2 + 1] = v1;
    }
}

// ---------------- farthest point sampling (redux, 1 barrier/step) ----------------
template<int PER>
__global__ __launch_bounds__(256)
void fps_kernel(const float* __restrict__ pos, int n, int m, float* __restrict__ qout)
{
    const int b = blockIdx.x, tid = threadIdx.x;
    const int lane = tid & 31, warp = tid >> 5;
    const float* P = pos + (size_t)b * n * 3;
    float* Q = qout + (size_t)b * m * 3;
    float px[PER], py[PER], pz[PER], dmin[PER];
#pragma unroll
    for (int u = 0; u < PER; u++) {
        int i = tid + 256 * u;
        px[u] = P[i * 3]; py[u] = P[i * 3 + 1]; pz[u] = P[i * 3 + 2];
        dmin[u] = 1e30f;
    }
    __shared__ unsigned s_v[2][8];
    __shared__ int      s_i[2][8];

    float qx = P[0], qy = P[1], qz = P[2];
    if (tid == 0) { Q[0] = qx; Q[1] = qy; Q[2] = qz; }

    for (int s = 1; s < m; s++) {
        float bv = -1e31f; int bi = 0;
#pragma unroll
        for (int u = 0; u < PER; u++) {
            float dx = px[u] - qx, dy = py[u] - qy, dz = pz[u] - qz;
            float d = dx * dx + dy * dy + dz * dz;
            d = fminf(dmin[u], d);
            dmin[u] = d;
            if (d > bv) { bv = d; bi = tid + 256 * u; }
        }
        unsigned vb = __float_as_uint(bv);
        unsigned vmax = __reduce_max_sync(FULLM, vb);
        int cand = (vb == vmax) ? bi : 0x7fffffff;
        int imin = __reduce_min_sync(FULLM, cand);
        const int par = s & 1;
        if (lane == 0) { s_v[par][warp] = vmax; s_i[par][warp] = imin; }
        __syncthreads();
        unsigned v8 = (lane < 8) ? s_v[par][lane] : 0u;
        unsigned vm8 = __reduce_max_sync(FULLM, v8);
        int c8 = (lane < 8 && v8 == vm8) ? s_i[par][lane] : 0x7fffffff;
        int fi = __reduce_min_sync(FULLM, c8);
        qx = P[fi * 3]; qy = P[fi * 3 + 1]; qz = P[fi * 3 + 2];
        if (tid == 0) { Q[s * 3] = qx; Q[s * 3 + 1] = qy; Q[s * 3 + 2] = qz; }
    }
}

// ---------------- ball-query: filter-then-select ----------------
// One block per (batch,center). Compact in-ball candidates into shared list;
// emit directly when count<=K (order-invariant downstream), exact top-K fallback otherwise.
__global__ __launch_bounds__(128)
void knn_ball(const float* __restrict__ pos, const float* __restrict__ q,
              int n, int m, int* __restrict__ nbr)
{
    __shared__ int   cidx[KCAP];
    __shared__ float cdd[KCAP];
    __shared__ int   cnt;
    __shared__ unsigned w_v[4];
    __shared__ int      w_i[4];

    const int bc = blockIdx.x;
    const int tid = threadIdx.x;
    const float* P = pos + (size_t)(bc / m) * n * 3;
    const float qx = q[(size_t)bc * 3], qy = q[(size_t)bc * 3 + 1], qz = q[(size_t)bc * 3 + 2];

    if (tid == 0) cnt = 0;
    __syncthreads();

    for (int i = tid; i < n; i += 128) {
        float dx = P[i * 3] - qx, dy = P[i * 3 + 1] - qy, dz = P[i * 3 + 2] - qz;
        float d2 = dx * dx + dy * dy + dz * dz;
        if (d2 <= 4.0f) {
            int p = atomicAdd(&cnt, 1);
            if (p < KCAP) { cidx[p] = i; cdd[p] = d2; }
        }
    }
    __syncthreads();

    int c = cnt;
    if (c > KCAP) c = KCAP;
    int* o = nbr + (size_t)bc * KNB;

    if (c <= KNB) {
        // all candidates selected; slot order is free (max-aggregation is order-invariant)
        if (tid < KNB) o[tid] = (tid < c) ? cidx[tid] : -1;
    } else {
        // exact K smallest d2, ties -> lowest original index (matches stable top_k)
        for (int r = 0; r < KNB; r++) {
            float bv = 1e38f; int bi = 0x7fffffff;
            for (int s2 = tid; s2 < c; s2 += 128) {
                float v = cdd[s2];
                int oi = cidx[s2];
                if (v < bv || (v == bv && oi < bi)) { bv = v; bi = oi; }
            }
            unsigned vb = __float_as_uint(bv);
            unsigned vmin = __reduce_min_sync(FULLM, vb);
            int cand = (vb == vmin) ? bi : 0x7fffffff;
            int imin = __reduce_min_sync(FULLM, cand);
            if ((tid & 31) == 0) { w_v[tid >> 5] = vmin; w_i[tid >> 5] = imin; }
            __syncthreads();
            unsigned v4 = ((tid & 31) < 4) ? w_v[tid & 31] : 0xffffffffu;
            unsigned vm4 = __reduce_min_sync(FULLM, v4);
            int c4 = ((tid & 31) < 4 && v4 == vm4) ? w_i[tid & 31] : 0x7fffffff;
            int fi = __reduce_min_sync(FULLM, c4);
            if (tid == 0) o[r] = fi;
            for (int s2 = tid; s2 < c; s2 += 128)
                if (cidx[s2] == fi) cdd[s2] = 1e38f;
            __syncthreads();
        }
    }
}

// ---------------- FP 3-NN interpolation + skip concat (packed IO) ----------------
__global__ __launch_bounds__(256)
void fp_interp(const uint4* __restrict__ cf, const float* __restrict__ cp,
               const float* __restrict__ fpos, const uint4* __restrict__ sf,
               int nc, int nf, uint4* __restrict__ fin)
{
    __shared__ float sp[2048 * 3];
    const int bpb = nf >> 8;
    const int b = blockIdx.x / bpb;
    const int i = (blockIdx.x % bpb) * 256 + threadIdx.x;
    for (int t = threadIdx.x; t < nc * 3; t += 256) sp[t] = cp[(size_t)b * nc * 3 + t];
    __syncthreads();
    const float px = fpos[((size_t)b * nf + i) * 3];
    const float py = fpos[((size_t)b * nf + i) * 3 + 1];
    const float pz = fpos[((size_t)b * nf + i) * 3 + 2];
    float bd0 = 1e38f, bd1 = 1e38f, bd2 = 1e38f;
    int bi0 = 0, bi1 = 0, bi2 = 0;
    for (int j = 0; j < nc; j++) {
        float dx = px - sp[j * 3], dy = py - sp[j * 3 + 1], dz = pz - sp[j * 3 + 2];
        float d = dx * dx + dy * dy + dz * dz;
        if (d < bd0)      { bd2 = bd1; bi2 = bi1; bd1 = bd0; bi1 = bi0; bd0 = d; bi0 = j; }
        else if (d < bd1) { bd2 = bd1; bi2 = bi1; bd1 = d; bi1 = j; }
        else if (d < bd2) { bd2 = d; bi2 = j; }
    }
    const float w0 = 1.f / fmaxf(bd0, 1e-16f);
    const float w1 = 1.f / fmaxf(bd1, 1e-16f);
    const float w2 = 1.f / fmaxf(bd2, 1e-16f);
    const float rws = 1.f / (w0 + w1 + w2);
    const uint4* f0 = cf + ((size_t)b * nc + bi0) * 32;
    const uint4* f1 = cf + ((size_t)b * nc + bi1) * 32;
    const uint4* f2 = cf + ((size_t)b * nc + bi2) * 32;
    const uint4* s4 = sf + ((size_t)b * nf + i) * 32;
    uint4* o4 = fin + ((size_t)b * nf + i) * 64;
#pragma unroll 8
    for (int u = 0; u < 32; u++) {
        uint4 a = f0[u], bb = f1[u], cc = f2[u];
        float ra = (w0 * (bf2f(a.x & 0xffff) + bf2f(a.z & 0xffff))
                  + w1 * (bf2f(bb.x & 0xffff) + bf2f(bb.z & 0xffff))
                  + w2 * (bf2f(cc.x & 0xffff) + bf2f(cc.z & 0xffff))) * rws;
        float rb = (w0 * (bf2f(a.x >> 16) + bf2f(a.z >> 16))
                  + w1 * (bf2f(bb.x >> 16) + bf2f(bb.z >> 16))
                  + w2 * (bf2f(cc.x >> 16) + bf2f(cc.z >> 16))) * rws;
        float rc = (w0 * (bf2f(a.y & 0xffff) + bf2f(a.w & 0xffff))
                  + w1 * (bf2f(bb.y & 0xffff) + bf2f(bb.w & 0xffff))
                  + w2 * (bf2f(cc.y & 0xffff) + bf2f(cc.w & 0xffff))) * rws;
        float rd = (w0 * (bf2f(a.y >> 16) + bf2f(a.w >> 16))
                  + w1 * (bf2f(bb.y >> 16) + bf2f(bb.w >> 16))
                  + w2 * (bf2f(cc.y >> 16) + bf2f(cc.w >> 16))) * rws;
        uint4 r;
        split2(ra, rb, r.x, r.z);
        split2(rc, rd, r.y, r.w);
        o4[u] = r;
        o4[32 + u] = s4[u];
    }
}

// ---------------- host ----------------
extern "C" void kernel_launch(void* const* d_in, const int* in_sizes, int n_in,
                              void* d_out, int out_size)
{
    const float* x      = (const float*)d_in[0];
    const float* pos0   = (const float*)d_in[1];
    const float* lin_w  = (const float*)d_in[3];
    const float* lin_b  = (const float*)d_in[4];
    const float* sa_w1  = (const float*)d_in[5];
    const float* sa_b1  = (const float*)d_in[6];
    const float* sa_g1  = (const float*)d_in[7];
    const float* sa_be1 = (const float*)d_in[8];
    const float* sa_w2  = (const float*)d_in[9];
    const float* sa_b2  = (const float*)d_in[10];
    const float* sa_g2  = (const float*)d_in[11];
    const float* sa_be2 = (const float*)d_in[12];
    const float* fp_w1  = (const float*)d_in[13];
    const float* fp_b1  = (const float*)d_in[14];
    const float* fp_g1  = (const float*)d_in[15];
    const float* fp_be1 = (const float*)d_in[16];
    const float* fp_w2  = (const float*)d_in[17];
    const float* fp_b2  = (const float*)d_in[18];
    const float* fp_g2  = (const float*)d_in[19];
    const float* fp_be2 = (const float*)d_in[20];
    const float* lo_w1  = (const float*)d_in[21];
    const float* lo_b1  = (const float*)d_in[22];
    const float* lo_g1  = (const float*)d_in[23];
    const float* lo_be1 = (const float*)d_in[24];
    const float* lo_w2  = (const float*)d_in[25];
    const float* lo_b2  = (const float*)d_in[26];
    const float* lo_g2  = (const float*)d_in[27];
    const float* lo_be2 = (const float*)d_in[28];
    float* out = (float*)d_out;

    float* buf = nullptr;
    cudaGetSymbolAddress((void**)&buf, g_buf);

    uint4* featPk[4] = { (uint4*)(buf + OFF_FEAT0), (uint4*)(buf + OFF_FEAT1),
                         (uint4*)(buf + OFF_FEAT2), (uint4*)(buf + OFF_FEAT3) };
    const float* posl[4] = { pos0, buf + OFF_POS1, buf + OFF_POS2, buf + OFF_POS3 };
    int* nbrL[3] = { (int*)(buf + OFF_NBR0), (int*)(buf + OFF_NBR1), (int*)(buf + OFF_NBR2) };
    uint4* h1Pk  = (uint4*)(buf + OFF_H1);
    uint4* finPk = (uint4*)(buf + OFF_FIN);
    uint4* f1Pk  = (uint4*)(buf + OFF_F1);
    uint4* xfPk  = (uint4*)(buf + OFF_XF);
    unsigned* wtBase = (unsigned*)(buf + OFF_WT);

    const int nlev[4] = {4096, 2048, 1024, 512};

    // side stream + events (created per call, never destroyed: capture-safe, no device mem)
    cudaStream_t s1;
    cudaStreamCreateWithFlags(&s1, cudaStreamNonBlocking);
    cudaEvent_t eFork, eK[3];
    cudaEventCreateWithFlags(&eFork, cudaEventDisableTiming);
    for (int l = 0; l < 3; l++) cudaEventCreateWithFlags(&eK[l], cudaEventDisableTiming);

    // fork: side stream joins the capture via event on the main (legacy) stream
    cudaEventRecord(eFork, 0);
    cudaStreamWaitEvent(s1, eFork, 0);

    // ---- geometry chain on s1 ----
    fps_kernel<16><<<NBATCH, 256, 0, s1>>>(posl[0], 4096, 2048, (float*)posl[1]);
    knn_ball<<<NBATCH * 2048, 128, 0, s1>>>(posl[0], posl[1], 4096, 2048, nbrL[0]);
    cudaEventRecord(eK[0], s1);
    fps_kernel<8><<<NBATCH, 256, 0, s1>>>(posl[1], 2048, 1024, (float*)posl[2]);
    knn_ball<<<NBATCH * 1024, 128, 0, s1>>>(posl[1], posl[2], 2048, 1024, nbrL[1]);
    cudaEventRecord(eK[1], s1);
    fps_kernel<4><<<NBATCH, 256, 0, s1>>>(posl[2], 1024, 512, (float*)posl[3]);
    knn_ball<<<NBATCH * 512, 128, 0, s1>>>(posl[2], posl[3], 1024, 512, nbrL[2]);
    cudaEventRecord(eK[2], s1);

    // ---- main stream: weights + lin_in ----
    {
        WTable tb;
        int cur = 0, e = 0;
        auto add = [&](const float* src, unsigned off, int K, int N, int Kp) {
            tb.d[e].src = src; tb.d[e].dstOff = off;
            tb.d[e].K = K; tb.d[e].N = N; tb.d[e].Kp = Kp; tb.d[e].start = cur;
            cur += N * (Kp >> 4) * 4;
            e++;
        };
        add(lin_w, WTO_LIN, 16, 128, 16);
        for (int l = 0; l < 3; l++) {
            add(sa_w1 + (size_t)l * 131 * 131, WTO_SAW1 + l * 18864, 131, 131, 144);
            add(sa_w2 + (size_t)l * 131 * 128, WTO_SAW2 + l * 18432, 131, 128, 144);
            add(fp_w1 + (size_t)l * 256 * 256, WTO_FPW1 + l * 65536, 256, 256, 256);
            add(fp_w2 + (size_t)l * 256 * 128, WTO_FPW2 + l * 32768, 256, 128, 256);
        }
        add(lo_w1, WTO_LOW1, 128, 128, 128);
        tb.total = cur;
        wconv_all<<<(cur + 255) / 256, 256>>>(tb, wtBase);
    }
    {
        dim3 grid(2, (NBATCH * 4096) / 128);
        gemm_tc<0, 0><<<grid, 256>>>(x, 16, nullptr, (uint4*)(wtBase + WTO_LIN),
                                     lin_b, nullptr, nullptr,
                                     (unsigned*)featPk[0], 128, NBATCH * 4096, 128, 16,
                                     nullptr, nullptr, nullptr, nullptr, 0, 0);
    }

    // ---- SA levels (join geometry per level) ----
    for (int l = 0; l < 3; l++) {
        int n = nlev[l], m = nlev[l + 1];
        cudaStreamWaitEvent(0, eK[l], 0);
        int rows = NBATCH * m * KNB;
        {
            dim3 grid(3, rows / 128);
            gemm_tc<1, 2><<<grid, 256>>>(nullptr, 0, nullptr,
                                         (uint4*)(wtBase + WTO_SAW1 + l * 18864),
                                         sa_b1 + l * 131, sa_g1 + l * 131, sa_be1 + l * 131,
                                         (unsigned*)h1Pk, 144, rows, 131, 144,
                                         featPk[l], posl[l], posl[l + 1], nbrL[l], n, m);
        }
        {
            dim3 grid(2, rows / 128);
            gemm_tc<2, 1><<<grid, 256>>>(nullptr, 0, h1Pk,
                                         (uint4*)(wtBase + WTO_SAW2 + l * 18432),
                                         sa_b2 + l * 128, sa_g2 + l * 128, sa_be2 + l * 128,
                                         (unsigned*)featPk[l + 1], 128, rows, 128, 144,
                                         nullptr, nullptr, nullptr, nbrL[l], n, m);
        }
    }

    // ---- FP levels ----
    const uint4* cfeat = featPk[3];
    for (int step = 0; step < 3; step++) {
        int mi = 2 - step;
        int nc = nlev[mi + 1], nf = nlev[mi];
        fp_interp<<<NBATCH * (nf / 256), 256>>>(cfeat, posl[mi + 1], posl[mi],
                                                featPk[mi], nc, nf, finPk);
        int rows = NBATCH * nf;
        {
            dim3 grid(4, rows / 128);
            gemm_tc<1, 1><<<grid, 256>>>(nullptr, 0, finPk,
                                         (uint4*)(wtBase + WTO_FPW1 + mi * 65536),
                                         fp_b1 + mi * 256, fp_g1 + mi * 256, fp_be1 + mi * 256,
                                         (unsigned*)f1Pk, 256, rows, 256, 256,
                                         nullptr, nullptr, nullptr, nullptr, 0, 0);
        }
        {
            dim3 grid(2, rows / 128);
            gemm_tc<1, 1><<<grid, 256>>>(nullptr, 0, f1Pk,
                                         (uint4*)(wtBase + WTO_FPW2 + mi * 32768),
                                         fp_b2 + mi * 128, fp_g2 + mi * 128, fp_be2 + mi * 128,
                                         (unsigned*)xfPk, 128, rows, 128, 256,
                                         nullptr, nullptr, nullptr, nullptr, 0, 0);
        }
        cfeat = xfPk;
    }

    // ---- final MLP ----
    {
        dim3 grid(2, (NBATCH * 4096) / 128);
        gemm_tc<1, 1><<<grid, 256>>>(nullptr, 0, xfPk, (uint4*)(wtBase + WTO_LOW1),
                                     lo_b1, lo_g1, lo_be1,
                                     (unsigned*)f1Pk, 128, NBATCH * 4096, 128, 128,
                                     nullptr, nullptr, nullptr, nullptr, 0, 0);
    }
    final_out<<<(NBATCH * 4096) / 32, 256>>>(f1Pk, lo_w2, lo_b2, lo_g2, lo_be2,
                                             out, NBATCH * 4096);
}

// round 12
// speedup vs baseline: 2.9076x; 1.3020x over previous
#include <cuda_runtime.h>
#include <cuda_bf16.h>
#include <cstddef>

#define NBATCH 4
#define KNB 64
#define KCAP 320
#define FULLM 0xffffffffu

// ---------------- scratch layout (floats) ----------------
#define OFF_FEAT0 0ull
#define OFF_FEAT1 2097152ull
#define OFF_FEAT2 3145728ull
#define OFF_FEAT3 3670016ull
#define OFF_POS1  3932160ull
#define OFF_POS2  3956736ull
#define OFF_POS3  3969024ull
#define OFF_FIN   4499456ull
#define OFF_F1    8693760ull
#define OFF_XF    12888064ull
#define OFF_WT    14985216ull
#define OFF_H1    15509504ull
// per-level compaction scratch
#define OFF_CNT0 91400192ull
#define OFF_OFS0 91408384ull
#define OFF_NBD0 91416584ull
#define OFF_RMP0 91940872ull
#define OFF_STG0 92465160ull
#define OFF_DR0  93513736ull
#define OFF_CNT1 93513744ull
#define OFF_OFS1 93517840ull
#define OFF_NBD1 93521944ull
#define OFF_RMP1 93784088ull
#define OFF_STG1 94046232ull
#define OFF_DR1  94570520ull
#define OFF_CNT2 94570528ull
#define OFF_OFS2 94572576ull
#define OFF_NBD2 94574632ull
#define OFF_RMP2 94705704ull
#define OFF_STG2 94836776ull
#define OFF_DR2  95098920ull
#define TOTAL_FLOATS 95098944ull

__device__ __align__(256) float g_buf[TOTAL_FLOATS];

// ---- WT sub-offsets (uint32 elements inside WT region) ----
#define WTO_LIN   0
#define WTO_SAW1  2048
#define WTO_SAW2  58640
#define WTO_FPW1  113936
#define WTO_FPW2  310544
#define WTO_LOW1  408848

// ---------------- bf16 helpers ----------------
__device__ __forceinline__ float bf2f(unsigned s16) {
    return __uint_as_float(s16 << 16);
}
__device__ __forceinline__ void split2(float a, float b, unsigned& hw, unsigned& lw) {
    __nv_bfloat16 ah = __float2bfloat16(a), bh = __float2bfloat16(b);
    float ar = a - __bfloat162float(ah);
    float br = b - __bfloat162float(bh);
    hw = (unsigned)__bfloat16_as_ushort(ah) | ((unsigned)__bfloat16_as_ushort(bh) << 16);
    lw = (unsigned)__bfloat16_as_ushort(__float2bfloat16(ar))
       | ((unsigned)__bfloat16_as_ushort(__float2bfloat16(br)) << 16);
}
__device__ __forceinline__ void store_pair(unsigned* C, int KpOut, int row, int g0,
                                           float v0, float v1) {
    unsigned hw, lw;
    split2(v0, v1, hw, lw);
    size_t off = ((size_t)row * (KpOut >> 2) + ((g0 >> 4) << 2) + ((g0 & 7) >> 1)) * 4
               + ((g0 >> 3) & 1);
    C[off]     = hw;
    C[off + 2] = lw;
}

// monotonic fp32<->uint encoding (order-preserving for atomicMax)
__device__ __forceinline__ unsigned encf(float f) {
    unsigned b = __float_as_uint(f);
    return (b & 0x80000000u) ? ~b : (b | 0x80000000u);
}
__device__ __forceinline__ float decf(unsigned u) {
    unsigned b = (u & 0x80000000u) ? (u & 0x7fffffffu) : ~u;
    return __uint_as_float(b);
}

__device__ __forceinline__ void mma16(float* c, const unsigned* a, unsigned b0, unsigned b1) {
    asm volatile(
        "mma.sync.aligned.m16n8k16.row.col.f32.bf16.bf16.f32 "
        "{%0,%1,%2,%3}, {%4,%5,%6,%7}, {%8,%9}, {%0,%1,%2,%3};"
        : "+f"(c[0]), "+f"(c[1]), "+f"(c[2]), "+f"(c[3])
        : "r"(a[0]), "r"(a[1]), "r"(a[2]), "r"(a[3]), "r"(b0), "r"(b1));
}

__device__ __forceinline__ int swz(int row, int t) {
    return t ^ ((row ^ (row >> 2)) & 3);
}

// ---------------- fused weight preprocess ----------------
struct WDesc { const float* src; unsigned dstOff; int K; int N; int Kp; int start; };
struct WTable { WDesc d[14]; int total; };

__global__ void wconv_all(WTable tb, unsigned* __restrict__ wtBase)
{
    int idx = blockIdx.x * blockDim.x + threadIdx.x;
    if (idx >= tb.total) return;
    int di = 0;
#pragma unroll
    for (int i = 1; i < 14; i++) if (idx >= tb.d[i].start) di = i;
    const WDesc D = tb.d[di];
    int e = idx - D.start;
    int t = e & 3;
    int c = (e >> 2) % (D.Kp >> 4);
    int n = e / ((D.Kp >> 4) * 4);
    int k0 = 16 * c + 2 * t;
    const float* W = D.src;
    float v0 = (k0     < D.K) ? W[(size_t)(k0    ) * D.N + n] : 0.f;
    float v1 = (k0 + 1 < D.K) ? W[(size_t)(k0 + 1) * D.N + n] : 0.f;
    float v2 = (k0 + 8 < D.K) ? W[(size_t)(k0 + 8) * D.N + n] : 0.f;
    float v3 = (k0 + 9 < D.K) ? W[(size_t)(k0 + 9) * D.N + n] : 0.f;
    uint4 u;
    split2(v0, v1, u.x, u.z);
    split2(v2, v3, u.y, u.w);
    ((uint4*)(wtBase + D.dstOff))[e] = u;
}

// ---------------- tensor-core GEMM (3xBF16), packed hi/lo I/O, double-buffered ----------------
// EPI: 0 = relu, 1 = relu+bn, 2 = relu+bn + segmented max via atomicMax into staging (Cpk).
// ASRC: 0 = fp32 A (lda), 1 = packed A, 2 = gather via rowmap (aux) from packed feat + pos delta.
template<int EPI, int ASRC>
__global__ __launch_bounds__(256)
void gemm_tc(const float* __restrict__ Afp, int lda,
             const uint4* __restrict__ Apk,
             const uint4* __restrict__ Wt,
             const float* __restrict__ bias, const float* __restrict__ gam,
             const float* __restrict__ bet,
             unsigned* __restrict__ Cpk, int KpOut, int M, int N, int Kp,
             const uint4* __restrict__ featPk, const float* __restrict__ posL,
             const float* __restrict__ q, const int* __restrict__ aux,
             int nPts, int mCen, const int* __restrict__ dR)
{
    __shared__ union SMU {
        struct { uint4 As4[2][512]; uint4 Ws4[2][256]; } mm;
        struct { float ep[128][66]; int sbc[128]; } epi;
    } sm;

    const int tid  = threadIdx.x;
    const int lane = tid & 31;
    const int warp = tid >> 5;
    const int mwarp = warp >> 1;
    const int nwarp = warp & 1;
    const int gid = lane >> 2;
    const int tig = lane & 3;
    const int bm = blockIdx.y * 128;
    const int bn = blockIdx.x * 64;

    int R = 0x7fffffff;
    if (ASRC == 2 || EPI == 2) {
        R = __ldg(dR);
        if (bm >= R) return;
    }

    float acc[2][4][4];
#pragma unroll
    for (int mt = 0; mt < 2; mt++)
#pragma unroll
        for (int nt = 0; nt < 4; nt++)
#pragma unroll
            for (int e = 0; e < 4; e++) acc[mt][nt][e] = 0.f;

    int gj = -1, gb = 0, gbc = 0;
    if (ASRC == 2 && tid < 128) {
        int gm = bm + tid;
        if (gm < R) {
            int rm = aux[gm];
            gj  = rm & 0xffff;
            gbc = rm >> 16;
            gb  = gbc / mCen;
        }
    }

    const int rowU4 = Kp >> 2;
    const int C = Kp >> 4;
    uint4 st[4];

    auto loadStage = [&](int c) {
        const int k0 = c << 4;
        if (tid < 128) {
            const int r = tid;
            if (ASRC == 1) {
                const uint4* p = Apk + (size_t)(bm + r) * rowU4 + c * 4;
                st[0] = p[0]; st[1] = p[1]; st[2] = p[2]; st[3] = p[3];
            } else if (ASRC == 2) {
                if (gj < 0) {
                    st[0] = st[1] = st[2] = st[3] = make_uint4(0, 0, 0, 0);
                } else if (k0 < 128) {
                    const uint4* p = featPk + ((size_t)gb * nPts + gj) * 32 + c * 4;
                    st[0] = p[0]; st[1] = p[1]; st[2] = p[2]; st[3] = p[3];
                } else {
                    const float* pp = posL + ((size_t)gb * nPts + gj) * 3;
                    const float* qq = q + (size_t)gbc * 3;
                    float d0 = pp[0] - qq[0], d1 = pp[1] - qq[1], d2 = pp[2] - qq[2];
                    unsigned h01, l01, h2z, l2z;
                    split2(d0, d1, h01, l01);
                    split2(d2, 0.f, h2z, l2z);
                    st[0] = make_uint4(h01, 0, l01, 0);
                    st[1] = make_uint4(h2z, 0, l2z, 0);
                    st[2] = make_uint4(0, 0, 0, 0);
                    st[3] = make_uint4(0, 0, 0, 0);
                }
            } else {
                float av[16];
                const float4* fp = (const float4*)(Afp + (size_t)(bm + r) * lda + k0);
#pragma unroll
                for (int i = 0; i < 4; i++) {
                    float4 v = fp[i];
                    av[i * 4]     = v.x; av[i * 4 + 1] = v.y;
                    av[i * 4 + 2] = v.z; av[i * 4 + 3] = v.w;
                }
#pragma unroll
                for (int t = 0; t < 4; t++) {
                    split2(av[2 * t],     av[2 * t + 1], st[t].x, st[t].z);
                    split2(av[2 * t + 8], av[2 * t + 9], st[t].y, st[t].w);
                }
            }
        } else if (tid < 192) {
            const int gn = bn + tid - 128;
            if (gn < N) {
                const uint4* p = Wt + (size_t)gn * rowU4 + c * 4;
                st[0] = p[0]; st[1] = p[1]; st[2] = p[2]; st[3] = p[3];
            } else {
                st[0] = st[1] = st[2] = st[3] = make_uint4(0, 0, 0, 0);
            }
        }
    };
    auto storeStage = [&](int b) {
        if (tid < 128) {
            const int r = tid;
#pragma unroll
            for (int t = 0; t < 4; t++) sm.mm.As4[b][r * 4 + swz(r, t)] = st[t];
        } else if (tid < 192) {
            const int n = tid - 128;
#pragma unroll
            for (int t = 0; t < 4; t++) sm.mm.Ws4[b][n * 4 + swz(n, t)] = st[t];
        }
    };

    loadStage(0);
    storeStage(0);
    __syncthreads();

    for (int c = 0; c < C; c++) {
        const int cb = c & 1;
        if (c + 1 < C) loadStage(c + 1);

        unsigned ah[2][4], al[2][4];
#pragma unroll
        for (int mt = 0; mt < 2; mt++) {
            int mr  = mwarp * 32 + mt * 16 + gid;
            int mr8 = mr + 8;
            uint4 ua = sm.mm.As4[cb][mr * 4 + swz(mr, tig)];
            uint4 ub = sm.mm.As4[cb][mr8 * 4 + swz(mr8, tig)];
            ah[mt][0] = ua.x; ah[mt][1] = ub.x; ah[mt][2] = ua.y; ah[mt][3] = ub.y;
            al[mt][0] = ua.z; al[mt][1] = ub.z; al[mt][2] = ua.w; al[mt][3] = ub.w;
        }
#pragma unroll
        for (int nt = 0; nt < 4; nt++) {
            int nc = nwarp * 32 + nt * 8 + gid;
            uint4 uw = sm.mm.Ws4[cb][nc * 4 + swz(nc, tig)];
#pragma unroll
            for (int mt = 0; mt < 2; mt++) {
                mma16(acc[mt][nt], ah[mt], uw.x, uw.y);
                mma16(acc[mt][nt], ah[mt], uw.z, uw.w);
                mma16(acc[mt][nt], al[mt], uw.x, uw.y);
            }
        }

        if (c + 1 < C) storeStage(cb ^ 1);
        __syncthreads();
    }

    const float inv = rsqrtf(1.f + 1e-5f);

    if (EPI < 2) {
#pragma unroll
        for (int mt = 0; mt < 2; mt++) {
#pragma unroll
            for (int nt = 0; nt < 4; nt++) {
                int g0 = bn + nwarp * 32 + nt * 8 + 2 * tig;
                if (g0 + 1 >= KpOut && g0 >= N) continue;
#pragma unroll
                for (int rr = 0; rr < 2; rr++) {
                    int row = bm + mwarp * 32 + mt * 16 + gid + rr * 8;
                    float v0 = acc[mt][nt][rr * 2];
                    float v1 = acc[mt][nt][rr * 2 + 1];
                    if (g0 < N) {
                        v0 = fmaxf(v0 + bias[g0], 0.f);
                        if (EPI == 1) v0 = gam[g0] * v0 * inv + bet[g0];
                    } else v0 = 0.f;
                    if (g0 + 1 < N) {
                        v1 = fmaxf(v1 + bias[g0 + 1], 0.f);
                        if (EPI == 1) v1 = gam[g0 + 1] * v1 * inv + bet[g0 + 1];
                    } else v1 = 0.f;
                    if (g0 + 1 < KpOut + 1 && g0 < KpOut)
                        store_pair(Cpk, KpOut, row, g0, v0, v1);
                }
            }
        }
    } else {
        // segmented max epilogue: bn values -> smem tile -> per-center atomicMax into staging
        if (tid < 128) {
            int r = bm + tid;
            sm.epi.sbc[tid] = (r < R) ? (aux[r] >> 16) : -1;
        }
#pragma unroll
        for (int mt = 0; mt < 2; mt++) {
#pragma unroll
            for (int nt = 0; nt < 4; nt++) {
#pragma unroll
                for (int e = 0; e < 4; e++) {
                    int rl = mwarp * 32 + mt * 16 + gid + (e >> 1) * 8;
                    int cl = nwarp * 32 + nt * 8 + 2 * tig + (e & 1);
                    int gn = bn + cl;
                    float v = acc[mt][nt][e] + bias[gn];
                    v = fmaxf(v, 0.f);
                    v = gam[gn] * v * inv + bet[gn];
                    sm.epi.ep[rl][cl] = v;
                }
            }
        }
        __syncthreads();
        const int col = tid & 63;
        const int r0 = (tid >> 6) * 32;
        int cur = -1;
        float mx = -1e30f;
#pragma unroll 4
        for (int rl = r0; rl < r0 + 32; rl++) {
            int bc = sm.epi.sbc[rl];
            if (bc != cur) {
                if (cur >= 0)
                    atomicMax(&Cpk[(size_t)cur * 128 + bn + col], encf(mx));
                cur = bc;
                mx = -1e30f;
            }
            if (bc >= 0) mx = fmaxf(mx, sm.epi.ep[rl][col]);
        }
        if (cur >= 0)
            atomicMax(&Cpk[(size_t)cur * 128 + bn + col], encf(mx));
    }
}

// ---------------- staging helpers ----------------
__global__ void stage_init(unsigned* __restrict__ st, int n)
{
    int idx = blockIdx.x * blockDim.x + threadIdx.x;
    if (idx < n) st[idx] = encf(-1e30f);
}

__global__ void stage_to_pack(const unsigned* __restrict__ st, int nC,
                              unsigned* __restrict__ outPk)
{
    int idx = blockIdx.x * blockDim.x + threadIdx.x;
    if (idx >= nC * 64) return;
    int center = idx >> 6;
    int g0 = (idx & 63) * 2;
    float v0 = decf(st[center * 128 + g0]);
    float v1 = decf(st[center * 128 + g0 + 1]);
    store_pair(outPk, 128, center, g0, v0, v1);
}

// ---------------- compaction: scan + rowmap build ----------------
__global__ void scan_offsets(const int* __restrict__ cnt, int nC,
                             int* __restrict__ off, int* __restrict__ dR)
{
    __shared__ int part[256];
    const int tid = threadIdx.x;
    const int chunk = (nC + 255) / 256;
    const int base = tid * chunk;
    int s = 0;
    for (int i = 0; i < chunk; i++) {
        int j = base + i;
        if (j < nC) s += cnt[j];
    }
    part[tid] = s;
    __syncthreads();
    if (tid == 0) {
        int acc = 0;
        for (int i = 0; i < 256; i++) { int t = part[i]; part[i] = acc; acc += t; }
        dR[0] = acc;
    }
    __syncthreads();
    int acc = part[tid];
    for (int i = 0; i < chunk; i++) {
        int j = base + i;
        if (j < nC) { off[j] = acc; acc += cnt[j]; }
    }
}

__global__ void build_rowmap(const int* __restrict__ cnt, const int* __restrict__ off,
                             const int* __restrict__ nbrd, int* __restrict__ rowmap)
{
    const int bc = blockIdx.x;
    const int t = threadIdx.x;
    if (t < cnt[bc]) rowmap[off[bc] + t] = nbrd[bc * 64 + t] | (bc << 16);
}

// ---------------- final tiny layer ----------------
__global__ __launch_bounds__(256)
void final_out(const uint4* __restrict__ Apk, const float* __restrict__ W,
               const float* __restrict__ bias, const float* __restrict__ gam,
               const float* __restrict__ bet, float* __restrict__ out, int M)
{
    __shared__ float sw[256];
    const int tid = threadIdx.x;
    sw[tid] = W[tid];
    __syncthreads();
    const int row = blockIdx.x * 32 + (tid >> 3);
    const int sub = tid & 7;
    if (row >= M) return;
    const uint4* a4 = Apk + (size_t)row * 32 + sub * 4;
    float acc0 = 0.f, acc1 = 0.f;
#pragma unroll
    for (int i = 0; i < 4; i++) {
        uint4 u = a4[i];
        int g = sub * 4 + i;
        int e0 = 16 * (g >> 2) + 2 * (g & 3);
        float va = bf2f(u.x & 0xffff) + bf2f(u.z & 0xffff);
        float vb = bf2f(u.x >> 16)    + bf2f(u.z >> 16);
        float vc = bf2f(u.y & 0xffff) + bf2f(u.w & 0xffff);
        float vd = bf2f(u.y >> 16)    + bf2f(u.w >> 16);
        acc0 += va * sw[e0 * 2]        + vb * sw[(e0 + 1) * 2]
              + vc * sw[(e0 + 8) * 2]  + vd * sw[(e0 + 9) * 2];
        acc1 += va * sw[e0 * 2 + 1]       + vb * sw[(e0 + 1) * 2 + 1]
              + vc * sw[(e0 + 8) * 2 + 1] + vd * sw[(e0 + 9) * 2 + 1];
    }
#pragma unroll
    for (int off = 4; off; off >>= 1) {
        acc0 += __shfl_down_sync(FULLM, acc0, off);
        acc1 += __shfl_down_sync(FULLM, acc1, off);
    }
    if (sub == 0) {
        const float inv = rsqrtf(1.f + 1e-5f);
        float v0 = fmaxf(acc0 + bias[0], 0.f);
        float v1 = fmaxf(acc1 + bias[1], 0.f);
        v0 = gam[0] * v0 * inv + bet[0];
        v1 = gam[1] * v1 * inv + bet[1];
        out[(size_t)row * 2]     = v0;
        out[(size_t)row * 2 + 1] = v1;
    }
}

// ---------------- farthest point sampling (redux, 1 barrier/step) ----------------
template<int PER>
__global__ __launch_bounds__(256)
void fps_kernel(const float* __restrict__ pos, int n, int m, float* __restrict__ qout)
{
    const int b = blockIdx.x, tid = threadIdx.x;
    const int lane = tid & 31, warp = tid >> 5;
    const float* P = pos + (size_t)b * n * 3;
    float* Q = qout + (size_t)b * m * 3;
    float px[PER], py[PER], pz[PER], dmin[PER];
#pragma unroll
    for (int u = 0; u < PER; u++) {
        int i = tid + 256 * u;
        px[u] = P[i * 3]; py[u] = P[i * 3 + 1]; pz[u] = P[i * 3 + 2];
        dmin[u] = 1e30f;
    }
    __shared__ unsigned s_v[2][8];
    __shared__ int      s_i[2][8];

    float qx = P[0], qy = P[1], qz = P[2];
    if (tid == 0) { Q[0] = qx; Q[1] = qy; Q[2] = qz; }

    for (int s = 1; s < m; s++) {
        float bv = -1e31f; int bi = 0;
#pragma unroll
        for (int u = 0; u < PER; u++) {
            float dx = px[u] - qx, dy = py[u] - qy, dz = pz[u] - qz;
            float d = dx * dx + dy * dy + dz * dz;
            d = fminf(dmin[u], d);
            dmin[u] = d;
            if (d > bv) { bv = d; bi = tid + 256 * u; }
        }
        unsigned vb = __float_as_uint(bv);
        unsigned vmax = __reduce_max_sync(FULLM, vb);
        int cand = (vb == vmax) ? bi : 0x7fffffff;
        int imin = __reduce_min_sync(FULLM, cand);
        const int par = s & 1;
        if (lane == 0) { s_v[par][warp] = vmax; s_i[par][warp] = imin; }
        __syncthreads();
        unsigned v8 = (lane < 8) ? s_v[par][lane] : 0u;
        unsigned vm8 = __reduce_max_sync(FULLM, v8);
        int c8 = (lane < 8 && v8 == vm8) ? s_i[par][lane] : 0x7fffffff;
        int fi = __reduce_min_sync(FULLM, c8);
        qx = P[fi * 3]; qy = P[fi * 3 + 1]; qz = P[fi * 3 + 2];
        if (tid == 0) { Q[s * 3] = qx; Q[s * 3 + 1] = qy; Q[s * 3 + 2] = qz; }
    }
}

// ---------------- ball-query: filter-then-select, dense output + counts ----------------
__global__ __launch_bounds__(128)
void knn_ball(const float* __restrict__ pos, const float* __restrict__ q,
              int n, int m, int* __restrict__ nbrd, int* __restrict__ cntArr)
{
    __shared__ int   cidx[KCAP];
    __shared__ float cdd[KCAP];
    __shared__ int   cnt;
    __shared__ unsigned w_v[4];
    __shared__ int      w_i[4];

    const int bc = blockIdx.x;
    const int tid = threadIdx.x;
    const float* P = pos + (size_t)(bc / m) * n * 3;
    const float qx = q[(size_t)bc * 3], qy = q[(size_t)bc * 3 + 1], qz = q[(size_t)bc * 3 + 2];

    if (tid == 0) cnt = 0;
    __syncthreads();

    for (int i = tid; i < n; i += 128) {
        float dx = P[i * 3] - qx, dy = P[i * 3 + 1] - qy, dz = P[i * 3 + 2] - qz;
        float d2 = dx * dx + dy * dy + dz * dz;
        if (d2 <= 4.0f) {
            int p = atomicAdd(&cnt, 1);
            if (p < KCAP) { cidx[p] = i; cdd[p] = d2; }
        }
    }
    __syncthreads();

    int c = cnt;
    if (c > KCAP) c = KCAP;
    int* o = nbrd + (size_t)bc * KNB;

    if (c <= KNB) {
        if (tid == 0) cntArr[bc] = c;
        if (tid < c) o[tid] = cidx[tid];
    } else {
        if (tid == 0) cntArr[bc] = KNB;
        for (int r = 0; r < KNB; r++) {
            float bv = 1e38f; int bi = 0x7fffffff;
            for (int s2 = tid; s2 < c; s2 += 128) {
                float v = cdd[s2];
                int oi = cidx[s2];
                if (v < bv || (v == bv && oi < bi)) { bv = v; bi = oi; }
            }
            unsigned vb = __float_as_uint(bv);
            unsigned vmin = __reduce_min_sync(FULLM, vb);
            int cand = (vb == vmin) ? bi : 0x7fffffff;
            int imin = __reduce_min_sync(FULLM, cand);
            if ((tid & 31) == 0) { w_v[tid >> 5] = vmin; w_i[tid >> 5] = imin; }
            __syncthreads();
            unsigned v4 = ((tid & 31) < 4) ? w_v[tid & 31] : 0xffffffffu;
            unsigned vm4 = __reduce_min_sync(FULLM, v4);
            int c4 = ((tid & 31) < 4 && v4 == vm4) ? w_i[tid & 31] : 0x7fffffff;
            int fi = __reduce_min_sync(FULLM, c4);
            if (tid == 0) o[r] = fi;
            for (int s2 = tid; s2 < c; s2 += 128)
                if (cidx[s2] == fi) cdd[s2] = 1e38f;
            __syncthreads();
        }
    }
}

// ---------------- FP 3-NN interpolation + skip concat (packed IO) ----------------
__global__ __launch_bounds__(256)
void fp_interp(const uint4* __restrict__ cf, const float* __restrict__ cp,
               const float* __restrict__ fpos, const uint4* __restrict__ sf,
               int nc, int nf, uint4* __restrict__ fin)
{
    __shared__ float sp[2048 * 3];
    const int bpb = nf >> 8;
    const int b = blockIdx.x / bpb;
    const int i = (blockIdx.x % bpb) * 256 + threadIdx.x;
    for (int t = threadIdx.x; t < nc * 3; t += 256) sp[t] = cp[(size_t)b * nc * 3 + t];
    __syncthreads();
    const float px = fpos[((size_t)b * nf + i) * 3];
    const float py = fpos[((size_t)b * nf + i) * 3 + 1];
    const float pz = fpos[((size_t)b * nf + i) * 3 + 2];
    float bd0 = 1e38f, bd1 = 1e38f, bd2 = 1e38f;
    int bi0 = 0, bi1 = 0, bi2 = 0;
    for (int j = 0; j < nc; j++) {
        float dx = px - sp[j * 3], dy = py - sp[j * 3 + 1], dz = pz - sp[j * 3 + 2];
        float d = dx * dx + dy * dy + dz * dz;
        if (d < bd0)      { bd2 = bd1; bi2 = bi1; bd1 = bd0; bi1 = bi0; bd0 = d; bi0 = j; }
        else if (d < bd1) { bd2 = bd1; bi2 = bi1; bd1 = d; bi1 = j; }
        else if (d < bd2) { bd2 = d; bi2 = j; }
    }
    const float w0 = 1.f / fmaxf(bd0, 1e-16f);
    const float w1 = 1.f / fmaxf(bd1, 1e-16f);
    const float w2 = 1.f / fmaxf(bd2, 1e-16f);
    const float rws = 1.f / (w0 + w1 + w2);
    const uint4* f0 = cf + ((size_t)b * nc + bi0) * 32;
    const uint4* f1 = cf + ((size_t)b * nc + bi1) * 32;
    const uint4* f2 = cf + ((size_t)b * nc + bi2) * 32;
    const uint4* s4 = sf + ((size_t)b * nf + i) * 32;
    uint4* o4 = fin + ((size_t)b * nf + i) * 64;
#pragma unroll 8
    for (int u = 0; u < 32; u++) {
        uint4 a = f0[u], bb = f1[u], cc = f2[u];
        float ra = (w0 * (bf2f(a.x & 0xffff) + bf2f(a.z & 0xffff))
                  + w1 * (bf2f(bb.x & 0xffff) + bf2f(bb.z & 0xffff))
                  + w2 * (bf2f(cc.x & 0xffff) + bf2f(cc.z & 0xffff))) * rws;
        float rb = (w0 * (bf2f(a.x >> 16) + bf2f(a.z >> 16))
                  + w1 * (bf2f(bb.x >> 16) + bf2f(bb.z >> 16))
                  + w2 * (bf2f(cc.x >> 16) + bf2f(cc.z >> 16))) * rws;
        float rc = (w0 * (bf2f(a.y & 0xffff) + bf2f(a.w & 0xffff))
                  + w1 * (bf2f(bb.y & 0xffff) + bf2f(bb.w & 0xffff))
                  + w2 * (bf2f(cc.y & 0xffff) + bf2f(cc.w & 0xffff))) * rws;
        float rd = (w0 * (bf2f(a.y >> 16) + bf2f(a.w >> 16))
                  + w1 * (bf2f(bb.y >> 16) + bf2f(bb.w >> 16))
                  + w2 * (bf2f(cc.y >> 16) + bf2f(cc.w >> 16))) * rws;
        uint4 r;
        split2(ra, rb, r.x, r.z);
        split2(rc, rd, r.y, r.w);
        o4[u] = r;
        o4[32 + u] = s4[u];
    }
}

// ---------------- host ----------------
extern "C" void kernel_launch(void* const* d_in, const int* in_sizes, int n_in,
                              void* d_out, int out_size)
{
    const float* x      = (const float*)d_in[0];
    const float* pos0   = (const float*)d_in[1];
    const float* lin_w  = (const float*)d_in[3];
    const float* lin_b  = (const float*)d_in[4];
    const float* sa_w1  = (const float*)d_in[5];
    const float* sa_b1  = (const float*)d_in[6];
    const float* sa_g1  = (const float*)d_in[7];
    const float* sa_be1 = (const float*)d_in[8];
    const float* sa_w2  = (const float*)d_in[9];
    const float* sa_b2  = (const float*)d_in[10];
    const float* sa_g2  = (const float*)d_in[11];
    const float* sa_be2 = (const float*)d_in[12];
    const float* fp_w1  = (const float*)d_in[13];
    const float* fp_b1  = (const float*)d_in[14];
    const float* fp_g1  = (const float*)d_in[15];
    const float* fp_be1 = (const float*)d_in[16];
    const float* fp_w2  = (const float*)d_in[17];
    const float* fp_b2  = (const float*)d_in[18];
    const float* fp_g2  = (const float*)d_in[19];
    const float* fp_be2 = (const float*)d_in[20];
    const float* lo_w1  = (const float*)d_in[21];
    const float* lo_b1  = (const float*)d_in[22];
    const float* lo_g1  = (const float*)d_in[23];
    const float* lo_be1 = (const float*)d_in[24];
    const float* lo_w2  = (const float*)d_in[25];
    const float* lo_b2  = (const float*)d_in[26];
    const float* lo_g2  = (const float*)d_in[27];
    const float* lo_be2 = (const float*)d_in[28];
    float* out = (float*)d_out;

    float* buf = nullptr;
    cudaGetSymbolAddress((void**)&buf, g_buf);

    uint4* featPk[4] = { (uint4*)(buf + OFF_FEAT0), (uint4*)(buf + OFF_FEAT1),
                         (uint4*)(buf + OFF_FEAT2), (uint4*)(buf + OFF_FEAT3) };
    const float* posl[4] = { pos0, buf + OFF_POS1, buf + OFF_POS2, buf + OFF_POS3 };
    int* cntL[3]  = { (int*)(buf + OFF_CNT0), (int*)(buf + OFF_CNT1), (int*)(buf + OFF_CNT2) };
    int* ofsL[3]  = { (int*)(buf + OFF_OFS0), (int*)(buf + OFF_OFS1), (int*)(buf + OFF_OFS2) };
    int* nbdL[3]  = { (int*)(buf + OFF_NBD0), (int*)(buf + OFF_NBD1), (int*)(buf + OFF_NBD2) };
    int* rmpL[3]  = { (int*)(buf + OFF_RMP0), (int*)(buf + OFF_RMP1), (int*)(buf + OFF_RMP2) };
    unsigned* stgL[3] = { (unsigned*)(buf + OFF_STG0), (unsigned*)(buf + OFF_STG1),
                          (unsigned*)(buf + OFF_STG2) };
    int* drL[3]   = { (int*)(buf + OFF_DR0), (int*)(buf + OFF_DR1), (int*)(buf + OFF_DR2) };
    uint4* h1Pk  = (uint4*)(buf + OFF_H1);
    uint4* finPk = (uint4*)(buf + OFF_FIN);
    uint4* f1Pk  = (uint4*)(buf + OFF_F1);
    uint4* xfPk  = (uint4*)(buf + OFF_XF);
    unsigned* wtBase = (unsigned*)(buf + OFF_WT);

    const int nlev[4] = {4096, 2048, 1024, 512};

    cudaStream_t s1;
    cudaStreamCreateWithFlags(&s1, cudaStreamNonBlocking);
    cudaEvent_t eFork, eK[3];
    cudaEventCreateWithFlags(&eFork, cudaEventDisableTiming);
    for (int l = 0; l < 3; l++) cudaEventCreateWithFlags(&eK[l], cudaEventDisableTiming);

    cudaEventRecord(eFork, 0);
    cudaStreamWaitEvent(s1, eFork, 0);

    // ---- geometry + compaction chain on s1 ----
    for (int l = 0; l < 3; l++) {
        int n = nlev[l], m = nlev[l + 1];
        int nC = NBATCH * m;
        if (l == 0)      fps_kernel<16><<<NBATCH, 256, 0, s1>>>(posl[0], n, m, (float*)posl[1]);
        else if (l == 1) fps_kernel<8><<<NBATCH, 256, 0, s1>>>(posl[1], n, m, (float*)posl[2]);
        else             fps_kernel<4><<<NBATCH, 256, 0, s1>>>(posl[2], n, m, (float*)posl[3]);
        knn_ball<<<nC, 128, 0, s1>>>(posl[l], posl[l + 1], n, m, nbdL[l], cntL[l]);
        scan_offsets<<<1, 256, 0, s1>>>(cntL[l], nC, ofsL[l], drL[l]);
        build_rowmap<<<nC, 64, 0, s1>>>(cntL[l], ofsL[l], nbdL[l], rmpL[l]);
        stage_init<<<(nC * 128 + 255) / 256, 256, 0, s1>>>(stgL[l], nC * 128);
        cudaEventRecord(eK[l], s1);
    }

    // ---- main stream: weights + lin_in ----
    {
        WTable tb;
        int cur = 0, e = 0;
        auto add = [&](const float* src, unsigned off, int K, int N, int Kp) {
            tb.d[e].src = src; tb.d[e].dstOff = off;
            tb.d[e].K = K; tb.d[e].N = N; tb.d[e].Kp = Kp; tb.d[e].start = cur;
            cur += N * (Kp >> 4) * 4;
            e++;
        };
        add(lin_w, WTO_LIN, 16, 128, 16);
        for (int l = 0; l < 3; l++) {
            add(sa_w1 + (size_t)l * 131 * 131, WTO_SAW1 + l * 18864, 131, 131, 144);
            add(sa_w2 + (size_t)l * 131 * 128, WTO_SAW2 + l * 18432, 131, 128, 144);
            add(fp_w1 + (size_t)l * 256 * 256, WTO_FPW1 + l * 65536, 256, 256, 256);
            add(fp_w2 + (size_t)l * 256 * 128, WTO_FPW2 + l * 32768, 256, 128, 256);
        }
        add(lo_w1, WTO_LOW1, 128, 128, 128);
        tb.total = cur;
        wconv_all<<<(cur + 255) / 256, 256>>>(tb, wtBase);
    }
    {
        dim3 grid(2, (NBATCH * 4096) / 128);
        gemm_tc<0, 0><<<grid, 256>>>(x, 16, nullptr, (uint4*)(wtBase + WTO_LIN),
                                     lin_b, nullptr, nullptr,
                                     (unsigned*)featPk[0], 128, NBATCH * 4096, 128, 16,
                                     nullptr, nullptr, nullptr, nullptr, 0, 0, nullptr);
    }

    // ---- SA levels (compacted rows, join geometry per level) ----
    for (int l = 0; l < 3; l++) {
        int n = nlev[l], m = nlev[l + 1];
        int nC = NBATCH * m;
        int rowsMax = nC * KNB;
        cudaStreamWaitEvent(0, eK[l], 0);
        {
            dim3 grid(3, rowsMax / 128);
            gemm_tc<1, 2><<<grid, 256>>>(nullptr, 0, nullptr,
                                         (uint4*)(wtBase + WTO_SAW1 + l * 18864),
                                         sa_b1 + l * 131, sa_g1 + l * 131, sa_be1 + l * 131,
                                         (unsigned*)h1Pk, 144, rowsMax, 131, 144,
                                         featPk[l], posl[l], posl[l + 1], rmpL[l],
                                         n, m, drL[l]);
        }
        {
            dim3 grid(2, rowsMax / 128);
            gemm_tc<2, 1><<<grid, 256>>>(nullptr, 0, h1Pk,
                                         (uint4*)(wtBase + WTO_SAW2 + l * 18432),
                                         sa_b2 + l * 128, sa_g2 + l * 128, sa_be2 + l * 128,
                                         stgL[l], 128, rowsMax, 128, 144,
                                         nullptr, nullptr, nullptr, rmpL[l],
                                         n, m, drL[l]);
        }
        stage_to_pack<<<(nC * 64 + 255) / 256, 256>>>(stgL[l], nC, (unsigned*)featPk[l + 1]);
    }

    // ---- FP levels ----
    const uint4* cfeat = featPk[3];
    for (int step = 0; step < 3; step++) {
        int mi = 2 - step;
        int nc = nlev[mi + 1], nf = nlev[mi];
        fp_interp<<<NBATCH * (nf / 256), 256>>>(cfeat, posl[mi + 1], posl[mi],
                                                featPk[mi], nc, nf, finPk);
        int rows = NBATCH * nf;
        {
            dim3 grid(4, rows / 128);
            gemm_tc<1, 1><<<grid, 256>>>(nullptr, 0, finPk,
                                         (uint4*)(wtBase + WTO_FPW1 + mi * 65536),
                                         fp_b1 + mi * 256, fp_g1 + mi * 256, fp_be1 + mi * 256,
                                         (unsigned*)f1Pk, 256, rows, 256, 256,
                                         nullptr, nullptr, nullptr, nullptr, 0, 0, nullptr);
        }
        {
            dim3 grid(2, rows / 128);
            gemm_tc<1, 1><<<grid, 256>>>(nullptr, 0, f1Pk,
                                         (uint4*)(wtBase + WTO_FPW2 + mi * 32768),
                                         fp_b2 + mi * 128, fp_g2 + mi * 128, fp_be2 + mi * 128,
                                         (unsigned*)xfPk, 128, rows, 128, 256,
                                         nullptr, nullptr, nullptr, nullptr, 0, 0, nullptr);
        }
        cfeat = xfPk;
    }

    // ---- final MLP ----
    {
        dim3 grid(2, (NBATCH * 4096) / 128);
        gemm_tc<1, 1><<<grid, 256>>>(nullptr, 0, xfPk, (uint4*)(wtBase + WTO_LOW1),
                                     lo_b1, lo_g1, lo_be1,
                                     (unsigned*)f1Pk, 128, NBATCH * 4096, 128, 128,
                                     nullptr, nullptr, nullptr, nullptr, 0, 0, nullptr);
    }
    final_out<<<(NBATCH * 4096) / 32, 256>>>(f1Pk, lo_w2, lo_b2, lo_g2, lo_be2,
                                             out, NBATCH * 4096);
}